// round 6
// baseline (speedup 1.0000x reference)
#include <cuda_runtime.h>
#include <cuda_bf16.h>
#include <math.h>
#include <stdint.h>

#define NCELL 8192
#define NINP  2000
#define KPAD  2048
#define HDIM  128
#define NOUTD 32
#define BN_EPS 1e-3f

#define BM 128
#define BN 128
#define BK 16

#if defined(__CUDA_ARCH_FEAT_SM103_ALL) || defined(__CUDA_ARCH_FEAT_SM100_ALL) || \
    defined(__CUDA_ARCH_FEAT_SM110_ALL) || defined(__CUDA_ARCH_FEAT_SM101_ALL)
#define TC_ENABLED 1
#else
#define TC_ENABLED 0
#endif

// ---------------------------------------------------------------------------
// Scratch
// ---------------------------------------------------------------------------
__device__ __align__(256) float g_bufA[NCELL * HDIM];
__device__ __align__(256) float g_bufB[NCELL * HDIM];
__device__ __align__(256) float g_qkv [NCELL * 3 * HDIM];
__device__ __align__(256) float g_kagg[NCELL * HDIM];
__device__ __align__(256) float g_stats[512];

__device__ __align__(256) __nv_bfloat16 g_q_hi [NCELL * HDIM];
__device__ __align__(256) __nv_bfloat16 g_q_lo [NCELL * HDIM];
__device__ __align__(256) __nv_bfloat16 g_ka_hi[NCELL * HDIM];
__device__ __align__(256) __nv_bfloat16 g_ka_lo[NCELL * HDIM];
__device__ __align__(256) __nv_bfloat16 g_kT_hi[HDIM * NCELL];
__device__ __align__(256) __nv_bfloat16 g_kT_lo[HDIM * NCELL];
__device__ __align__(256) __nv_bfloat16 g_vT_hi[HDIM * NCELL];
__device__ __align__(256) __nv_bfloat16 g_vT_lo[HDIM * NCELL];
__device__ __align__(256) __nv_bfloat16 g_wT_hi[HDIM * KPAD];
__device__ __align__(256) __nv_bfloat16 g_wT_lo[HDIM * KPAD];

// ---------------------------------------------------------------------------
// PTX helpers
// ---------------------------------------------------------------------------
__device__ __forceinline__ uint32_t cvta_smem(const void *p) {
    uint32_t a;
    asm("{ .reg .u64 t; cvta.to.shared.u64 t, %1; cvt.u32.u64 %0, t; }"
        : "=r"(a) : "l"(p));
    return a;
}
__device__ __forceinline__ uint32_t elect_one() {
    uint32_t p;
    asm volatile("{ .reg .pred p; elect.sync _|p, 0xFFFFFFFF; selp.b32 %0, 1, 0, p; }"
                 : "=r"(p));
    return p;
}
__device__ __forceinline__ void mbar_init(uint32_t mbar, uint32_t cnt) {
    asm volatile("mbarrier.init.shared.b64 [%0], %1;"
                 :: "r"(mbar), "r"(cnt) : "memory");
}
__device__ __forceinline__ void mbar_wait(uint32_t mbar, uint32_t parity) {
    asm volatile(
        "{\n\t.reg .pred P;\n"
        "LW_%=:\n\t"
        "mbarrier.try_wait.parity.acquire.cta.shared::cta.b64 P, [%0], %1, 0x989680;\n\t"
        "@P bra LD_%=;\n\t"
        "bra LW_%=;\n"
        "LD_%=:\n\t}"
        :: "r"(mbar), "r"(parity) : "memory");
}
__device__ __forceinline__ void fence_async_smem() {
    asm volatile("fence.proxy.async.shared::cta;" ::: "memory");
}
__device__ __forceinline__ void cpa16(uint32_t dst, const void *src) {
    asm volatile("cp.async.cg.shared.global [%0], [%1], 16;"
                 :: "r"(dst), "l"(src) : "memory");
}
__device__ __forceinline__ void cpa_commit() {
    asm volatile("cp.async.commit_group;" ::: "memory");
}
template <int N>
__device__ __forceinline__ void cpa_wait() {
    asm volatile("cp.async.wait_group %0;" :: "n"(N) : "memory");
}
__device__ __forceinline__ void red4(float *p, float a, float b, float c, float d) {
    asm volatile("red.global.add.v4.f32 [%0], {%1, %2, %3, %4};"
                 :: "l"(p), "f"(a), "f"(b), "f"(c), "f"(d) : "memory");
}

// ---- tcgen05 ----
__device__ __forceinline__ void tc_alloc(uint32_t smem_dst, uint32_t ncols) {
    asm volatile("tcgen05.alloc.cta_group::1.sync.aligned.shared::cta.b32 [%0], %1;"
                 :: "r"(smem_dst), "r"(ncols) : "memory");
}
__device__ __forceinline__ void tc_dealloc(uint32_t tmem, uint32_t ncols) {
    asm volatile("tcgen05.dealloc.cta_group::1.sync.aligned.b32 %0, %1;"
                 :: "r"(tmem), "r"(ncols));
}
__device__ __forceinline__ void tc_relinquish() {
    asm volatile("tcgen05.relinquish_alloc_permit.cta_group::1.sync.aligned;");
}
__device__ __forceinline__ void tc_commit(uint32_t mbar) {
    asm volatile("tcgen05.commit.cta_group::1.mbarrier::arrive::one.shared::cluster.b64 [%0];"
                 :: "r"(mbar) : "memory");
}
__device__ __forceinline__ void tc_fence_after() {
    asm volatile("tcgen05.fence::after_thread_sync;" ::: "memory");
}
__device__ __forceinline__ void tc_wait_ld() {
    asm volatile("tcgen05.wait::ld.sync.aligned;" ::: "memory");
}
__device__ __forceinline__ void ldtm32(uint32_t *r, uint32_t addr) {
    asm volatile(
        "tcgen05.ld.sync.aligned.32x32b.x32.b32 "
        "{%0, %1, %2, %3, %4, %5, %6, %7, "
        " %8, %9, %10, %11, %12, %13, %14, %15, "
        " %16, %17, %18, %19, %20, %21, %22, %23, "
        " %24, %25, %26, %27, %28, %29, %30, %31}, [%32];"
        : "=r"(r[0]),  "=r"(r[1]),  "=r"(r[2]),  "=r"(r[3]),
          "=r"(r[4]),  "=r"(r[5]),  "=r"(r[6]),  "=r"(r[7]),
          "=r"(r[8]),  "=r"(r[9]),  "=r"(r[10]), "=r"(r[11]),
          "=r"(r[12]), "=r"(r[13]), "=r"(r[14]), "=r"(r[15]),
          "=r"(r[16]), "=r"(r[17]), "=r"(r[18]), "=r"(r[19]),
          "=r"(r[20]), "=r"(r[21]), "=r"(r[22]), "=r"(r[23]),
          "=r"(r[24]), "=r"(r[25]), "=r"(r[26]), "=r"(r[27]),
          "=r"(r[28]), "=r"(r[29]), "=r"(r[30]), "=r"(r[31])
        : "r"(addr));
}
__device__ __forceinline__ void mma_f16_ss(uint32_t d, uint64_t a_desc,
                                           uint64_t b_desc, uint32_t idesc,
                                           uint32_t en) {
    asm volatile(
        "{\n\t.reg .pred p;\n\t"
        "setp.ne.u32 p, %5, 0;\n\t"
        "tcgen05.mma.cta_group::1.kind::f16 [%0], %1, %2, %3, {%4, %4, %4, %4}, p;\n\t}"
        :: "r"(d), "l"(a_desc), "l"(b_desc), "r"(idesc), "r"(0u), "r"(en)
        : "memory");
}
__device__ __forceinline__ uint64_t make_desc(uint32_t addr) {
    return ((uint64_t)2 << 61) | ((uint64_t)1 << 46) | ((uint64_t)64 << 32) |
           ((uint64_t)1 << 16) | (((uint64_t)(addr >> 4)) & 0x3FFF);
}
__device__ __forceinline__ void fma2(float2 &c, const float2 &a, const float2 &b) {
    unsigned long long       &cc = reinterpret_cast<unsigned long long &>(c);
    const unsigned long long &aa = reinterpret_cast<const unsigned long long &>(a);
    const unsigned long long &bb = reinterpret_cast<const unsigned long long &>(b);
    asm("fma.rn.f32x2 %0, %1, %2, %0;" : "+l"(cc) : "l"(aa), "l"(bb));
}
__device__ __forceinline__ void split1(float v, __nv_bfloat16 &h, __nv_bfloat16 &l) {
    h = __float2bfloat16(v);
    l = __float2bfloat16(v - __bfloat162float(h));
}
__device__ __forceinline__ uint32_t pack2(__nv_bfloat16 a, __nv_bfloat16 b) {
    __nv_bfloat162 p(a, b);
    return *reinterpret_cast<uint32_t *>(&p);
}

static constexpr uint32_t TC_IDESC = 0x8200490u; // F32 acc, BF16xBF16, M=128, N=128

__device__ __forceinline__ uint32_t sw16(int r, int ch) {  // 128x64 bf16 tile
    uint32_t byte = (r >> 3) * 1024 + (r & 7) * 128 + ch * 16;
    return byte ^ ((byte >> 3) & 0x70);
}
__device__ __forceinline__ uint32_t sw32(int r, int ch) {  // 128x128 bf16 tile
    uint32_t byte = ((r >> 3) + (ch >> 3) * 16) * 1024 + (r & 7) * 128 + (ch & 7) * 16;
    return byte ^ ((byte >> 3) & 0x70);
}

// ---------------------------------------------------------------------------
// tc_skinny_f32: C[128-mtile, 128] += split(A_f32)[M,K] @ (Bhi+Blo)[128,K]^T
// Overlapped: load+convert of stage s+1 runs under MMA(s).
// ---------------------------------------------------------------------------
#define SKF_SMEM (1024 + 2 * 65536)

__global__ void __launch_bounds__(128)
tc_skinny_f32(const float *__restrict__ A, int lda, int Kvalid,
              const __nv_bfloat16 *__restrict__ Bhi,
              const __nv_bfloat16 *__restrict__ Blo, int ldb,
              float *__restrict__ C, int ldc, int kpc, float alpha)
{
#if TC_ENABLED
    extern __shared__ char sm[];
    const uint32_t sb = cvta_smem(sm);
    const int tid = threadIdx.x;
    const int wid = tid >> 5;

    if (wid == 0) tc_alloc(sb, 128);
    if (tid == 64) mbar_init(sb + 8, 1);
    __syncthreads();
    uint32_t tmem;
    asm volatile("ld.shared.b32 %0, [%1];" : "=r"(tmem) : "r"(sb));

    const int m0 = blockIdx.x * 128;
    const int kb0 = blockIdx.z * kpc;
    const int S = kpc >> 6;

    float4 regs[16];

    auto ldA = [&](int s) {
        const int kb = kb0 + s * 64;
#pragma unroll
        for (int i = 0; i < 16; ++i) {
            int g = i * 128 + tid;
            int r = g >> 4, ch = g & 15;
            int col = kb + ch * 4;
            if (col < Kvalid)
                regs[i] = *(const float4 *)(A + (size_t)(m0 + r) * lda + col);
            else
                regs[i] = make_float4(0.f, 0.f, 0.f, 0.f);
        }
    };
    auto ldB = [&](int s) {
        const uint32_t bh = sb + 1024 + (s & 1) * 65536 + 32768;
        const int kb = kb0 + s * 64;
#pragma unroll
        for (int i = 0; i < 8; ++i) {
            int g = i * 128 + tid;
            int r = g >> 3, ch = g & 7;
            uint32_t so = sw16(r, ch);
            cpa16(bh + so,         Bhi + (size_t)r * ldb + kb + ch * 8);
            cpa16(bh + 16384 + so, Blo + (size_t)r * ldb + kb + ch * 8);
        }
        cpa_commit();
    };
    auto stA = [&](int s) {
        char *ah = sm + 1024 + (s & 1) * 65536;
        char *al = ah + 16384;
#pragma unroll
        for (int i = 0; i < 16; ++i) {
            int g = i * 128 + tid;
            int r = g >> 4, ch = g & 15;
            float4 v = regs[i];
            __nv_bfloat16 h0, h1, h2, h3, l0, l1, l2, l3;
            split1(v.x, h0, l0); split1(v.y, h1, l1);
            split1(v.z, h2, l2); split1(v.w, h3, l3);
            uint32_t b = (uint32_t)(r * 128 + ch * 8);
            uint32_t sz = b ^ ((b >> 3) & 0x70);
            *(uint2 *)(ah + sz) = make_uint2(pack2(h0, h1), pack2(h2, h3));
            *(uint2 *)(al + sz) = make_uint2(pack2(l0, l1), pack2(l2, l3));
        }
    };

    // prologue: stage 0 fully in smem
    ldB(0);
    ldA(0);
    cpa_wait<0>();
    stA(0);
    __syncthreads();
    fence_async_smem();

    uint32_t ph = 0;
    for (int s = 0; s < S; ++s) {
        if (wid == 0 && elect_one()) {
            const uint32_t base = sb + 1024 + (s & 1) * 65536;
            uint64_t dah = make_desc(base);
            uint64_t dal = make_desc(base + 16384);
            uint64_t dbh = make_desc(base + 32768);
            uint64_t dbl = make_desc(base + 49152);
#pragma unroll
            for (int k = 0; k < 4; ++k) {
                uint64_t off = (uint64_t)(k * 2);
                mma_f16_ss(tmem, dah + off, dbh + off, TC_IDESC, (s > 0) || (k > 0));
                mma_f16_ss(tmem, dah + off, dbl + off, TC_IDESC, 1u);
                mma_f16_ss(tmem, dal + off, dbh + off, TC_IDESC, 1u);
            }
            tc_commit(sb + 8);
        }
        // overlap next stage's load + convert with the MMA batch
        if (s + 1 < S) {
            ldB(s + 1);
            ldA(s + 1);
            cpa_wait<0>();
            stA(s + 1);
        }
        mbar_wait(sb + 8, ph);
        ph ^= 1;
        __syncthreads();
        fence_async_smem();
    }

    tc_fence_after();
#pragma unroll
    for (int part = 0; part < 4; ++part) {
        uint32_t d[32];
        ldtm32(d, tmem + part * 32);
        tc_wait_ld();
        float *cp = C + (size_t)(m0 + tid) * ldc + part * 32;
#pragma unroll
        for (int j = 0; j < 8; ++j)
            red4(cp + j * 4,
                 __uint_as_float(d[j * 4 + 0]) * alpha,
                 __uint_as_float(d[j * 4 + 1]) * alpha,
                 __uint_as_float(d[j * 4 + 2]) * alpha,
                 __uint_as_float(d[j * 4 + 3]) * alpha);
    }
    __syncthreads();
    if (wid == 0) {
        tc_relinquish();
        tc_dealloc(tmem, 128);
    }
#endif
}

// ---------------------------------------------------------------------------
// tc_wide: logits, 4 N-tiles per CTA; epilogue of group n-1 overlaps MMA(n).
// smem: 1KB hdr + A 64KB + 2 x B 64KB + 17KB staging
// ---------------------------------------------------------------------------
#define WIDE_EP   (1024 + 65536 + 131072)
#define WIDE_SMEM (WIDE_EP + 16896)

__global__ void __launch_bounds__(128)
tc_wide(const __nv_bfloat16 *__restrict__ Ahi, const __nv_bfloat16 *__restrict__ Alo,
        const __nv_bfloat16 *__restrict__ Bhi, const __nv_bfloat16 *__restrict__ Blo,
        float *__restrict__ C, float alpha)
{
#if TC_ENABLED
    extern __shared__ char sm[];
    const uint32_t sb = cvta_smem(sm);
    const int tid = threadIdx.x;
    const int wid = tid >> 5;

    if (wid == 0) tc_alloc(sb, 512);
    if (tid == 64) mbar_init(sb + 8, 1);
    __syncthreads();
    uint32_t tmem;
    asm volatile("ld.shared.b32 %0, [%1];" : "=r"(tmem) : "r"(sb));

    const int m0 = blockIdx.x * 128;
    const int ng0 = blockIdx.y * 512;

    const uint32_t A0 = sb + 1024;
    const uint32_t A1 = A0 + 32768;

    auto load_B = [&](int n) {
        const uint32_t base = sb + 1024 + 65536 + (n & 1) * 65536;
        const int r0 = ng0 + n * 128;
#pragma unroll
        for (int i = tid; i < 2048; i += 128) {
            int r = i >> 4, ch = i & 15;
            uint32_t so = sw32(r, ch);
            cpa16(base + so,         Bhi + (size_t)(r0 + r) * HDIM + ch * 8);
            cpa16(base + 32768 + so, Blo + (size_t)(r0 + r) * HDIM + ch * 8);
        }
        cpa_commit();
    };
    auto epi = [&](int g) {
        float *st = (float *)(sm + WIDE_EP);
#pragma unroll
        for (int part = 0; part < 4; ++part) {
            uint32_t d[32];
            ldtm32(d, tmem + g * 128 + part * 32);
            tc_wait_ld();
#pragma unroll
            for (int c = 0; c < 32; ++c)
                st[tid * 33 + c] = __uint_as_float(d[c]) * alpha;
            __syncthreads();
            const int col0 = ng0 + g * 128 + part * 32;
#pragma unroll
            for (int i = 0; i < 32; ++i) {
                int idx = i * 128 + tid;
                int rr = idx >> 5, cc = idx & 31;
                C[(size_t)(m0 + rr) * NCELL + col0 + cc] = st[rr * 33 + cc];
            }
            __syncthreads();
        }
    };

    // prologue: A hi/lo + B(0) in one cp.async group
#pragma unroll
    for (int i = tid; i < 2048; i += 128) {
        int r = i >> 4, ch = i & 15;
        uint32_t so = sw32(r, ch);
        cpa16(A0 + so, Ahi + (size_t)(m0 + r) * HDIM + ch * 8);
        cpa16(A1 + so, Alo + (size_t)(m0 + r) * HDIM + ch * 8);
    }
    {
        const uint32_t base = sb + 1024 + 65536;
#pragma unroll
        for (int i = tid; i < 2048; i += 128) {
            int r = i >> 4, ch = i & 15;
            uint32_t so = sw32(r, ch);
            cpa16(base + so,         Bhi + (size_t)(ng0 + r) * HDIM + ch * 8);
            cpa16(base + 32768 + so, Blo + (size_t)(ng0 + r) * HDIM + ch * 8);
        }
    }
    cpa_commit();

    uint32_t ph = 0;
    for (int n = 0; n < 4; ++n) {
        if (n + 1 < 4) { load_B(n + 1); cpa_wait<1>(); }
        else           { cpa_wait<0>(); }
        __syncthreads();
        fence_async_smem();
        if (wid == 0 && elect_one()) {
            const uint32_t bbase = sb + 1024 + 65536 + (n & 1) * 65536;
            uint64_t dah = make_desc(A0);
            uint64_t dal = make_desc(A1);
            uint64_t dbh = make_desc(bbase);
            uint64_t dbl = make_desc(bbase + 32768);
            const uint32_t acc = tmem + n * 128;
#pragma unroll
            for (int k = 0; k < 8; ++k) {
                uint64_t off = (uint64_t)((k & 3) * 2 + (k >> 2) * 1024);
                mma_f16_ss(acc, dah + off, dbh + off, TC_IDESC, k > 0);
                mma_f16_ss(acc, dah + off, dbl + off, TC_IDESC, 1u);
                mma_f16_ss(acc, dal + off, dbh + off, TC_IDESC, 1u);
            }
            tc_commit(sb + 8);
        }
        if (n > 0) epi(n - 1);          // store previous group under MMA(n)
        mbar_wait(sb + 8, ph);
        ph ^= 1;
        tc_fence_after();
        __syncthreads();
    }
    epi(3);

    __syncthreads();
    if (wid == 0) {
        tc_relinquish();
        tc_dealloc(tmem, 512);
    }
#endif
}

// ---------------------------------------------------------------------------
// fp32 -> bf16 hi/lo split kernels
// ---------------------------------------------------------------------------
__global__ void split_cols(const float *__restrict__ src, int ldsrc, int col0,
                           int cols4, __nv_bfloat16 *__restrict__ hi,
                           __nv_bfloat16 *__restrict__ lo)
{
    int idx = blockIdx.x * blockDim.x + threadIdx.x;
    int r = idx / cols4, c = idx - r * cols4;
    float4 v = *(const float4 *)(src + (size_t)r * ldsrc + col0 + c * 4);
    __nv_bfloat16 h0, h1, h2, h3, l0, l1, l2, l3;
    split1(v.x, h0, l0); split1(v.y, h1, l1);
    split1(v.z, h2, l2); split1(v.w, h3, l3);
    __nv_bfloat162 *ph = (__nv_bfloat162 *)(hi + (size_t)idx * 4);
    __nv_bfloat162 *pl = (__nv_bfloat162 *)(lo + (size_t)idx * 4);
    ph[0] = __nv_bfloat162(h0, h1); ph[1] = __nv_bfloat162(h2, h3);
    pl[0] = __nv_bfloat162(l0, l1); pl[1] = __nv_bfloat162(l2, l3);
}

__global__ void wT_split(const float *__restrict__ W, const int *__restrict__ hid,
                         __nv_bfloat16 *__restrict__ hi, __nv_bfloat16 *__restrict__ lo)
{
    int idx = blockIdx.x * blockDim.x + threadIdx.x;   // 128*2048
    int r = idx >> 7;        // k 0..2047
    int c = idx & 127;       // col 0..127
    const float *Wh = W + (size_t)hid[0] * NINP * HDIM;
    float v = (r < NINP) ? Wh[(size_t)r * HDIM + c] : 0.f;
    __nv_bfloat16 h, l;
    split1(v, h, l);
    size_t o = (size_t)c * KPAD + r;
    hi[o] = h;
    lo[o] = l;
}

__global__ void transpose_split(const float *__restrict__ src, int ldsrc, int col0,
                                __nv_bfloat16 *__restrict__ hi,
                                __nv_bfloat16 *__restrict__ lo)
{
    __shared__ float t[32][33];
    int r0 = blockIdx.x * 32, c0 = blockIdx.y * 32;
    int tx = threadIdx.x, ty = threadIdx.y;  // 32 x 8
#pragma unroll
    for (int i = 0; i < 4; ++i) {
        int r = ty + i * 8;
        t[r][tx] = src[(size_t)(r0 + r) * ldsrc + col0 + c0 + tx];
    }
    __syncthreads();
#pragma unroll
    for (int i = 0; i < 4; ++i) {
        int c = ty + i * 8;
        float v = t[tx][c];
        __nv_bfloat16 h, l;
        split1(v, h, l);
        size_t o = (size_t)(c0 + c) * NCELL + r0 + tx;
        hi[o] = h;
        lo[o] = l;
    }
}

// ---------------------------------------------------------------------------
// gemm_small: C[M,N] = bnrelu(A)[M,128] @ B[128,N] (+bias), direct store.
// BNA: A' = relu(A*scale[k] + shift[k]) applied on load (scale/shift in smem).
// ---------------------------------------------------------------------------
template <bool BNA>
__global__ void __launch_bounds__(256)
gemm_small(const float *__restrict__ A, const float *__restrict__ B,
           float *__restrict__ C, int ldb, int ldc,
           const float *__restrict__ bias,
           const float *__restrict__ bnS, const float *__restrict__ bnB)
{
    __shared__ float As[BK][BM + 4];
    __shared__ float Bs[BK][BN + 4];
    __shared__ float bnSs[128], bnBs[128];

    const int tid = threadIdx.x;
    const int tx = tid & 15;
    const int ty = tid >> 4;
    const int m0 = blockIdx.x * BM;
    const int n0 = blockIdx.y * BN;

    if (BNA && tid < 128) { bnSs[tid] = bnS[tid]; bnBs[tid] = bnB[tid]; }

    const int f0 = tid, f1 = tid + 256;
    const int aRow0 = f0 >> 2, aK0 = (f0 & 3) * 4;
    const int aRow1 = f1 >> 2, aK1 = (f1 & 3) * 4;
    const int bK0 = f0 >> 5, bN0 = (f0 & 31) * 4;
    const int bK1 = f1 >> 5, bN1 = (f1 & 31) * 4;

    const float *Ap0 = A + (size_t)(m0 + aRow0) * HDIM + aK0;
    const float *Ap1 = A + (size_t)(m0 + aRow1) * HDIM + aK1;
    const float *Bp0 = B + (size_t)bK0 * ldb + n0 + bN0;
    const float *Bp1 = B + (size_t)bK1 * ldb + n0 + bN1;

    float2 acc[8][4];
#pragma unroll
    for (int i = 0; i < 8; ++i)
#pragma unroll
        for (int j = 0; j < 4; ++j) acc[i][j] = make_float2(0.f, 0.f);

    float4 ra0 = *(const float4 *)Ap0;
    float4 ra1 = *(const float4 *)Ap1;
    float4 rb0 = *(const float4 *)Bp0;
    float4 rb1 = *(const float4 *)Bp1;

    const int chunks = HDIM / BK;   // 8
    for (int c = 0; c < chunks; ++c) {
        __syncthreads();
        const int cK = c * BK;
        if (BNA) {
            As[aK0 + 0][aRow0] = fmaxf(fmaf(ra0.x, bnSs[cK + aK0 + 0], bnBs[cK + aK0 + 0]), 0.f);
            As[aK0 + 1][aRow0] = fmaxf(fmaf(ra0.y, bnSs[cK + aK0 + 1], bnBs[cK + aK0 + 1]), 0.f);
            As[aK0 + 2][aRow0] = fmaxf(fmaf(ra0.z, bnSs[cK + aK0 + 2], bnBs[cK + aK0 + 2]), 0.f);
            As[aK0 + 3][aRow0] = fmaxf(fmaf(ra0.w, bnSs[cK + aK0 + 3], bnBs[cK + aK0 + 3]), 0.f);
            As[aK1 + 0][aRow1] = fmaxf(fmaf(ra1.x, bnSs[cK + aK1 + 0], bnBs[cK + aK1 + 0]), 0.f);
            As[aK1 + 1][aRow1] = fmaxf(fmaf(ra1.y, bnSs[cK + aK1 + 1], bnBs[cK + aK1 + 1]), 0.f);
            As[aK1 + 2][aRow1] = fmaxf(fmaf(ra1.z, bnSs[cK + aK1 + 2], bnBs[cK + aK1 + 2]), 0.f);
            As[aK1 + 3][aRow1] = fmaxf(fmaf(ra1.w, bnSs[cK + aK1 + 3], bnBs[cK + aK1 + 3]), 0.f);
        } else {
            As[aK0 + 0][aRow0] = ra0.x; As[aK0 + 1][aRow0] = ra0.y;
            As[aK0 + 2][aRow0] = ra0.z; As[aK0 + 3][aRow0] = ra0.w;
            As[aK1 + 0][aRow1] = ra1.x; As[aK1 + 1][aRow1] = ra1.y;
            As[aK1 + 2][aRow1] = ra1.z; As[aK1 + 3][aRow1] = ra1.w;
        }
        *(float4 *)&Bs[bK0][bN0] = rb0;
        *(float4 *)&Bs[bK1][bN1] = rb1;
        __syncthreads();

        if (c + 1 < chunks) {
            Ap0 += BK; Ap1 += BK;
            ra0 = *(const float4 *)Ap0;
            ra1 = *(const float4 *)Ap1;
            Bp0 += (size_t)BK * ldb; Bp1 += (size_t)BK * ldb;
            rb0 = *(const float4 *)Bp0;
            rb1 = *(const float4 *)Bp1;
        }

#pragma unroll
        for (int kk = 0; kk < BK; ++kk) {
            float4 a0 = *(const float4 *)&As[kk][ty * 4];
            float4 a1 = *(const float4 *)&As[kk][64 + ty * 4];
            float4 b0 = *(const float4 *)&Bs[kk][tx * 4];
            float4 b1 = *(const float4 *)&Bs[kk][64 + tx * 4];
            float av[8] = {a0.x, a0.y, a0.z, a0.w, a1.x, a1.y, a1.z, a1.w};
            float2 bp[4] = {make_float2(b0.x, b0.y), make_float2(b0.z, b0.w),
                            make_float2(b1.x, b1.y), make_float2(b1.z, b1.w)};
#pragma unroll
            for (int i = 0; i < 8; ++i) {
                float2 aa = make_float2(av[i], av[i]);
#pragma unroll
                for (int j = 0; j < 4; ++j) fma2(acc[i][j], aa, bp[j]);
            }
        }
    }

    float bad0[4] = {0.f, 0.f, 0.f, 0.f}, bad1[4] = {0.f, 0.f, 0.f, 0.f};
    if (bias != nullptr) {
#pragma unroll
        for (int j = 0; j < 4; ++j) {
            bad0[j] = bias[n0 + tx * 4 + j];
            bad1[j] = bias[n0 + 64 + tx * 4 + j];
        }
    }
#pragma unroll
    for (int i = 0; i < 8; ++i) {
        int r = m0 + ((i < 4) ? (ty * 4 + i) : (64 + ty * 4 + (i - 4)));
        float v[8] = {acc[i][0].x, acc[i][0].y, acc[i][1].x, acc[i][1].y,
                      acc[i][2].x, acc[i][2].y, acc[i][3].x, acc[i][3].y};
        float *crow = C + (size_t)r * ldc;
        float4 w0 = make_float4(v[0] + bad0[0], v[1] + bad0[1],
                                v[2] + bad0[2], v[3] + bad0[3]);
        float4 w1 = make_float4(v[4] + bad1[0], v[5] + bad1[1],
                                v[6] + bad1[2], v[7] + bad1[3]);
        *(float4 *)(crow + n0 + tx * 4) = w0;
        *(float4 *)(crow + n0 + 64 + tx * 4) = w1;
    }
}

// ---------------------------------------------------------------------------
// BatchNorm stats
// ---------------------------------------------------------------------------
__global__ void bn_stats(const float *__restrict__ h, float *__restrict__ stats)
{
    int col = threadIdx.x;
    int r0 = blockIdx.x * 32;
    float s = 0.f, s2 = 0.f;
#pragma unroll 8
    for (int r = 0; r < 32; ++r) {
        float v = h[(size_t)(r0 + r) * HDIM + col];
        s += v; s2 += v * v;
    }
    atomicAdd(&stats[col], s);
    atomicAdd(&stats[128 + col], s2);
}

__global__ void bn_finalize(float *__restrict__ stats,
                            const float *__restrict__ g, const float *__restrict__ be,
                            const int *__restrict__ hid, int headStride)
{
    int c = threadIdx.x;
    int off = hid ? hid[0] * headStride : 0;
    float mean = stats[c] * (1.f / (float)NCELL);
    float var = stats[128 + c] * (1.f / (float)NCELL) - mean * mean;
    float rstd = rsqrtf(var + BN_EPS);
    float gg = g[off + c];
    stats[256 + c] = gg * rstd;
    stats[384 + c] = be[off + c] - gg * mean * rstd;
}

// ---------------------------------------------------------------------------
// Row softmax in place
// ---------------------------------------------------------------------------
__global__ void softmax_row(float *__restrict__ attn)
{
    extern __shared__ float row[];
    __shared__ float red[256];
    const int t = threadIdx.x;
    float *p = attn + (size_t)blockIdx.x * NCELL;

    float m = -1e30f;
    for (int i = t; i < NCELL / 4; i += 256) {
        float4 v = ((const float4 *)p)[i];
        ((float4 *)row)[i] = v;
        m = fmaxf(m, fmaxf(fmaxf(v.x, v.y), fmaxf(v.z, v.w)));
    }
    red[t] = m; __syncthreads();
    for (int s = 128; s > 0; s >>= 1) {
        if (t < s) red[t] = fmaxf(red[t], red[t + s]);
        __syncthreads();
    }
    const float bmax = red[0];
    __syncthreads();

    float sum = 0.f;
    for (int i = t; i < NCELL / 4; i += 256) {
        float4 v = ((float4 *)row)[i];
        v.x = __expf(v.x - bmax); v.y = __expf(v.y - bmax);
        v.z = __expf(v.z - bmax); v.w = __expf(v.w - bmax);
        sum += v.x + v.y + v.z + v.w;
        ((float4 *)row)[i] = v;
    }
    red[t] = sum; __syncthreads();
    for (int s = 128; s > 0; s >>= 1) {
        if (t < s) red[t] += red[t + s];
        __syncthreads();
    }
    const float inv = 1.f / red[0];
    __syncthreads();

    for (int i = t; i < NCELL / 4; i += 256) {
        float4 v = ((float4 *)row)[i];
        v.x *= inv; v.y *= inv; v.z *= inv; v.w *= inv;
        ((float4 *)p)[i] = v;
    }
}

// ---------------------------------------------------------------------------
// Variational heads
// ---------------------------------------------------------------------------
__global__ void heads_kernel(const float *__restrict__ o,
                             const float *__restrict__ mW, const float *__restrict__ mb,
                             const float *__restrict__ vW, const float *__restrict__ vb,
                             const float *__restrict__ eps,
                             float *__restrict__ qm, float *__restrict__ qv,
                             float *__restrict__ lat)
{
    extern __shared__ float smh[];
    float *Wm  = smh;
    float *Wv  = smh + 4096;
    float *osm = smh + 8192;
    const int t = threadIdx.x;
    const int r0 = blockIdx.x * 128;

    for (int i = t; i < HDIM * NOUTD; i += 256) { Wm[i] = mW[i]; Wv[i] = vW[i]; }
    for (int i = t; i < 128 * HDIM; i += 256) {
        int r = i >> 7, c = i & 127;
        osm[r * 129 + c] = o[(size_t)(r0 + r) * HDIM + c];
    }
    __syncthreads();

    for (int idx = t; idx < 128 * NOUTD; idx += 256) {
        int r = idx >> 5, c = idx & 31;
        const float *orow = &osm[r * 129];
        float dm = 0.f, dv = 0.f;
#pragma unroll 8
        for (int k = 0; k < HDIM; ++k) {
            float ov = orow[k];
            dm += ov * Wm[k * NOUTD + c];
            dv += ov * Wv[k * NOUTD + c];
        }
        int R = r0 + r;
        float mval = dm + mb[c];
        float vval = __expf(dv + vb[c]);
        qm[R * NOUTD + c]  = mval;
        qv[R * NOUTD + c]  = vval;
        lat[R * NOUTD + c] = mval + sqrtf(vval) * eps[R * NOUTD + c];
    }
}

// ---------------------------------------------------------------------------
// Launch
// ---------------------------------------------------------------------------
extern "C" void kernel_launch(void *const *d_in, const int *in_sizes, int n_in,
                              void *d_out, int out_size)
{
    const float *x       = (const float *)d_in[0];
    const float *spatial = (const float *)d_in[1];
    const float *eps     = (const float *)d_in[2];
    const float *enc_W   = (const float *)d_in[3];
    const float *enc_g   = (const float *)d_in[5];
    const float *enc_be  = (const float *)d_in[6];
    const float *sh_W1   = (const float *)d_in[7];
    const float *sh_g1   = (const float *)d_in[9];
    const float *sh_be1  = (const float *)d_in[10];
    const float *sh_W2   = (const float *)d_in[11];
    const float *sh_g2   = (const float *)d_in[13];
    const float *sh_be2  = (const float *)d_in[14];
    const float *qkv_W   = (const float *)d_in[15];
    const float *qkv_b   = (const float *)d_in[16];
    const float *o_W     = (const float *)d_in[17];
    const float *o_b     = (const float *)d_in[18];
    const float *mean_W  = (const float *)d_in[19];
    const float *mean_b  = (const float *)d_in[20];
    const float *var_W   = (const float *)d_in[21];
    const float *var_b   = (const float *)d_in[22];
    const int   *hid     = (const int *)d_in[23];

    float *out = (float *)d_out;
    float *out_qm   = out;
    float *out_qv   = out + (size_t)NCELL * NOUTD;
    float *out_lat  = out + 2 * (size_t)NCELL * NOUTD;
    float *out_attn = out + 3 * (size_t)NCELL * NOUTD;

    float *bufA, *bufB, *qkv, *kagg, *stats;
    __nv_bfloat16 *q_hi, *q_lo, *ka_hi, *ka_lo;
    __nv_bfloat16 *kT_hi, *kT_lo, *vT_hi, *vT_lo, *wT_hi, *wT_lo;
    cudaGetSymbolAddress((void **)&bufA, g_bufA);
    cudaGetSymbolAddress((void **)&bufB, g_bufB);
    cudaGetSymbolAddress((void **)&qkv,  g_qkv);
    cudaGetSymbolAddress((void **)&kagg, g_kagg);
    cudaGetSymbolAddress((void **)&stats, g_stats);
    cudaGetSymbolAddress((void **)&q_hi, g_q_hi);
    cudaGetSymbolAddress((void **)&q_lo, g_q_lo);
    cudaGetSymbolAddress((void **)&ka_hi, g_ka_hi);
    cudaGetSymbolAddress((void **)&ka_lo, g_ka_lo);
    cudaGetSymbolAddress((void **)&kT_hi, g_kT_hi);
    cudaGetSymbolAddress((void **)&kT_lo, g_kT_lo);
    cudaGetSymbolAddress((void **)&vT_hi, g_vT_hi);
    cudaGetSymbolAddress((void **)&vT_lo, g_vT_lo);
    cudaGetSymbolAddress((void **)&wT_hi, g_wT_hi);
    cudaGetSymbolAddress((void **)&wT_lo, g_wT_lo);

    cudaFuncSetAttribute(tc_skinny_f32, cudaFuncAttributeMaxDynamicSharedMemorySize, SKF_SMEM);
    cudaFuncSetAttribute(tc_wide,       cudaFuncAttributeMaxDynamicSharedMemorySize, WIDE_SMEM);

    const size_t NH_BYTES = (size_t)NCELL * HDIM * sizeof(float);
    const float SCALE = 0.08838834764831845f; // 1/sqrt(128)
    const float *bnS = stats + 256;
    const float *bnB = stats + 384;

    // 1. encoder: h = x @ enc_W[hid]  (raw; BN1 fused into sh1's A-load)
    wT_split<<<1024, 256>>>(enc_W, hid, wT_hi, wT_lo);
    cudaMemsetAsync(bufA, 0, NH_BYTES);
    tc_skinny_f32<<<dim3(64, 1, 8), 128, SKF_SMEM>>>(
        x, NINP, NINP, wT_hi, wT_lo, KPAD, bufA, HDIM, 256, 1.f);
    cudaMemsetAsync(stats, 0, 256 * sizeof(float));
    bn_stats<<<256, 128>>>(bufA, stats);
    bn_finalize<<<1, 128>>>(stats, enc_g, enc_be, hid, HDIM);

    // 2. sh1 = BN1(bufA) @ W1  (raw out)
    gemm_small<true><<<dim3(64, 1), 256>>>(bufA, sh_W1, bufB, HDIM, HDIM,
                                           nullptr, bnS, bnB);
    cudaMemsetAsync(stats, 0, 256 * sizeof(float));
    bn_stats<<<256, 128>>>(bufB, stats);
    bn_finalize<<<1, 128>>>(stats, sh_g1, sh_be1, nullptr, 0);

    // 3. sh2 = BN2(bufB) @ W2  (raw out)
    gemm_small<true><<<dim3(64, 1), 256>>>(bufB, sh_W2, bufA, HDIM, HDIM,
                                           nullptr, bnS, bnB);
    cudaMemsetAsync(stats, 0, 256 * sizeof(float));
    bn_stats<<<256, 128>>>(bufA, stats);
    bn_finalize<<<1, 128>>>(stats, sh_g2, sh_be2, nullptr, 0);

    // 4. qkv = BN3(bufA) @ qkv_W + qkv_b
    gemm_small<true><<<dim3(64, 3), 256>>>(bufA, qkv_W, qkv, 3 * HDIM, 3 * HDIM,
                                           qkv_b, bnS, bnB);

    // 5. small bf16 conversions (q, kT, vT)
    split_cols<<<1024, 256>>>(qkv, 3 * HDIM, 0, HDIM / 4, q_hi, q_lo);
    transpose_split<<<dim3(256, 4), dim3(32, 8)>>>(qkv, 3 * HDIM, HDIM, kT_hi, kT_lo);
    transpose_split<<<dim3(256, 4), dim3(32, 8)>>>(qkv, 3 * HDIM, 2 * HDIM, vT_hi, vT_lo);

    // 6. k_agg = spatial @ k
    cudaMemsetAsync(kagg, 0, NH_BYTES);
    tc_skinny_f32<<<dim3(64, 1, 8), 128, SKF_SMEM>>>(
        spatial, NCELL, NCELL, kT_hi, kT_lo, NCELL, kagg, HDIM, 1024, 1.f);
    split_cols<<<1024, 256>>>(kagg, HDIM, 0, HDIM / 4, ka_hi, ka_lo);

    // 7. logits = (q @ k_agg^T) / sqrt(H)
    tc_wide<<<dim3(64, 16), 128, WIDE_SMEM>>>(q_hi, q_lo, ka_hi, ka_lo, out_attn, SCALE);

    // 8. softmax in place
    softmax_row<<<NCELL, 256, NCELL * sizeof(float)>>>(out_attn);

    // 9. av = attn @ v
    cudaMemsetAsync(bufA, 0, NH_BYTES);
    tc_skinny_f32<<<dim3(64, 1, 8), 128, SKF_SMEM>>>(
        out_attn, NCELL, NCELL, vT_hi, vT_lo, NCELL, bufA, HDIM, 1024, 1.f);

    // 10. o = av @ o_W + o_b
    gemm_small<false><<<dim3(64, 1), 256>>>(bufA, o_W, bufB, HDIM, HDIM,
                                            o_b, nullptr, nullptr);

    // 11. variational heads
    const int heads_smem = (4096 + 4096 + 128 * 129) * sizeof(float);
    cudaFuncSetAttribute(heads_kernel, cudaFuncAttributeMaxDynamicSharedMemorySize,
                         heads_smem);
    heads_kernel<<<64, 256, heads_smem>>>(bufB, mean_W, mean_b, var_W, var_b,
                                          eps, out_qm, out_qv, out_lat);
}

// round 7
// speedup vs baseline: 1.2037x; 1.2037x over previous
#include <cuda_runtime.h>
#include <cuda_bf16.h>
#include <math.h>
#include <stdint.h>

#define NCELL 8192
#define NINP  2000
#define KPAD  2048
#define HDIM  128
#define NOUTD 32
#define BN_EPS 1e-3f

#define BM 128
#define BN 128
#define BK 16

#if defined(__CUDA_ARCH_FEAT_SM103_ALL) || defined(__CUDA_ARCH_FEAT_SM100_ALL) || \
    defined(__CUDA_ARCH_FEAT_SM110_ALL) || defined(__CUDA_ARCH_FEAT_SM101_ALL)
#define TC_ENABLED 1
#else
#define TC_ENABLED 0
#endif

// ---------------------------------------------------------------------------
// Scratch
// ---------------------------------------------------------------------------
__device__ __align__(256) float g_bufA[NCELL * HDIM];
__device__ __align__(256) float g_bufB[NCELL * HDIM];
__device__ __align__(256) float g_qkv [NCELL * 3 * HDIM];
__device__ __align__(256) float g_kagg[NCELL * HDIM];
__device__ __align__(256) float g_stats[512];

__device__ __align__(256) __nv_bfloat16 g_q_hi [NCELL * HDIM];
__device__ __align__(256) __nv_bfloat16 g_q_lo [NCELL * HDIM];
__device__ __align__(256) __nv_bfloat16 g_ka_hi[NCELL * HDIM];
__device__ __align__(256) __nv_bfloat16 g_ka_lo[NCELL * HDIM];
__device__ __align__(256) __nv_bfloat16 g_kT_hi[HDIM * NCELL];
__device__ __align__(256) __nv_bfloat16 g_kT_lo[HDIM * NCELL];
__device__ __align__(256) __nv_bfloat16 g_vT_hi[HDIM * NCELL];
__device__ __align__(256) __nv_bfloat16 g_vT_lo[HDIM * NCELL];
__device__ __align__(256) __nv_bfloat16 g_wT_hi[HDIM * KPAD];
__device__ __align__(256) __nv_bfloat16 g_wT_lo[HDIM * KPAD];

// ---------------------------------------------------------------------------
// PTX helpers
// ---------------------------------------------------------------------------
__device__ __forceinline__ uint32_t cvta_smem(const void *p) {
    uint32_t a;
    asm("{ .reg .u64 t; cvta.to.shared.u64 t, %1; cvt.u32.u64 %0, t; }"
        : "=r"(a) : "l"(p));
    return a;
}
__device__ __forceinline__ uint32_t elect_one() {
    uint32_t p;
    asm volatile("{ .reg .pred p; elect.sync _|p, 0xFFFFFFFF; selp.b32 %0, 1, 0, p; }"
                 : "=r"(p));
    return p;
}
__device__ __forceinline__ void mbar_init(uint32_t mbar, uint32_t cnt) {
    asm volatile("mbarrier.init.shared.b64 [%0], %1;"
                 :: "r"(mbar), "r"(cnt) : "memory");
}
__device__ __forceinline__ void mbar_wait(uint32_t mbar, uint32_t parity) {
    asm volatile(
        "{\n\t.reg .pred P;\n"
        "LW_%=:\n\t"
        "mbarrier.try_wait.parity.acquire.cta.shared::cta.b64 P, [%0], %1, 0x989680;\n\t"
        "@P bra LD_%=;\n\t"
        "bra LW_%=;\n"
        "LD_%=:\n\t}"
        :: "r"(mbar), "r"(parity) : "memory");
}
__device__ __forceinline__ void fence_async_smem() {
    asm volatile("fence.proxy.async.shared::cta;" ::: "memory");
}
__device__ __forceinline__ void cpa16(uint32_t dst, const void *src) {
    asm volatile("cp.async.cg.shared.global [%0], [%1], 16;"
                 :: "r"(dst), "l"(src) : "memory");
}
__device__ __forceinline__ void cpa_commit() {
    asm volatile("cp.async.commit_group;" ::: "memory");
}
template <int N>
__device__ __forceinline__ void cpa_wait() {
    asm volatile("cp.async.wait_group %0;" :: "n"(N) : "memory");
}
__device__ __forceinline__ void red4(float *p, float a, float b, float c, float d) {
    asm volatile("red.global.add.v4.f32 [%0], {%1, %2, %3, %4};"
                 :: "l"(p), "f"(a), "f"(b), "f"(c), "f"(d) : "memory");
}

// ---- tcgen05 ----
__device__ __forceinline__ void tc_alloc(uint32_t smem_dst, uint32_t ncols) {
    asm volatile("tcgen05.alloc.cta_group::1.sync.aligned.shared::cta.b32 [%0], %1;"
                 :: "r"(smem_dst), "r"(ncols) : "memory");
}
__device__ __forceinline__ void tc_dealloc(uint32_t tmem, uint32_t ncols) {
    asm volatile("tcgen05.dealloc.cta_group::1.sync.aligned.b32 %0, %1;"
                 :: "r"(tmem), "r"(ncols));
}
__device__ __forceinline__ void tc_relinquish() {
    asm volatile("tcgen05.relinquish_alloc_permit.cta_group::1.sync.aligned;");
}
__device__ __forceinline__ void tc_commit(uint32_t mbar) {
    asm volatile("tcgen05.commit.cta_group::1.mbarrier::arrive::one.shared::cluster.b64 [%0];"
                 :: "r"(mbar) : "memory");
}
__device__ __forceinline__ void tc_fence_after() {
    asm volatile("tcgen05.fence::after_thread_sync;" ::: "memory");
}
__device__ __forceinline__ void tc_wait_ld() {
    asm volatile("tcgen05.wait::ld.sync.aligned;" ::: "memory");
}
__device__ __forceinline__ void ldtm32(uint32_t *r, uint32_t addr) {
    asm volatile(
        "tcgen05.ld.sync.aligned.32x32b.x32.b32 "
        "{%0, %1, %2, %3, %4, %5, %6, %7, "
        " %8, %9, %10, %11, %12, %13, %14, %15, "
        " %16, %17, %18, %19, %20, %21, %22, %23, "
        " %24, %25, %26, %27, %28, %29, %30, %31}, [%32];"
        : "=r"(r[0]),  "=r"(r[1]),  "=r"(r[2]),  "=r"(r[3]),
          "=r"(r[4]),  "=r"(r[5]),  "=r"(r[6]),  "=r"(r[7]),
          "=r"(r[8]),  "=r"(r[9]),  "=r"(r[10]), "=r"(r[11]),
          "=r"(r[12]), "=r"(r[13]), "=r"(r[14]), "=r"(r[15]),
          "=r"(r[16]), "=r"(r[17]), "=r"(r[18]), "=r"(r[19]),
          "=r"(r[20]), "=r"(r[21]), "=r"(r[22]), "=r"(r[23]),
          "=r"(r[24]), "=r"(r[25]), "=r"(r[26]), "=r"(r[27]),
          "=r"(r[28]), "=r"(r[29]), "=r"(r[30]), "=r"(r[31])
        : "r"(addr));
}
__device__ __forceinline__ void mma_f16_ss(uint32_t d, uint64_t a_desc,
                                           uint64_t b_desc, uint32_t idesc,
                                           uint32_t en) {
    asm volatile(
        "{\n\t.reg .pred p;\n\t"
        "setp.ne.u32 p, %5, 0;\n\t"
        "tcgen05.mma.cta_group::1.kind::f16 [%0], %1, %2, %3, {%4, %4, %4, %4}, p;\n\t}"
        :: "r"(d), "l"(a_desc), "l"(b_desc), "r"(idesc), "r"(0u), "r"(en)
        : "memory");
}
__device__ __forceinline__ uint64_t make_desc(uint32_t addr) {
    return ((uint64_t)2 << 61) | ((uint64_t)1 << 46) | ((uint64_t)64 << 32) |
           ((uint64_t)1 << 16) | (((uint64_t)(addr >> 4)) & 0x3FFF);
}
__device__ __forceinline__ void fma2(float2 &c, const float2 &a, const float2 &b) {
    unsigned long long       &cc = reinterpret_cast<unsigned long long &>(c);
    const unsigned long long &aa = reinterpret_cast<const unsigned long long &>(a);
    const unsigned long long &bb = reinterpret_cast<const unsigned long long &>(b);
    asm("fma.rn.f32x2 %0, %1, %2, %0;" : "+l"(cc) : "l"(aa), "l"(bb));
}
__device__ __forceinline__ void split1(float v, __nv_bfloat16 &h, __nv_bfloat16 &l) {
    h = __float2bfloat16(v);
    l = __float2bfloat16(v - __bfloat162float(h));
}
__device__ __forceinline__ uint32_t pack2(__nv_bfloat16 a, __nv_bfloat16 b) {
    __nv_bfloat162 p(a, b);
    return *reinterpret_cast<uint32_t *>(&p);
}

static constexpr uint32_t TC_IDESC = 0x8200490u; // F32 acc, BF16xBF16, M=128, N=128

__device__ __forceinline__ uint32_t sw16(int r, int ch) {  // 128x64 bf16 tile
    uint32_t byte = (r >> 3) * 1024 + (r & 7) * 128 + ch * 16;
    return byte ^ ((byte >> 3) & 0x70);
}
__device__ __forceinline__ uint32_t sw32(int r, int ch) {  // 128x128 bf16 tile
    uint32_t byte = ((r >> 3) + (ch >> 3) * 16) * 1024 + (r & 7) * 128 + (ch & 7) * 16;
    return byte ^ ((byte >> 3) & 0x70);
}

// ---------------------------------------------------------------------------
// tc_skinny_f32 (Round-5 structure, verbatim): C += split(A_f32) @ (Bhi+Blo)^T
// ---------------------------------------------------------------------------
#define SKF_SMEM (1024 + 2 * 65536)

__global__ void __launch_bounds__(128)
tc_skinny_f32(const float *__restrict__ A, int lda, int Kvalid,
              const __nv_bfloat16 *__restrict__ Bhi,
              const __nv_bfloat16 *__restrict__ Blo, int ldb,
              float *__restrict__ C, int ldc, int kpc, float alpha)
{
#if TC_ENABLED
    extern __shared__ char sm[];
    const uint32_t sb = cvta_smem(sm);
    const int tid = threadIdx.x;
    const int wid = tid >> 5;

    if (wid == 0) tc_alloc(sb, 128);
    if (tid == 64) mbar_init(sb + 8, 1);
    __syncthreads();
    uint32_t tmem;
    asm volatile("ld.shared.b32 %0, [%1];" : "=r"(tmem) : "r"(sb));

    const int m0 = blockIdx.x * 128;
    const int kb0 = blockIdx.z * kpc;
    const int S = kpc >> 6;

    float4 regs[16];

    auto ldA = [&](int s) {
        const int kb = kb0 + s * 64;
#pragma unroll
        for (int i = 0; i < 16; ++i) {
            int g = i * 128 + tid;
            int r = g >> 4, ch = g & 15;
            int col = kb + ch * 4;
            if (col < Kvalid)
                regs[i] = *(const float4 *)(A + (size_t)(m0 + r) * lda + col);
            else
                regs[i] = make_float4(0.f, 0.f, 0.f, 0.f);
        }
    };
    auto ldB = [&](int s) {
        const uint32_t bh = sb + 1024 + (s & 1) * 65536 + 32768;
        const int kb = kb0 + s * 64;
#pragma unroll
        for (int i = 0; i < 8; ++i) {
            int g = i * 128 + tid;
            int r = g >> 3, ch = g & 7;
            uint32_t so = sw16(r, ch);
            cpa16(bh + so,         Bhi + (size_t)r * ldb + kb + ch * 8);
            cpa16(bh + 16384 + so, Blo + (size_t)r * ldb + kb + ch * 8);
        }
        cpa_commit();
    };
    auto stA = [&](int s) {
        char *ah = sm + 1024 + (s & 1) * 65536;
        char *al = ah + 16384;
#pragma unroll
        for (int i = 0; i < 16; ++i) {
            int g = i * 128 + tid;
            int r = g >> 4, ch = g & 15;
            float4 v = regs[i];
            __nv_bfloat16 h0, h1, h2, h3, l0, l1, l2, l3;
            split1(v.x, h0, l0); split1(v.y, h1, l1);
            split1(v.z, h2, l2); split1(v.w, h3, l3);
            uint32_t b = (uint32_t)(r * 128 + ch * 8);
            uint32_t sz = b ^ ((b >> 3) & 0x70);
            *(uint2 *)(ah + sz) = make_uint2(pack2(h0, h1), pack2(h2, h3));
            *(uint2 *)(al + sz) = make_uint2(pack2(l0, l1), pack2(l2, l3));
        }
    };

    ldB(0);
    ldA(0);
    uint32_t ph = 0;
    for (int s = 0; s < S; ++s) {
        cpa_wait<0>();     // B(s) in smem
        stA(s);            // regs(s) -> swizzled hi/lo smem
        __syncthreads();
        fence_async_smem();
        if (wid == 0 && elect_one()) {
            const uint32_t base = sb + 1024 + (s & 1) * 65536;
            uint64_t dah = make_desc(base);
            uint64_t dal = make_desc(base + 16384);
            uint64_t dbh = make_desc(base + 32768);
            uint64_t dbl = make_desc(base + 49152);
#pragma unroll
            for (int k = 0; k < 4; ++k) {
                uint64_t off = (uint64_t)(k * 2);
                mma_f16_ss(tmem, dah + off, dbh + off, TC_IDESC, (s > 0) || (k > 0));
                mma_f16_ss(tmem, dah + off, dbl + off, TC_IDESC, 1u);
                mma_f16_ss(tmem, dal + off, dbh + off, TC_IDESC, 1u);
            }
            tc_commit(sb + 8);
        }
        if (s + 1 < S) { ldB(s + 1); ldA(s + 1); }  // overlap MMA
        mbar_wait(sb + 8, ph);
        ph ^= 1;
        __syncthreads();
    }

    tc_fence_after();
#pragma unroll
    for (int part = 0; part < 4; ++part) {
        uint32_t d[32];
        ldtm32(d, tmem + part * 32);
        tc_wait_ld();
        float *cp = C + (size_t)(m0 + tid) * ldc + part * 32;
#pragma unroll
        for (int j = 0; j < 8; ++j)
            red4(cp + j * 4,
                 __uint_as_float(d[j * 4 + 0]) * alpha,
                 __uint_as_float(d[j * 4 + 1]) * alpha,
                 __uint_as_float(d[j * 4 + 2]) * alpha,
                 __uint_as_float(d[j * 4 + 3]) * alpha);
    }
    __syncthreads();
    if (wid == 0) {
        tc_relinquish();
        tc_dealloc(tmem, 128);
    }
#endif
}

// ---------------------------------------------------------------------------
// tc_wide (Round-5 structure, verbatim): 4 N-tiles per CTA, epilogue after loop
// ---------------------------------------------------------------------------
#define WIDE_SMEM (1024 + 65536 + 131072)

__global__ void __launch_bounds__(128)
tc_wide(const __nv_bfloat16 *__restrict__ Ahi, const __nv_bfloat16 *__restrict__ Alo,
        const __nv_bfloat16 *__restrict__ Bhi, const __nv_bfloat16 *__restrict__ Blo,
        float *__restrict__ C, float alpha)
{
#if TC_ENABLED
    extern __shared__ char sm[];
    const uint32_t sb = cvta_smem(sm);
    const int tid = threadIdx.x;
    const int wid = tid >> 5;

    if (wid == 0) tc_alloc(sb, 512);
    if (tid == 64) mbar_init(sb + 8, 1);
    __syncthreads();
    uint32_t tmem;
    asm volatile("ld.shared.b32 %0, [%1];" : "=r"(tmem) : "r"(sb));

    const int m0 = blockIdx.x * 128;
    const int ng0 = blockIdx.y * 512;

    const uint32_t A0 = sb + 1024;
    const uint32_t A1 = A0 + 32768;

    auto load_B = [&](int n) {
        const uint32_t base = sb + 1024 + 65536 + (n & 1) * 65536;
        const int r0 = ng0 + n * 128;
#pragma unroll
        for (int i = tid; i < 2048; i += 128) {
            int r = i >> 4, ch = i & 15;
            uint32_t so = sw32(r, ch);
            cpa16(base + so,         Bhi + (size_t)(r0 + r) * HDIM + ch * 8);
            cpa16(base + 32768 + so, Blo + (size_t)(r0 + r) * HDIM + ch * 8);
        }
        cpa_commit();
    };

#pragma unroll
    for (int i = tid; i < 2048; i += 128) {
        int r = i >> 4, ch = i & 15;
        uint32_t so = sw32(r, ch);
        cpa16(A0 + so, Ahi + (size_t)(m0 + r) * HDIM + ch * 8);
        cpa16(A1 + so, Alo + (size_t)(m0 + r) * HDIM + ch * 8);
    }
    {
        const uint32_t base = sb + 1024 + 65536;
#pragma unroll
        for (int i = tid; i < 2048; i += 128) {
            int r = i >> 4, ch = i & 15;
            uint32_t so = sw32(r, ch);
            cpa16(base + so,         Bhi + (size_t)(ng0 + r) * HDIM + ch * 8);
            cpa16(base + 32768 + so, Blo + (size_t)(ng0 + r) * HDIM + ch * 8);
        }
    }
    cpa_commit();

    uint32_t ph = 0;
    for (int n = 0; n < 4; ++n) {
        if (n + 1 < 4) { load_B(n + 1); cpa_wait<1>(); }
        else           { cpa_wait<0>(); }
        __syncthreads();
        fence_async_smem();
        if (wid == 0 && elect_one()) {
            const uint32_t bbase = sb + 1024 + 65536 + (n & 1) * 65536;
            uint64_t dah = make_desc(A0);
            uint64_t dal = make_desc(A1);
            uint64_t dbh = make_desc(bbase);
            uint64_t dbl = make_desc(bbase + 32768);
            const uint32_t acc = tmem + n * 128;
#pragma unroll
            for (int k = 0; k < 8; ++k) {
                uint64_t off = (uint64_t)((k & 3) * 2 + (k >> 2) * 1024);
                mma_f16_ss(acc, dah + off, dbh + off, TC_IDESC, k > 0);
                mma_f16_ss(acc, dah + off, dbl + off, TC_IDESC, 1u);
                mma_f16_ss(acc, dal + off, dbh + off, TC_IDESC, 1u);
            }
            tc_commit(sb + 8);
        }
        mbar_wait(sb + 8, ph);
        ph ^= 1;
        __syncthreads();
    }

    tc_fence_after();
    float *st = (float *)(sm + 1024);
    for (int n = 0; n < 4; ++n) {
#pragma unroll
        for (int part = 0; part < 4; ++part) {
            uint32_t d[32];
            ldtm32(d, tmem + n * 128 + part * 32);
            tc_wait_ld();
#pragma unroll
            for (int c = 0; c < 32; ++c)
                st[tid * 33 + c] = __uint_as_float(d[c]) * alpha;
            __syncthreads();
            const int col0 = ng0 + n * 128 + part * 32;
#pragma unroll
            for (int i = 0; i < 32; ++i) {
                int idx = i * 128 + tid;
                int rr = idx >> 5, cc = idx & 31;
                C[(size_t)(m0 + rr) * NCELL + col0 + cc] = st[rr * 33 + cc];
            }
            __syncthreads();
        }
    }
    __syncthreads();
    if (wid == 0) {
        tc_relinquish();
        tc_dealloc(tmem, 512);
    }
#endif
}

// ---------------------------------------------------------------------------
// fp32 -> bf16 hi/lo split kernels
// ---------------------------------------------------------------------------
__global__ void split_cols(const float *__restrict__ src, int ldsrc, int col0,
                           int cols4, __nv_bfloat16 *__restrict__ hi,
                           __nv_bfloat16 *__restrict__ lo)
{
    int idx = blockIdx.x * blockDim.x + threadIdx.x;
    int r = idx / cols4, c = idx - r * cols4;
    float4 v = *(const float4 *)(src + (size_t)r * ldsrc + col0 + c * 4);
    __nv_bfloat16 h0, h1, h2, h3, l0, l1, l2, l3;
    split1(v.x, h0, l0); split1(v.y, h1, l1);
    split1(v.z, h2, l2); split1(v.w, h3, l3);
    __nv_bfloat162 *ph = (__nv_bfloat162 *)(hi + (size_t)idx * 4);
    __nv_bfloat162 *pl = (__nv_bfloat162 *)(lo + (size_t)idx * 4);
    ph[0] = __nv_bfloat162(h0, h1); ph[1] = __nv_bfloat162(h2, h3);
    pl[0] = __nv_bfloat162(l0, l1); pl[1] = __nv_bfloat162(l2, l3);
}

__global__ void wT_split(const float *__restrict__ W, const int *__restrict__ hid,
                         __nv_bfloat16 *__restrict__ hi, __nv_bfloat16 *__restrict__ lo)
{
    int idx = blockIdx.x * blockDim.x + threadIdx.x;   // 128*2048
    int r = idx >> 7;
    int c = idx & 127;
    const float *Wh = W + (size_t)hid[0] * NINP * HDIM;
    float v = (r < NINP) ? Wh[(size_t)r * HDIM + c] : 0.f;
    __nv_bfloat16 h, l;
    split1(v, h, l);
    size_t o = (size_t)c * KPAD + r;
    hi[o] = h;
    lo[o] = l;
}

__global__ void transpose_split(const float *__restrict__ src, int ldsrc, int col0,
                                __nv_bfloat16 *__restrict__ hi,
                                __nv_bfloat16 *__restrict__ lo)
{
    __shared__ float t[32][33];
    int r0 = blockIdx.x * 32, c0 = blockIdx.y * 32;
    int tx = threadIdx.x, ty = threadIdx.y;  // 32 x 8
#pragma unroll
    for (int i = 0; i < 4; ++i) {
        int r = ty + i * 8;
        t[r][tx] = src[(size_t)(r0 + r) * ldsrc + col0 + c0 + tx];
    }
    __syncthreads();
#pragma unroll
    for (int i = 0; i < 4; ++i) {
        int c = ty + i * 8;
        float v = t[tx][c];
        __nv_bfloat16 h, l;
        split1(v, h, l);
        size_t o = (size_t)(c0 + c) * NCELL + r0 + tx;
        hi[o] = h;
        lo[o] = l;
    }
}

// ---------------------------------------------------------------------------
// gemm_small: C[M,N] = bnrelu(A)[M,128] @ B[128,N] (+bias), direct store.
// ---------------------------------------------------------------------------
template <bool BNA>
__global__ void __launch_bounds__(256)
gemm_small(const float *__restrict__ A, const float *__restrict__ B,
           float *__restrict__ C, int ldb, int ldc,
           const float *__restrict__ bias,
           const float *__restrict__ bnS, const float *__restrict__ bnB)
{
    __shared__ float As[BK][BM + 4];
    __shared__ float Bs[BK][BN + 4];
    __shared__ float bnSs[128], bnBs[128];

    const int tid = threadIdx.x;
    const int tx = tid & 15;
    const int ty = tid >> 4;
    const int m0 = blockIdx.x * BM;
    const int n0 = blockIdx.y * BN;

    if (BNA && tid < 128) { bnSs[tid] = bnS[tid]; bnBs[tid] = bnB[tid]; }

    const int f0 = tid, f1 = tid + 256;
    const int aRow0 = f0 >> 2, aK0 = (f0 & 3) * 4;
    const int aRow1 = f1 >> 2, aK1 = (f1 & 3) * 4;
    const int bK0 = f0 >> 5, bN0 = (f0 & 31) * 4;
    const int bK1 = f1 >> 5, bN1 = (f1 & 31) * 4;

    const float *Ap0 = A + (size_t)(m0 + aRow0) * HDIM + aK0;
    const float *Ap1 = A + (size_t)(m0 + aRow1) * HDIM + aK1;
    const float *Bp0 = B + (size_t)bK0 * ldb + n0 + bN0;
    const float *Bp1 = B + (size_t)bK1 * ldb + n0 + bN1;

    float2 acc[8][4];
#pragma unroll
    for (int i = 0; i < 8; ++i)
#pragma unroll
        for (int j = 0; j < 4; ++j) acc[i][j] = make_float2(0.f, 0.f);

    float4 ra0 = *(const float4 *)Ap0;
    float4 ra1 = *(const float4 *)Ap1;
    float4 rb0 = *(const float4 *)Bp0;
    float4 rb1 = *(const float4 *)Bp1;

    const int chunks = HDIM / BK;   // 8
    for (int c = 0; c < chunks; ++c) {
        __syncthreads();
        const int cK = c * BK;
        if (BNA) {
            As[aK0 + 0][aRow0] = fmaxf(fmaf(ra0.x, bnSs[cK + aK0 + 0], bnBs[cK + aK0 + 0]), 0.f);
            As[aK0 + 1][aRow0] = fmaxf(fmaf(ra0.y, bnSs[cK + aK0 + 1], bnBs[cK + aK0 + 1]), 0.f);
            As[aK0 + 2][aRow0] = fmaxf(fmaf(ra0.z, bnSs[cK + aK0 + 2], bnBs[cK + aK0 + 2]), 0.f);
            As[aK0 + 3][aRow0] = fmaxf(fmaf(ra0.w, bnSs[cK + aK0 + 3], bnBs[cK + aK0 + 3]), 0.f);
            As[aK1 + 0][aRow1] = fmaxf(fmaf(ra1.x, bnSs[cK + aK1 + 0], bnBs[cK + aK1 + 0]), 0.f);
            As[aK1 + 1][aRow1] = fmaxf(fmaf(ra1.y, bnSs[cK + aK1 + 1], bnBs[cK + aK1 + 1]), 0.f);
            As[aK1 + 2][aRow1] = fmaxf(fmaf(ra1.z, bnSs[cK + aK1 + 2], bnBs[cK + aK1 + 2]), 0.f);
            As[aK1 + 3][aRow1] = fmaxf(fmaf(ra1.w, bnSs[cK + aK1 + 3], bnBs[cK + aK1 + 3]), 0.f);
        } else {
            As[aK0 + 0][aRow0] = ra0.x; As[aK0 + 1][aRow0] = ra0.y;
            As[aK0 + 2][aRow0] = ra0.z; As[aK0 + 3][aRow0] = ra0.w;
            As[aK1 + 0][aRow1] = ra1.x; As[aK1 + 1][aRow1] = ra1.y;
            As[aK1 + 2][aRow1] = ra1.z; As[aK1 + 3][aRow1] = ra1.w;
        }
        *(float4 *)&Bs[bK0][bN0] = rb0;
        *(float4 *)&Bs[bK1][bN1] = rb1;
        __syncthreads();

        if (c + 1 < chunks) {
            Ap0 += BK; Ap1 += BK;
            ra0 = *(const float4 *)Ap0;
            ra1 = *(const float4 *)Ap1;
            Bp0 += (size_t)BK * ldb; Bp1 += (size_t)BK * ldb;
            rb0 = *(const float4 *)Bp0;
            rb1 = *(const float4 *)Bp1;
        }

#pragma unroll
        for (int kk = 0; kk < BK; ++kk) {
            float4 a0 = *(const float4 *)&As[kk][ty * 4];
            float4 a1 = *(const float4 *)&As[kk][64 + ty * 4];
            float4 b0 = *(const float4 *)&Bs[kk][tx * 4];
            float4 b1 = *(const float4 *)&Bs[kk][64 + tx * 4];
            float av[8] = {a0.x, a0.y, a0.z, a0.w, a1.x, a1.y, a1.z, a1.w};
            float2 bp[4] = {make_float2(b0.x, b0.y), make_float2(b0.z, b0.w),
                            make_float2(b1.x, b1.y), make_float2(b1.z, b1.w)};
#pragma unroll
            for (int i = 0; i < 8; ++i) {
                float2 aa = make_float2(av[i], av[i]);
#pragma unroll
                for (int j = 0; j < 4; ++j) fma2(acc[i][j], aa, bp[j]);
            }
        }
    }

    float bad0[4] = {0.f, 0.f, 0.f, 0.f}, bad1[4] = {0.f, 0.f, 0.f, 0.f};
    if (bias != nullptr) {
#pragma unroll
        for (int j = 0; j < 4; ++j) {
            bad0[j] = bias[n0 + tx * 4 + j];
            bad1[j] = bias[n0 + 64 + tx * 4 + j];
        }
    }
#pragma unroll
    for (int i = 0; i < 8; ++i) {
        int r = m0 + ((i < 4) ? (ty * 4 + i) : (64 + ty * 4 + (i - 4)));
        float v[8] = {acc[i][0].x, acc[i][0].y, acc[i][1].x, acc[i][1].y,
                      acc[i][2].x, acc[i][2].y, acc[i][3].x, acc[i][3].y};
        float *crow = C + (size_t)r * ldc;
        float4 w0 = make_float4(v[0] + bad0[0], v[1] + bad0[1],
                                v[2] + bad0[2], v[3] + bad0[3]);
        float4 w1 = make_float4(v[4] + bad1[0], v[5] + bad1[1],
                                v[6] + bad1[2], v[7] + bad1[3]);
        *(float4 *)(crow + n0 + tx * 4) = w0;
        *(float4 *)(crow + n0 + 64 + tx * 4) = w1;
    }
}

// ---------------------------------------------------------------------------
// BatchNorm stats
// ---------------------------------------------------------------------------
__global__ void bn_stats(const float *__restrict__ h, float *__restrict__ stats)
{
    int col = threadIdx.x;
    int r0 = blockIdx.x * 32;
    float s = 0.f, s2 = 0.f;
#pragma unroll 8
    for (int r = 0; r < 32; ++r) {
        float v = h[(size_t)(r0 + r) * HDIM + col];
        s += v; s2 += v * v;
    }
    atomicAdd(&stats[col], s);
    atomicAdd(&stats[128 + col], s2);
}

__global__ void bn_finalize(float *__restrict__ stats,
                            const float *__restrict__ g, const float *__restrict__ be,
                            const int *__restrict__ hid, int headStride)
{
    int c = threadIdx.x;
    int off = hid ? hid[0] * headStride : 0;
    float mean = stats[c] * (1.f / (float)NCELL);
    float var = stats[128 + c] * (1.f / (float)NCELL) - mean * mean;
    float rstd = rsqrtf(var + BN_EPS);
    float gg = g[off + c];
    stats[256 + c] = gg * rstd;
    stats[384 + c] = be[off + c] - gg * mean * rstd;
}

// ---------------------------------------------------------------------------
// Row softmax in place
// ---------------------------------------------------------------------------
__global__ void softmax_row(float *__restrict__ attn)
{
    extern __shared__ float row[];
    __shared__ float red[256];
    const int t = threadIdx.x;
    float *p = attn + (size_t)blockIdx.x * NCELL;

    float m = -1e30f;
    for (int i = t; i < NCELL / 4; i += 256) {
        float4 v = ((const float4 *)p)[i];
        ((float4 *)row)[i] = v;
        m = fmaxf(m, fmaxf(fmaxf(v.x, v.y), fmaxf(v.z, v.w)));
    }
    red[t] = m; __syncthreads();
    for (int s = 128; s > 0; s >>= 1) {
        if (t < s) red[t] = fmaxf(red[t], red[t + s]);
        __syncthreads();
    }
    const float bmax = red[0];
    __syncthreads();

    float sum = 0.f;
    for (int i = t; i < NCELL / 4; i += 256) {
        float4 v = ((float4 *)row)[i];
        v.x = __expf(v.x - bmax); v.y = __expf(v.y - bmax);
        v.z = __expf(v.z - bmax); v.w = __expf(v.w - bmax);
        sum += v.x + v.y + v.z + v.w;
        ((float4 *)row)[i] = v;
    }
    red[t] = sum; __syncthreads();
    for (int s = 128; s > 0; s >>= 1) {
        if (t < s) red[t] += red[t + s];
        __syncthreads();
    }
    const float inv = 1.f / red[0];
    __syncthreads();

    for (int i = t; i < NCELL / 4; i += 256) {
        float4 v = ((float4 *)row)[i];
        v.x *= inv; v.y *= inv; v.z *= inv; v.w *= inv;
        ((float4 *)p)[i] = v;
    }
}

// ---------------------------------------------------------------------------
// Variational heads
// ---------------------------------------------------------------------------
__global__ void heads_kernel(const float *__restrict__ o,
                             const float *__restrict__ mW, const float *__restrict__ mb,
                             const float *__restrict__ vW, const float *__restrict__ vb,
                             const float *__restrict__ eps,
                             float *__restrict__ qm, float *__restrict__ qv,
                             float *__restrict__ lat)
{
    extern __shared__ float smh[];
    float *Wm  = smh;
    float *Wv  = smh + 4096;
    float *osm = smh + 8192;
    const int t = threadIdx.x;
    const int r0 = blockIdx.x * 128;

    for (int i = t; i < HDIM * NOUTD; i += 256) { Wm[i] = mW[i]; Wv[i] = vW[i]; }
    for (int i = t; i < 128 * HDIM; i += 256) {
        int r = i >> 7, c = i & 127;
        osm[r * 129 + c] = o[(size_t)(r0 + r) * HDIM + c];
    }
    __syncthreads();

    for (int idx = t; idx < 128 * NOUTD; idx += 256) {
        int r = idx >> 5, c = idx & 31;
        const float *orow = &osm[r * 129];
        float dm = 0.f, dv = 0.f;
#pragma unroll 8
        for (int k = 0; k < HDIM; ++k) {
            float ov = orow[k];
            dm += ov * Wm[k * NOUTD + c];
            dv += ov * Wv[k * NOUTD + c];
        }
        int R = r0 + r;
        float mval = dm + mb[c];
        float vval = __expf(dv + vb[c]);
        qm[R * NOUTD + c]  = mval;
        qv[R * NOUTD + c]  = vval;
        lat[R * NOUTD + c] = mval + sqrtf(vval) * eps[R * NOUTD + c];
    }
}

// ---------------------------------------------------------------------------
// Launch
// ---------------------------------------------------------------------------
extern "C" void kernel_launch(void *const *d_in, const int *in_sizes, int n_in,
                              void *d_out, int out_size)
{
    const float *x       = (const float *)d_in[0];
    const float *spatial = (const float *)d_in[1];
    const float *eps     = (const float *)d_in[2];
    const float *enc_W   = (const float *)d_in[3];
    const float *enc_g   = (const float *)d_in[5];
    const float *enc_be  = (const float *)d_in[6];
    const float *sh_W1   = (const float *)d_in[7];
    const float *sh_g1   = (const float *)d_in[9];
    const float *sh_be1  = (const float *)d_in[10];
    const float *sh_W2   = (const float *)d_in[11];
    const float *sh_g2   = (const float *)d_in[13];
    const float *sh_be2  = (const float *)d_in[14];
    const float *qkv_W   = (const float *)d_in[15];
    const float *qkv_b   = (const float *)d_in[16];
    const float *o_W     = (const float *)d_in[17];
    const float *o_b     = (const float *)d_in[18];
    const float *mean_W  = (const float *)d_in[19];
    const float *mean_b  = (const float *)d_in[20];
    const float *var_W   = (const float *)d_in[21];
    const float *var_b   = (const float *)d_in[22];
    const int   *hid     = (const int *)d_in[23];

    float *out = (float *)d_out;
    float *out_qm   = out;
    float *out_qv   = out + (size_t)NCELL * NOUTD;
    float *out_lat  = out + 2 * (size_t)NCELL * NOUTD;
    float *out_attn = out + 3 * (size_t)NCELL * NOUTD;

    float *bufA, *bufB, *qkv, *kagg, *stats;
    __nv_bfloat16 *q_hi, *q_lo, *ka_hi, *ka_lo;
    __nv_bfloat16 *kT_hi, *kT_lo, *vT_hi, *vT_lo, *wT_hi, *wT_lo;
    cudaGetSymbolAddress((void **)&bufA, g_bufA);
    cudaGetSymbolAddress((void **)&bufB, g_bufB);
    cudaGetSymbolAddress((void **)&qkv,  g_qkv);
    cudaGetSymbolAddress((void **)&kagg, g_kagg);
    cudaGetSymbolAddress((void **)&stats, g_stats);
    cudaGetSymbolAddress((void **)&q_hi, g_q_hi);
    cudaGetSymbolAddress((void **)&q_lo, g_q_lo);
    cudaGetSymbolAddress((void **)&ka_hi, g_ka_hi);
    cudaGetSymbolAddress((void **)&ka_lo, g_ka_lo);
    cudaGetSymbolAddress((void **)&kT_hi, g_kT_hi);
    cudaGetSymbolAddress((void **)&kT_lo, g_kT_lo);
    cudaGetSymbolAddress((void **)&vT_hi, g_vT_hi);
    cudaGetSymbolAddress((void **)&vT_lo, g_vT_lo);
    cudaGetSymbolAddress((void **)&wT_hi, g_wT_hi);
    cudaGetSymbolAddress((void **)&wT_lo, g_wT_lo);

    cudaFuncSetAttribute(tc_skinny_f32, cudaFuncAttributeMaxDynamicSharedMemorySize, SKF_SMEM);
    cudaFuncSetAttribute(tc_wide,       cudaFuncAttributeMaxDynamicSharedMemorySize, WIDE_SMEM);

    const size_t NH_BYTES = (size_t)NCELL * HDIM * sizeof(float);
    const float SCALE = 0.08838834764831845f; // 1/sqrt(128)
    const float *bnS = stats + 256;
    const float *bnB = stats + 384;

    // 1. encoder: h = x @ enc_W[hid]  (raw; BN1 fused into sh1's A-load)
    wT_split<<<1024, 256>>>(enc_W, hid, wT_hi, wT_lo);
    cudaMemsetAsync(bufA, 0, NH_BYTES);
    tc_skinny_f32<<<dim3(64, 1, 4), 128, SKF_SMEM>>>(
        x, NINP, NINP, wT_hi, wT_lo, KPAD, bufA, HDIM, 512, 1.f);
    cudaMemsetAsync(stats, 0, 256 * sizeof(float));
    bn_stats<<<256, 128>>>(bufA, stats);
    bn_finalize<<<1, 128>>>(stats, enc_g, enc_be, hid, HDIM);

    // 2. sh1 = BN1(bufA) @ W1
    gemm_small<true><<<dim3(64, 1), 256>>>(bufA, sh_W1, bufB, HDIM, HDIM,
                                           nullptr, bnS, bnB);
    cudaMemsetAsync(stats, 0, 256 * sizeof(float));
    bn_stats<<<256, 128>>>(bufB, stats);
    bn_finalize<<<1, 128>>>(stats, sh_g1, sh_be1, nullptr, 0);

    // 3. sh2 = BN2(bufB) @ W2
    gemm_small<true><<<dim3(64, 1), 256>>>(bufB, sh_W2, bufA, HDIM, HDIM,
                                           nullptr, bnS, bnB);
    cudaMemsetAsync(stats, 0, 256 * sizeof(float));
    bn_stats<<<256, 128>>>(bufA, stats);
    bn_finalize<<<1, 128>>>(stats, sh_g2, sh_be2, nullptr, 0);

    // 4. qkv = BN3(bufA) @ qkv_W + qkv_b
    gemm_small<true><<<dim3(64, 3), 256>>>(bufA, qkv_W, qkv, 3 * HDIM, 3 * HDIM,
                                           qkv_b, bnS, bnB);

    // 5. small bf16 conversions (q, kT, vT)
    split_cols<<<1024, 256>>>(qkv, 3 * HDIM, 0, HDIM / 4, q_hi, q_lo);
    transpose_split<<<dim3(256, 4), dim3(32, 8)>>>(qkv, 3 * HDIM, HDIM, kT_hi, kT_lo);
    transpose_split<<<dim3(256, 4), dim3(32, 8)>>>(qkv, 3 * HDIM, 2 * HDIM, vT_hi, vT_lo);

    // 6. k_agg = spatial @ k   (split-K = 4)
    cudaMemsetAsync(kagg, 0, NH_BYTES);
    tc_skinny_f32<<<dim3(64, 1, 4), 128, SKF_SMEM>>>(
        spatial, NCELL, NCELL, kT_hi, kT_lo, NCELL, kagg, HDIM, 2048, 1.f);
    split_cols<<<1024, 256>>>(kagg, HDIM, 0, HDIM / 4, ka_hi, ka_lo);

    // 7. logits = (q @ k_agg^T) / sqrt(H)
    tc_wide<<<dim3(64, 16), 128, WIDE_SMEM>>>(q_hi, q_lo, ka_hi, ka_lo, out_attn, SCALE);

    // 8. softmax in place
    softmax_row<<<NCELL, 256, NCELL * sizeof(float)>>>(out_attn);

    // 9. av = attn @ v   (split-K = 4)
    cudaMemsetAsync(bufA, 0, NH_BYTES);
    tc_skinny_f32<<<dim3(64, 1, 4), 128, SKF_SMEM>>>(
        out_attn, NCELL, NCELL, vT_hi, vT_lo, NCELL, bufA, HDIM, 2048, 1.f);

    // 10. o = av @ o_W + o_b
    gemm_small<false><<<dim3(64, 1), 256>>>(bufA, o_W, bufB, HDIM, HDIM,
                                            o_b, nullptr, nullptr);

    // 11. variational heads
    const int heads_smem = (4096 + 4096 + 128 * 129) * sizeof(float);
    cudaFuncSetAttribute(heads_kernel, cudaFuncAttributeMaxDynamicSharedMemorySize,
                         heads_smem);
    heads_kernel<<<64, 256, heads_smem>>>(bufB, mean_W, mean_b, var_W, var_b,
                                          eps, out_qm, out_qv, out_lat);
}

// round 8
// speedup vs baseline: 1.3089x; 1.0874x over previous
#include <cuda_runtime.h>
#include <cuda_bf16.h>
#include <math.h>
#include <stdint.h>

#define NCELL 8192
#define NINP  2000
#define KPAD  2048
#define HDIM  128
#define NOUTD 32
#define BN_EPS 1e-3f

#define BM 128
#define BN 128
#define BK 16

#if defined(__CUDA_ARCH_FEAT_SM103_ALL) || defined(__CUDA_ARCH_FEAT_SM100_ALL) || \
    defined(__CUDA_ARCH_FEAT_SM110_ALL) || defined(__CUDA_ARCH_FEAT_SM101_ALL)
#define TC_ENABLED 1
#else
#define TC_ENABLED 0
#endif

// ---------------------------------------------------------------------------
// Scratch
// ---------------------------------------------------------------------------
__device__ __align__(256) float g_bufA[NCELL * HDIM];
__device__ __align__(256) float g_bufB[NCELL * HDIM];
__device__ __align__(256) float g_qkv [NCELL * 3 * HDIM];
__device__ __align__(256) float g_kagg[NCELL * HDIM];
__device__ __align__(256) float g_stats[768];   // 3 BN slots x (sum[128], sumsq[128])

__device__ __align__(256) __nv_bfloat16 g_q_hi [NCELL * HDIM];
__device__ __align__(256) __nv_bfloat16 g_q_lo [NCELL * HDIM];
__device__ __align__(256) __nv_bfloat16 g_ka_hi[NCELL * HDIM];
__device__ __align__(256) __nv_bfloat16 g_ka_lo[NCELL * HDIM];
__device__ __align__(256) __nv_bfloat16 g_kT_hi[HDIM * NCELL];
__device__ __align__(256) __nv_bfloat16 g_kT_lo[HDIM * NCELL];
__device__ __align__(256) __nv_bfloat16 g_vT_hi[HDIM * NCELL];
__device__ __align__(256) __nv_bfloat16 g_vT_lo[HDIM * NCELL];
__device__ __align__(256) __nv_bfloat16 g_wT_hi[HDIM * KPAD];
__device__ __align__(256) __nv_bfloat16 g_wT_lo[HDIM * KPAD];

// ---------------------------------------------------------------------------
// PTX helpers
// ---------------------------------------------------------------------------
__device__ __forceinline__ uint32_t cvta_smem(const void *p) {
    uint32_t a;
    asm("{ .reg .u64 t; cvta.to.shared.u64 t, %1; cvt.u32.u64 %0, t; }"
        : "=r"(a) : "l"(p));
    return a;
}
__device__ __forceinline__ uint32_t elect_one() {
    uint32_t p;
    asm volatile("{ .reg .pred p; elect.sync _|p, 0xFFFFFFFF; selp.b32 %0, 1, 0, p; }"
                 : "=r"(p));
    return p;
}
__device__ __forceinline__ void mbar_init(uint32_t mbar, uint32_t cnt) {
    asm volatile("mbarrier.init.shared.b64 [%0], %1;"
                 :: "r"(mbar), "r"(cnt) : "memory");
}
__device__ __forceinline__ void mbar_wait(uint32_t mbar, uint32_t parity) {
    asm volatile(
        "{\n\t.reg .pred P;\n"
        "LW_%=:\n\t"
        "mbarrier.try_wait.parity.acquire.cta.shared::cta.b64 P, [%0], %1, 0x989680;\n\t"
        "@P bra LD_%=;\n\t"
        "bra LW_%=;\n"
        "LD_%=:\n\t}"
        :: "r"(mbar), "r"(parity) : "memory");
}
__device__ __forceinline__ void fence_async_smem() {
    asm volatile("fence.proxy.async.shared::cta;" ::: "memory");
}
__device__ __forceinline__ void cpa16(uint32_t dst, const void *src) {
    asm volatile("cp.async.cg.shared.global [%0], [%1], 16;"
                 :: "r"(dst), "l"(src) : "memory");
}
__device__ __forceinline__ void cpa_commit() {
    asm volatile("cp.async.commit_group;" ::: "memory");
}
template <int N>
__device__ __forceinline__ void cpa_wait() {
    asm volatile("cp.async.wait_group %0;" :: "n"(N) : "memory");
}
__device__ __forceinline__ void red4(float *p, float a, float b, float c, float d) {
    asm volatile("red.global.add.v4.f32 [%0], {%1, %2, %3, %4};"
                 :: "l"(p), "f"(a), "f"(b), "f"(c), "f"(d) : "memory");
}

// ---- tcgen05 ----
__device__ __forceinline__ void tc_alloc(uint32_t smem_dst, uint32_t ncols) {
    asm volatile("tcgen05.alloc.cta_group::1.sync.aligned.shared::cta.b32 [%0], %1;"
                 :: "r"(smem_dst), "r"(ncols) : "memory");
}
__device__ __forceinline__ void tc_dealloc(uint32_t tmem, uint32_t ncols) {
    asm volatile("tcgen05.dealloc.cta_group::1.sync.aligned.b32 %0, %1;"
                 :: "r"(tmem), "r"(ncols));
}
__device__ __forceinline__ void tc_relinquish() {
    asm volatile("tcgen05.relinquish_alloc_permit.cta_group::1.sync.aligned;");
}
__device__ __forceinline__ void tc_commit(uint32_t mbar) {
    asm volatile("tcgen05.commit.cta_group::1.mbarrier::arrive::one.shared::cluster.b64 [%0];"
                 :: "r"(mbar) : "memory");
}
__device__ __forceinline__ void tc_fence_after() {
    asm volatile("tcgen05.fence::after_thread_sync;" ::: "memory");
}
__device__ __forceinline__ void tc_wait_ld() {
    asm volatile("tcgen05.wait::ld.sync.aligned;" ::: "memory");
}
__device__ __forceinline__ void ldtm32(uint32_t *r, uint32_t addr) {
    asm volatile(
        "tcgen05.ld.sync.aligned.32x32b.x32.b32 "
        "{%0, %1, %2, %3, %4, %5, %6, %7, "
        " %8, %9, %10, %11, %12, %13, %14, %15, "
        " %16, %17, %18, %19, %20, %21, %22, %23, "
        " %24, %25, %26, %27, %28, %29, %30, %31}, [%32];"
        : "=r"(r[0]),  "=r"(r[1]),  "=r"(r[2]),  "=r"(r[3]),
          "=r"(r[4]),  "=r"(r[5]),  "=r"(r[6]),  "=r"(r[7]),
          "=r"(r[8]),  "=r"(r[9]),  "=r"(r[10]), "=r"(r[11]),
          "=r"(r[12]), "=r"(r[13]), "=r"(r[14]), "=r"(r[15]),
          "=r"(r[16]), "=r"(r[17]), "=r"(r[18]), "=r"(r[19]),
          "=r"(r[20]), "=r"(r[21]), "=r"(r[22]), "=r"(r[23]),
          "=r"(r[24]), "=r"(r[25]), "=r"(r[26]), "=r"(r[27]),
          "=r"(r[28]), "=r"(r[29]), "=r"(r[30]), "=r"(r[31])
        : "r"(addr));
}
__device__ __forceinline__ void mma_f16_ss(uint32_t d, uint64_t a_desc,
                                           uint64_t b_desc, uint32_t idesc,
                                           uint32_t en) {
    asm volatile(
        "{\n\t.reg .pred p;\n\t"
        "setp.ne.u32 p, %5, 0;\n\t"
        "tcgen05.mma.cta_group::1.kind::f16 [%0], %1, %2, %3, {%4, %4, %4, %4}, p;\n\t}"
        :: "r"(d), "l"(a_desc), "l"(b_desc), "r"(idesc), "r"(0u), "r"(en)
        : "memory");
}
__device__ __forceinline__ uint64_t make_desc(uint32_t addr) {
    return ((uint64_t)2 << 61) | ((uint64_t)1 << 46) | ((uint64_t)64 << 32) |
           ((uint64_t)1 << 16) | (((uint64_t)(addr >> 4)) & 0x3FFF);
}
__device__ __forceinline__ void fma2(float2 &c, const float2 &a, const float2 &b) {
    unsigned long long       &cc = reinterpret_cast<unsigned long long &>(c);
    const unsigned long long &aa = reinterpret_cast<const unsigned long long &>(a);
    const unsigned long long &bb = reinterpret_cast<const unsigned long long &>(b);
    asm("fma.rn.f32x2 %0, %1, %2, %0;" : "+l"(cc) : "l"(aa), "l"(bb));
}
__device__ __forceinline__ void split1(float v, __nv_bfloat16 &h, __nv_bfloat16 &l) {
    h = __float2bfloat16(v);
    l = __float2bfloat16(v - __bfloat162float(h));
}

// Fast packed hi/lo split: bit-identical to split1 per lane.
// hi = {bf16(v.y):bf16(v.x)}, etc. f32(bf16) == (bits << 16).
__device__ __forceinline__ void split4_fast(float4 v, uint2 &hi, uint2 &lo) {
    uint32_t h01, h23, l01, l23;
    asm("cvt.rn.bf16x2.f32 %0, %1, %2;" : "=r"(h01) : "f"(v.y), "f"(v.x));
    asm("cvt.rn.bf16x2.f32 %0, %1, %2;" : "=r"(h23) : "f"(v.w), "f"(v.z));
    float r0 = v.x - __uint_as_float(h01 << 16);
    float r1 = v.y - __uint_as_float(h01 & 0xFFFF0000u);
    float r2 = v.z - __uint_as_float(h23 << 16);
    float r3 = v.w - __uint_as_float(h23 & 0xFFFF0000u);
    asm("cvt.rn.bf16x2.f32 %0, %1, %2;" : "=r"(l01) : "f"(r1), "f"(r0));
    asm("cvt.rn.bf16x2.f32 %0, %1, %2;" : "=r"(l23) : "f"(r3), "f"(r2));
    hi = make_uint2(h01, h23);
    lo = make_uint2(l01, l23);
}

static constexpr uint32_t TC_IDESC = 0x8200490u; // F32 acc, BF16xBF16, M=128, N=128

__device__ __forceinline__ uint32_t sw32(int r, int ch) {  // 128x128 bf16 tile
    uint32_t byte = ((r >> 3) + (ch >> 3) * 16) * 1024 + (r & 7) * 128 + (ch & 7) * 16;
    return byte ^ ((byte >> 3) & 0x70);
}

// ---------------------------------------------------------------------------
// tc_skinny_f32 (R5 pipeline; fast convert + strength-reduced addressing)
// ---------------------------------------------------------------------------
#define SKF_SMEM (1024 + 2 * 65536)

__global__ void __launch_bounds__(128)
tc_skinny_f32(const float *__restrict__ A, int lda, int Kvalid,
              const __nv_bfloat16 *__restrict__ Bhi,
              const __nv_bfloat16 *__restrict__ Blo, int ldb,
              float *__restrict__ C, int ldc, int kpc, float alpha)
{
#if TC_ENABLED
    extern __shared__ char sm[];
    const uint32_t sb = cvta_smem(sm);
    const int tid = threadIdx.x;
    const int wid = tid >> 5;

    if (wid == 0) tc_alloc(sb, 128);
    if (tid == 64) mbar_init(sb + 8, 1);
    __syncthreads();
    uint32_t tmem;
    asm volatile("ld.shared.b32 %0, [%1];" : "=r"(tmem) : "r"(sb));

    const int m0 = blockIdx.x * 128;
    const int kb0 = blockIdx.z * kpc;
    const int S = kpc >> 6;

    // per-thread invariant offsets
    // A: g = i*128 + tid -> row = i*8 + (tid>>4), colchunk = tid&15
    const int aRow = tid >> 4;           // + i*8
    const int aCol = (tid & 15) * 4;     // + kb
    const float *aBase = A + (size_t)(m0 + aRow) * lda + aCol;
    const size_t aRowStep = (size_t)8 * lda;
    // A smem: byte = i*1024 + toffA (swizzle XOR folded: bits7-9 from (tid>>4)*128)
    const uint32_t toffA = (uint32_t)(((tid >> 4) * 128 + (tid & 15) * 8) ^ ((tid >> 4) << 4));
    // B: g = i*128 + tid -> row = i*16 + (tid>>3), colchunk = tid&7
    const int bRow = tid >> 3;           // + i*16
    const int bCol = (tid & 7) * 8;      // + kb
    const uint32_t toffB = (uint32_t)((((tid >> 3) & 7) * 128 + (tid & 7) * 16) ^
                                      ((((tid >> 3) & 7) << 4)));
    const uint32_t bAtom = (uint32_t)(tid >> 6) * 1024;  // (bRow>>3) low bit region

    float4 regs[16];

    auto ldA = [&](int s) {
        const int kb = kb0 + s * 64;
        const bool ok = (kb + aCol) < Kvalid;
        const float *p = aBase + kb;
#pragma unroll
        for (int i = 0; i < 16; ++i) {
            regs[i] = ok ? *(const float4 *)(p + i * aRowStep)
                         : make_float4(0.f, 0.f, 0.f, 0.f);
        }
    };
    auto ldB = [&](int s) {
        const uint32_t bh = sb + 1024 + (s & 1) * 65536 + 32768;
        const int kb = kb0 + s * 64;
        const __nv_bfloat16 *ph = Bhi + (size_t)bRow * ldb + kb + bCol;
        const __nv_bfloat16 *pl = Blo + (size_t)bRow * ldb + kb + bCol;
        const uint32_t so0 = bAtom + toffB;
#pragma unroll
        for (int i = 0; i < 8; ++i) {
            uint32_t so = so0 + i * 2048;
            cpa16(bh + so,         ph + (size_t)i * 16 * ldb);
            cpa16(bh + 16384 + so, pl + (size_t)i * 16 * ldb);
        }
        cpa_commit();
    };
    auto stA = [&](int s) {
        char *ah = sm + 1024 + (s & 1) * 65536;
        char *al = ah + 16384;
#pragma unroll
        for (int i = 0; i < 16; ++i) {
            uint2 h, l;
            split4_fast(regs[i], h, l);
            uint32_t sz = toffA + i * 1024;
            *(uint2 *)(ah + sz) = h;
            *(uint2 *)(al + sz) = l;
        }
    };

    ldB(0);
    ldA(0);
    uint32_t ph = 0;
    for (int s = 0; s < S; ++s) {
        cpa_wait<0>();
        stA(s);
        __syncthreads();
        fence_async_smem();
        if (wid == 0 && elect_one()) {
            const uint32_t base = sb + 1024 + (s & 1) * 65536;
            uint64_t dah = make_desc(base);
            uint64_t dal = make_desc(base + 16384);
            uint64_t dbh = make_desc(base + 32768);
            uint64_t dbl = make_desc(base + 49152);
#pragma unroll
            for (int k = 0; k < 4; ++k) {
                uint64_t off = (uint64_t)(k * 2);
                mma_f16_ss(tmem, dah + off, dbh + off, TC_IDESC, (s > 0) || (k > 0));
                mma_f16_ss(tmem, dah + off, dbl + off, TC_IDESC, 1u);
                mma_f16_ss(tmem, dal + off, dbh + off, TC_IDESC, 1u);
            }
            tc_commit(sb + 8);
        }
        if (s + 1 < S) { ldB(s + 1); ldA(s + 1); }
        mbar_wait(sb + 8, ph);
        ph ^= 1;
        __syncthreads();
    }

    tc_fence_after();
#pragma unroll
    for (int part = 0; part < 4; ++part) {
        uint32_t d[32];
        ldtm32(d, tmem + part * 32);
        tc_wait_ld();
        float *cp = C + (size_t)(m0 + tid) * ldc + part * 32;
#pragma unroll
        for (int j = 0; j < 8; ++j)
            red4(cp + j * 4,
                 __uint_as_float(d[j * 4 + 0]) * alpha,
                 __uint_as_float(d[j * 4 + 1]) * alpha,
                 __uint_as_float(d[j * 4 + 2]) * alpha,
                 __uint_as_float(d[j * 4 + 3]) * alpha);
    }
    __syncthreads();
    if (wid == 0) {
        tc_relinquish();
        tc_dealloc(tmem, 128);
    }
#endif
}

// ---------------------------------------------------------------------------
// tc_wide (R5 structure, verbatim)
// ---------------------------------------------------------------------------
#define WIDE_SMEM (1024 + 65536 + 131072)

__global__ void __launch_bounds__(128)
tc_wide(const __nv_bfloat16 *__restrict__ Ahi, const __nv_bfloat16 *__restrict__ Alo,
        const __nv_bfloat16 *__restrict__ Bhi, const __nv_bfloat16 *__restrict__ Blo,
        float *__restrict__ C, float alpha)
{
#if TC_ENABLED
    extern __shared__ char sm[];
    const uint32_t sb = cvta_smem(sm);
    const int tid = threadIdx.x;
    const int wid = tid >> 5;

    if (wid == 0) tc_alloc(sb, 512);
    if (tid == 64) mbar_init(sb + 8, 1);
    __syncthreads();
    uint32_t tmem;
    asm volatile("ld.shared.b32 %0, [%1];" : "=r"(tmem) : "r"(sb));

    const int m0 = blockIdx.x * 128;
    const int ng0 = blockIdx.y * 512;

    const uint32_t A0 = sb + 1024;
    const uint32_t A1 = A0 + 32768;

    auto load_B = [&](int n) {
        const uint32_t base = sb + 1024 + 65536 + (n & 1) * 65536;
        const int r0 = ng0 + n * 128;
#pragma unroll
        for (int i = tid; i < 2048; i += 128) {
            int r = i >> 4, ch = i & 15;
            uint32_t so = sw32(r, ch);
            cpa16(base + so,         Bhi + (size_t)(r0 + r) * HDIM + ch * 8);
            cpa16(base + 32768 + so, Blo + (size_t)(r0 + r) * HDIM + ch * 8);
        }
        cpa_commit();
    };

#pragma unroll
    for (int i = tid; i < 2048; i += 128) {
        int r = i >> 4, ch = i & 15;
        uint32_t so = sw32(r, ch);
        cpa16(A0 + so, Ahi + (size_t)(m0 + r) * HDIM + ch * 8);
        cpa16(A1 + so, Alo + (size_t)(m0 + r) * HDIM + ch * 8);
    }
    {
        const uint32_t base = sb + 1024 + 65536;
#pragma unroll
        for (int i = tid; i < 2048; i += 128) {
            int r = i >> 4, ch = i & 15;
            uint32_t so = sw32(r, ch);
            cpa16(base + so,         Bhi + (size_t)(ng0 + r) * HDIM + ch * 8);
            cpa16(base + 32768 + so, Blo + (size_t)(ng0 + r) * HDIM + ch * 8);
        }
    }
    cpa_commit();

    uint32_t ph = 0;
    for (int n = 0; n < 4; ++n) {
        if (n + 1 < 4) { load_B(n + 1); cpa_wait<1>(); }
        else           { cpa_wait<0>(); }
        __syncthreads();
        fence_async_smem();
        if (wid == 0 && elect_one()) {
            const uint32_t bbase = sb + 1024 + 65536 + (n & 1) * 65536;
            uint64_t dah = make_desc(A0);
            uint64_t dal = make_desc(A1);
            uint64_t dbh = make_desc(bbase);
            uint64_t dbl = make_desc(bbase + 32768);
            const uint32_t acc = tmem + n * 128;
#pragma unroll
            for (int k = 0; k < 8; ++k) {
                uint64_t off = (uint64_t)((k & 3) * 2 + (k >> 2) * 1024);
                mma_f16_ss(acc, dah + off, dbh + off, TC_IDESC, k > 0);
                mma_f16_ss(acc, dah + off, dbl + off, TC_IDESC, 1u);
                mma_f16_ss(acc, dal + off, dbh + off, TC_IDESC, 1u);
            }
            tc_commit(sb + 8);
        }
        mbar_wait(sb + 8, ph);
        ph ^= 1;
        __syncthreads();
    }

    tc_fence_after();
    float *st = (float *)(sm + 1024);
    for (int n = 0; n < 4; ++n) {
#pragma unroll
        for (int part = 0; part < 4; ++part) {
            uint32_t d[32];
            ldtm32(d, tmem + n * 128 + part * 32);
            tc_wait_ld();
#pragma unroll
            for (int c = 0; c < 32; ++c)
                st[tid * 33 + c] = __uint_as_float(d[c]) * alpha;
            __syncthreads();
            const int col0 = ng0 + n * 128 + part * 32;
#pragma unroll
            for (int i = 0; i < 32; ++i) {
                int idx = i * 128 + tid;
                int rr = idx >> 5, cc = idx & 31;
                C[(size_t)(m0 + rr) * NCELL + col0 + cc] = st[rr * 33 + cc];
            }
            __syncthreads();
        }
    }
    __syncthreads();
    if (wid == 0) {
        tc_relinquish();
        tc_dealloc(tmem, 512);
    }
#endif
}

// ---------------------------------------------------------------------------
// fp32 -> bf16 hi/lo split kernels
// ---------------------------------------------------------------------------
__global__ void split_cols(const float *__restrict__ src, int ldsrc, int col0,
                           int cols4, __nv_bfloat16 *__restrict__ hi,
                           __nv_bfloat16 *__restrict__ lo)
{
    int idx = blockIdx.x * blockDim.x + threadIdx.x;
    int r = idx / cols4, c = idx - r * cols4;
    float4 v = *(const float4 *)(src + (size_t)r * ldsrc + col0 + c * 4);
    uint2 h, l;
    split4_fast(v, h, l);
    *(uint2 *)(hi + (size_t)idx * 4) = h;
    *(uint2 *)(lo + (size_t)idx * 4) = l;
}

__global__ void wT_split(const float *__restrict__ W, const int *__restrict__ hid,
                         __nv_bfloat16 *__restrict__ hi, __nv_bfloat16 *__restrict__ lo)
{
    int idx = blockIdx.x * blockDim.x + threadIdx.x;   // 128*2048
    int r = idx >> 7;
    int c = idx & 127;
    const float *Wh = W + (size_t)hid[0] * NINP * HDIM;
    float v = (r < NINP) ? Wh[(size_t)r * HDIM + c] : 0.f;
    __nv_bfloat16 h, l;
    split1(v, h, l);
    size_t o = (size_t)c * KPAD + r;
    hi[o] = h;
    lo[o] = l;
}

__global__ void transpose_split(const float *__restrict__ src, int ldsrc, int col0,
                                __nv_bfloat16 *__restrict__ hi,
                                __nv_bfloat16 *__restrict__ lo)
{
    __shared__ float t[32][33];
    int r0 = blockIdx.x * 32, c0 = blockIdx.y * 32;
    int tx = threadIdx.x, ty = threadIdx.y;  // 32 x 8
#pragma unroll
    for (int i = 0; i < 4; ++i) {
        int r = ty + i * 8;
        t[r][tx] = src[(size_t)(r0 + r) * ldsrc + col0 + c0 + tx];
    }
    __syncthreads();
#pragma unroll
    for (int i = 0; i < 4; ++i) {
        int c = ty + i * 8;
        float v = t[tx][c];
        __nv_bfloat16 h, l;
        split1(v, h, l);
        size_t o = (size_t)(c0 + c) * NCELL + r0 + tx;
        hi[o] = h;
        lo[o] = l;
    }
}

// ---------------------------------------------------------------------------
// gemm_small: C[M,N] = bnrelu(A)[M,128] @ B[128,N] (+bias), direct store.
// BNA: scale/shift computed IN-KERNEL from raw stats (sum/sumsq) + g/be.
// STATS: accumulate per-column sum/sumsq of C into statsOut (raw).
// ---------------------------------------------------------------------------
template <bool BNA, bool STATS>
__global__ void __launch_bounds__(256)
gemm_small(const float *__restrict__ A, const float *__restrict__ B,
           float *__restrict__ C, int ldb, int ldc,
           const float *__restrict__ bias,
           const float *__restrict__ statsIn,
           const float *__restrict__ g, const float *__restrict__ be,
           const int *__restrict__ hid, int hstride,
           float *__restrict__ statsOut)
{
    __shared__ float As[BK][BM + 4];
    __shared__ float Bs[BK][BN + 4];
    __shared__ float bnSs[128], bnBs[128];

    const int tid = threadIdx.x;
    const int tx = tid & 15;
    const int ty = tid >> 4;
    const int m0 = blockIdx.x * BM;
    const int n0 = blockIdx.y * BN;

    if (BNA && tid < 128) {
        float s1 = statsIn[tid], s2 = statsIn[128 + tid];
        float mean = s1 * (1.f / (float)NCELL);
        float var = s2 * (1.f / (float)NCELL) - mean * mean;
        float rstd = rsqrtf(var + BN_EPS);
        int off = hid ? hid[0] * hstride : 0;
        float gg = g[off + tid];
        bnSs[tid] = gg * rstd;
        bnBs[tid] = be[off + tid] - gg * mean * rstd;
    }

    const int f0 = tid, f1 = tid + 256;
    const int aRow0 = f0 >> 2, aK0 = (f0 & 3) * 4;
    const int aRow1 = f1 >> 2, aK1 = (f1 & 3) * 4;
    const int bK0 = f0 >> 5, bN0 = (f0 & 31) * 4;
    const int bK1 = f1 >> 5, bN1 = (f1 & 31) * 4;

    const float *Ap0 = A + (size_t)(m0 + aRow0) * HDIM + aK0;
    const float *Ap1 = A + (size_t)(m0 + aRow1) * HDIM + aK1;
    const float *Bp0 = B + (size_t)bK0 * ldb + n0 + bN0;
    const float *Bp1 = B + (size_t)bK1 * ldb + n0 + bN1;

    float2 acc[8][4];
#pragma unroll
    for (int i = 0; i < 8; ++i)
#pragma unroll
        for (int j = 0; j < 4; ++j) acc[i][j] = make_float2(0.f, 0.f);

    float4 ra0 = *(const float4 *)Ap0;
    float4 ra1 = *(const float4 *)Ap1;
    float4 rb0 = *(const float4 *)Bp0;
    float4 rb1 = *(const float4 *)Bp1;

    const int chunks = HDIM / BK;   // 8
    for (int c = 0; c < chunks; ++c) {
        __syncthreads();
        const int cK = c * BK;
        if (BNA) {
            As[aK0 + 0][aRow0] = fmaxf(fmaf(ra0.x, bnSs[cK + aK0 + 0], bnBs[cK + aK0 + 0]), 0.f);
            As[aK0 + 1][aRow0] = fmaxf(fmaf(ra0.y, bnSs[cK + aK0 + 1], bnBs[cK + aK0 + 1]), 0.f);
            As[aK0 + 2][aRow0] = fmaxf(fmaf(ra0.z, bnSs[cK + aK0 + 2], bnBs[cK + aK0 + 2]), 0.f);
            As[aK0 + 3][aRow0] = fmaxf(fmaf(ra0.w, bnSs[cK + aK0 + 3], bnBs[cK + aK0 + 3]), 0.f);
            As[aK1 + 0][aRow1] = fmaxf(fmaf(ra1.x, bnSs[cK + aK1 + 0], bnBs[cK + aK1 + 0]), 0.f);
            As[aK1 + 1][aRow1] = fmaxf(fmaf(ra1.y, bnSs[cK + aK1 + 1], bnBs[cK + aK1 + 1]), 0.f);
            As[aK1 + 2][aRow1] = fmaxf(fmaf(ra1.z, bnSs[cK + aK1 + 2], bnBs[cK + aK1 + 2]), 0.f);
            As[aK1 + 3][aRow1] = fmaxf(fmaf(ra1.w, bnSs[cK + aK1 + 3], bnBs[cK + aK1 + 3]), 0.f);
        } else {
            As[aK0 + 0][aRow0] = ra0.x; As[aK0 + 1][aRow0] = ra0.y;
            As[aK0 + 2][aRow0] = ra0.z; As[aK0 + 3][aRow0] = ra0.w;
            As[aK1 + 0][aRow1] = ra1.x; As[aK1 + 1][aRow1] = ra1.y;
            As[aK1 + 2][aRow1] = ra1.z; As[aK1 + 3][aRow1] = ra1.w;
        }
        *(float4 *)&Bs[bK0][bN0] = rb0;
        *(float4 *)&Bs[bK1][bN1] = rb1;
        __syncthreads();

        if (c + 1 < chunks) {
            Ap0 += BK; Ap1 += BK;
            ra0 = *(const float4 *)Ap0;
            ra1 = *(const float4 *)Ap1;
            Bp0 += (size_t)BK * ldb; Bp1 += (size_t)BK * ldb;
            rb0 = *(const float4 *)Bp0;
            rb1 = *(const float4 *)Bp1;
        }

#pragma unroll
        for (int kk = 0; kk < BK; ++kk) {
            float4 a0 = *(const float4 *)&As[kk][ty * 4];
            float4 a1 = *(const float4 *)&As[kk][64 + ty * 4];
            float4 b0 = *(const float4 *)&Bs[kk][tx * 4];
            float4 b1 = *(const float4 *)&Bs[kk][64 + tx * 4];
            float av[8] = {a0.x, a0.y, a0.z, a0.w, a1.x, a1.y, a1.z, a1.w};
            float2 bp[4] = {make_float2(b0.x, b0.y), make_float2(b0.z, b0.w),
                            make_float2(b1.x, b1.y), make_float2(b1.z, b1.w)};
#pragma unroll
            for (int i = 0; i < 8; ++i) {
                float2 aa = make_float2(av[i], av[i]);
#pragma unroll
                for (int j = 0; j < 4; ++j) fma2(acc[i][j], aa, bp[j]);
            }
        }
    }

    float bad0[4] = {0.f, 0.f, 0.f, 0.f}, bad1[4] = {0.f, 0.f, 0.f, 0.f};
    if (bias != nullptr) {
#pragma unroll
        for (int j = 0; j < 4; ++j) {
            bad0[j] = bias[n0 + tx * 4 + j];
            bad1[j] = bias[n0 + 64 + tx * 4 + j];
        }
    }

    float cs[8], cq[8];
#pragma unroll
    for (int j = 0; j < 8; ++j) { cs[j] = 0.f; cq[j] = 0.f; }

#pragma unroll
    for (int i = 0; i < 8; ++i) {
        int r = m0 + ((i < 4) ? (ty * 4 + i) : (64 + ty * 4 + (i - 4)));
        float v[8] = {acc[i][0].x, acc[i][0].y, acc[i][1].x, acc[i][1].y,
                      acc[i][2].x, acc[i][2].y, acc[i][3].x, acc[i][3].y};
        float w[8];
#pragma unroll
        for (int j = 0; j < 4; ++j) { w[j] = v[j] + bad0[j]; w[4 + j] = v[4 + j] + bad1[j]; }
        if (STATS) {
#pragma unroll
            for (int j = 0; j < 8; ++j) { cs[j] += w[j]; cq[j] += w[j] * w[j]; }
        }
        float *crow = C + (size_t)r * ldc;
        *(float4 *)(crow + n0 + tx * 4)      = make_float4(w[0], w[1], w[2], w[3]);
        *(float4 *)(crow + n0 + 64 + tx * 4) = make_float4(w[4], w[5], w[6], w[7]);
    }

    if (STATS) {
        __syncthreads();
        float *sred = (float *)As;     // 256 floats: sum[128], sumsq[128]
        if (tid < 128) { sred[tid] = 0.f; sred[128 + tid] = 0.f; }
        __syncthreads();
#pragma unroll
        for (int j = 0; j < 8; ++j) {
            int col = (j < 4) ? (tx * 4 + j) : (64 + tx * 4 + (j - 4));
            atomicAdd(&sred[col], cs[j]);
            atomicAdd(&sred[128 + col], cq[j]);
        }
        __syncthreads();
        if (tid < 128) {
            atomicAdd(statsOut + tid, sred[tid]);
            atomicAdd(statsOut + 128 + tid, sred[128 + tid]);
        }
    }
}

// ---------------------------------------------------------------------------
// BatchNorm stats (enc output only)
// ---------------------------------------------------------------------------
__global__ void bn_stats(const float *__restrict__ h, float *__restrict__ stats)
{
    int col = threadIdx.x;
    int r0 = blockIdx.x * 32;
    float s = 0.f, s2 = 0.f;
#pragma unroll 8
    for (int r = 0; r < 32; ++r) {
        float v = h[(size_t)(r0 + r) * HDIM + col];
        s += v; s2 += v * v;
    }
    atomicAdd(&stats[col], s);
    atomicAdd(&stats[128 + col], s2);
}

// ---------------------------------------------------------------------------
// Row softmax in place
// ---------------------------------------------------------------------------
__global__ void softmax_row(float *__restrict__ attn)
{
    extern __shared__ float row[];
    __shared__ float red[256];
    const int t = threadIdx.x;
    float *p = attn + (size_t)blockIdx.x * NCELL;

    float m = -1e30f;
    for (int i = t; i < NCELL / 4; i += 256) {
        float4 v = ((const float4 *)p)[i];
        ((float4 *)row)[i] = v;
        m = fmaxf(m, fmaxf(fmaxf(v.x, v.y), fmaxf(v.z, v.w)));
    }
    red[t] = m; __syncthreads();
    for (int s = 128; s > 0; s >>= 1) {
        if (t < s) red[t] = fmaxf(red[t], red[t + s]);
        __syncthreads();
    }
    const float bmax = red[0];
    __syncthreads();

    float sum = 0.f;
    for (int i = t; i < NCELL / 4; i += 256) {
        float4 v = ((float4 *)row)[i];
        v.x = __expf(v.x - bmax); v.y = __expf(v.y - bmax);
        v.z = __expf(v.z - bmax); v.w = __expf(v.w - bmax);
        sum += v.x + v.y + v.z + v.w;
        ((float4 *)row)[i] = v;
    }
    red[t] = sum; __syncthreads();
    for (int s = 128; s > 0; s >>= 1) {
        if (t < s) red[t] += red[t + s];
        __syncthreads();
    }
    const float inv = 1.f / red[0];
    __syncthreads();

    for (int i = t; i < NCELL / 4; i += 256) {
        float4 v = ((float4 *)row)[i];
        v.x *= inv; v.y *= inv; v.z *= inv; v.w *= inv;
        ((float4 *)p)[i] = v;
    }
}

// ---------------------------------------------------------------------------
// Variational heads
// ---------------------------------------------------------------------------
__global__ void heads_kernel(const float *__restrict__ o,
                             const float *__restrict__ mW, const float *__restrict__ mb,
                             const float *__restrict__ vW, const float *__restrict__ vb,
                             const float *__restrict__ eps,
                             float *__restrict__ qm, float *__restrict__ qv,
                             float *__restrict__ lat)
{
    extern __shared__ float smh[];
    float *Wm  = smh;
    float *Wv  = smh + 4096;
    float *osm = smh + 8192;
    const int t = threadIdx.x;
    const int r0 = blockIdx.x * 128;

    for (int i = t; i < HDIM * NOUTD; i += 256) { Wm[i] = mW[i]; Wv[i] = vW[i]; }
    for (int i = t; i < 128 * HDIM; i += 256) {
        int r = i >> 7, c = i & 127;
        osm[r * 129 + c] = o[(size_t)(r0 + r) * HDIM + c];
    }
    __syncthreads();

    for (int idx = t; idx < 128 * NOUTD; idx += 256) {
        int r = idx >> 5, c = idx & 31;
        const float *orow = &osm[r * 129];
        float dm = 0.f, dv = 0.f;
#pragma unroll 8
        for (int k = 0; k < HDIM; ++k) {
            float ov = orow[k];
            dm += ov * Wm[k * NOUTD + c];
            dv += ov * Wv[k * NOUTD + c];
        }
        int R = r0 + r;
        float mval = dm + mb[c];
        float vval = __expf(dv + vb[c]);
        qm[R * NOUTD + c]  = mval;
        qv[R * NOUTD + c]  = vval;
        lat[R * NOUTD + c] = mval + sqrtf(vval) * eps[R * NOUTD + c];
    }
}

// ---------------------------------------------------------------------------
// Launch
// ---------------------------------------------------------------------------
extern "C" void kernel_launch(void *const *d_in, const int *in_sizes, int n_in,
                              void *d_out, int out_size)
{
    const float *x       = (const float *)d_in[0];
    const float *spatial = (const float *)d_in[1];
    const float *eps     = (const float *)d_in[2];
    const float *enc_W   = (const float *)d_in[3];
    const float *enc_g   = (const float *)d_in[5];
    const float *enc_be  = (const float *)d_in[6];
    const float *sh_W1   = (const float *)d_in[7];
    const float *sh_g1   = (const float *)d_in[9];
    const float *sh_be1  = (const float *)d_in[10];
    const float *sh_W2   = (const float *)d_in[11];
    const float *sh_g2   = (const float *)d_in[13];
    const float *sh_be2  = (const float *)d_in[14];
    const float *qkv_W   = (const float *)d_in[15];
    const float *qkv_b   = (const float *)d_in[16];
    const float *o_W     = (const float *)d_in[17];
    const float *o_b     = (const float *)d_in[18];
    const float *mean_W  = (const float *)d_in[19];
    const float *mean_b  = (const float *)d_in[20];
    const float *var_W   = (const float *)d_in[21];
    const float *var_b   = (const float *)d_in[22];
    const int   *hid     = (const int *)d_in[23];

    float *out = (float *)d_out;
    float *out_qm   = out;
    float *out_qv   = out + (size_t)NCELL * NOUTD;
    float *out_lat  = out + 2 * (size_t)NCELL * NOUTD;
    float *out_attn = out + 3 * (size_t)NCELL * NOUTD;

    float *bufA, *bufB, *qkv, *kagg, *stats;
    __nv_bfloat16 *q_hi, *q_lo, *ka_hi, *ka_lo;
    __nv_bfloat16 *kT_hi, *kT_lo, *vT_hi, *vT_lo, *wT_hi, *wT_lo;
    cudaGetSymbolAddress((void **)&bufA, g_bufA);
    cudaGetSymbolAddress((void **)&bufB, g_bufB);
    cudaGetSymbolAddress((void **)&qkv,  g_qkv);
    cudaGetSymbolAddress((void **)&kagg, g_kagg);
    cudaGetSymbolAddress((void **)&stats, g_stats);
    cudaGetSymbolAddress((void **)&q_hi, g_q_hi);
    cudaGetSymbolAddress((void **)&q_lo, g_q_lo);
    cudaGetSymbolAddress((void **)&ka_hi, g_ka_hi);
    cudaGetSymbolAddress((void **)&ka_lo, g_ka_lo);
    cudaGetSymbolAddress((void **)&kT_hi, g_kT_hi);
    cudaGetSymbolAddress((void **)&kT_lo, g_kT_lo);
    cudaGetSymbolAddress((void **)&vT_hi, g_vT_hi);
    cudaGetSymbolAddress((void **)&vT_lo, g_vT_lo);
    cudaGetSymbolAddress((void **)&wT_hi, g_wT_hi);
    cudaGetSymbolAddress((void **)&wT_lo, g_wT_lo);

    cudaFuncSetAttribute(tc_skinny_f32, cudaFuncAttributeMaxDynamicSharedMemorySize, SKF_SMEM);
    cudaFuncSetAttribute(tc_wide,       cudaFuncAttributeMaxDynamicSharedMemorySize, WIDE_SMEM);

    const size_t NH_BYTES = (size_t)NCELL * HDIM * sizeof(float);
    const float SCALE = 0.08838834764831845f; // 1/sqrt(128)
    float *slot0 = stats, *slot1 = stats + 256, *slot2 = stats + 512;

    // zero all BN stats slots once
    cudaMemsetAsync(stats, 0, 768 * sizeof(float));

    // 1. encoder: h = x @ enc_W[hid]
    wT_split<<<1024, 256>>>(enc_W, hid, wT_hi, wT_lo);
    cudaMemsetAsync(bufA, 0, NH_BYTES);
    tc_skinny_f32<<<dim3(64, 1, 4), 128, SKF_SMEM>>>(
        x, NINP, NINP, wT_hi, wT_lo, KPAD, bufA, HDIM, 512, 1.f);
    bn_stats<<<256, 128>>>(bufA, slot0);

    // 2. sh1 = BN1(bufA) @ W1 ; stats of sh1 -> slot1
    gemm_small<true, true><<<dim3(64, 1), 256>>>(
        bufA, sh_W1, bufB, HDIM, HDIM, nullptr,
        slot0, enc_g, enc_be, hid, HDIM, slot1);

    // 3. sh2 = BN2(bufB) @ W2 ; stats of sh2 -> slot2
    gemm_small<true, true><<<dim3(64, 1), 256>>>(
        bufB, sh_W2, bufA, HDIM, HDIM, nullptr,
        slot1, sh_g1, sh_be1, nullptr, 0, slot2);

    // 4. qkv = BN3(bufA) @ qkv_W + qkv_b
    gemm_small<true, false><<<dim3(64, 3), 256>>>(
        bufA, qkv_W, qkv, 3 * HDIM, 3 * HDIM, qkv_b,
        slot2, sh_g2, sh_be2, nullptr, 0, nullptr);

    // 5. small bf16 conversions (q, kT, vT)
    split_cols<<<1024, 256>>>(qkv, 3 * HDIM, 0, HDIM / 4, q_hi, q_lo);
    transpose_split<<<dim3(256, 4), dim3(32, 8)>>>(qkv, 3 * HDIM, HDIM, kT_hi, kT_lo);
    transpose_split<<<dim3(256, 4), dim3(32, 8)>>>(qkv, 3 * HDIM, 2 * HDIM, vT_hi, vT_lo);

    // 6. k_agg = spatial @ k   (split-K = 4)
    cudaMemsetAsync(kagg, 0, NH_BYTES);
    tc_skinny_f32<<<dim3(64, 1, 4), 128, SKF_SMEM>>>(
        spatial, NCELL, NCELL, kT_hi, kT_lo, NCELL, kagg, HDIM, 2048, 1.f);
    split_cols<<<1024, 256>>>(kagg, HDIM, 0, HDIM / 4, ka_hi, ka_lo);

    // 7. logits = (q @ k_agg^T) / sqrt(H)
    tc_wide<<<dim3(64, 16), 128, WIDE_SMEM>>>(q_hi, q_lo, ka_hi, ka_lo, out_attn, SCALE);

    // 8. softmax in place
    softmax_row<<<NCELL, 256, NCELL * sizeof(float)>>>(out_attn);

    // 9. av = attn @ v   (split-K = 4)
    cudaMemsetAsync(bufA, 0, NH_BYTES);
    tc_skinny_f32<<<dim3(64, 1, 4), 128, SKF_SMEM>>>(
        out_attn, NCELL, NCELL, vT_hi, vT_lo, NCELL, bufA, HDIM, 2048, 1.f);

    // 10. o = av @ o_W + o_b
    gemm_small<false, false><<<dim3(64, 1), 256>>>(
        bufA, o_W, bufB, HDIM, HDIM, o_b,
        nullptr, nullptr, nullptr, nullptr, 0, nullptr);

    // 11. variational heads
    const int heads_smem = (4096 + 4096 + 128 * 129) * sizeof(float);
    cudaFuncSetAttribute(heads_kernel, cudaFuncAttributeMaxDynamicSharedMemorySize,
                         heads_smem);
    heads_kernel<<<64, 256, heads_smem>>>(bufB, mean_W, mean_b, var_W, var_b,
                                          eps, out_qm, out_qv, out_lat);
}

// round 9
// speedup vs baseline: 1.3406x; 1.0242x over previous
#include <cuda_runtime.h>
#include <cuda_bf16.h>
#include <math.h>
#include <stdint.h>

#define NCELL 8192
#define NINP  2000
#define KPAD  2048
#define HDIM  128
#define NOUTD 32
#define BN_EPS 1e-3f

#define BK 16

#if defined(__CUDA_ARCH_FEAT_SM103_ALL) || defined(__CUDA_ARCH_FEAT_SM100_ALL) || \
    defined(__CUDA_ARCH_FEAT_SM110_ALL) || defined(__CUDA_ARCH_FEAT_SM101_ALL)
#define TC_ENABLED 1
#else
#define TC_ENABLED 0
#endif

// ---------------------------------------------------------------------------
// Scratch
// ---------------------------------------------------------------------------
__device__ __align__(256) float g_bufA[NCELL * HDIM];
__device__ __align__(256) float g_bufB[NCELL * HDIM];
__device__ __align__(256) float g_qkv [NCELL * 3 * HDIM];
__device__ __align__(256) float g_kagg[NCELL * HDIM];
__device__ __align__(256) float g_stats[768];   // 3 BN slots x (sum[128], sumsq[128])

__device__ __align__(256) __nv_bfloat16 g_q_hi [NCELL * HDIM];
__device__ __align__(256) __nv_bfloat16 g_q_lo [NCELL * HDIM];
__device__ __align__(256) __nv_bfloat16 g_ka_hi[NCELL * HDIM];
__device__ __align__(256) __nv_bfloat16 g_ka_lo[NCELL * HDIM];
__device__ __align__(256) __nv_bfloat16 g_kT_hi[HDIM * NCELL];
__device__ __align__(256) __nv_bfloat16 g_kT_lo[HDIM * NCELL];
__device__ __align__(256) __nv_bfloat16 g_vT_hi[HDIM * NCELL];
__device__ __align__(256) __nv_bfloat16 g_vT_lo[HDIM * NCELL];
__device__ __align__(256) __nv_bfloat16 g_wT_hi[HDIM * KPAD];
__device__ __align__(256) __nv_bfloat16 g_wT_lo[HDIM * KPAD];

// ---------------------------------------------------------------------------
// PTX helpers
// ---------------------------------------------------------------------------
__device__ __forceinline__ uint32_t cvta_smem(const void *p) {
    uint32_t a;
    asm("{ .reg .u64 t; cvta.to.shared.u64 t, %1; cvt.u32.u64 %0, t; }"
        : "=r"(a) : "l"(p));
    return a;
}
__device__ __forceinline__ uint32_t elect_one() {
    uint32_t p;
    asm volatile("{ .reg .pred p; elect.sync _|p, 0xFFFFFFFF; selp.b32 %0, 1, 0, p; }"
                 : "=r"(p));
    return p;
}
__device__ __forceinline__ void mbar_init(uint32_t mbar, uint32_t cnt) {
    asm volatile("mbarrier.init.shared.b64 [%0], %1;"
                 :: "r"(mbar), "r"(cnt) : "memory");
}
__device__ __forceinline__ void mbar_wait(uint32_t mbar, uint32_t parity) {
    asm volatile(
        "{\n\t.reg .pred P;\n"
        "LW_%=:\n\t"
        "mbarrier.try_wait.parity.acquire.cta.shared::cta.b64 P, [%0], %1, 0x989680;\n\t"
        "@P bra LD_%=;\n\t"
        "bra LW_%=;\n"
        "LD_%=:\n\t}"
        :: "r"(mbar), "r"(parity) : "memory");
}
__device__ __forceinline__ void fence_async_smem() {
    asm volatile("fence.proxy.async.shared::cta;" ::: "memory");
}
__device__ __forceinline__ void cpa16(uint32_t dst, const void *src) {
    asm volatile("cp.async.cg.shared.global [%0], [%1], 16;"
                 :: "r"(dst), "l"(src) : "memory");
}
__device__ __forceinline__ void cpa_commit() {
    asm volatile("cp.async.commit_group;" ::: "memory");
}
template <int N>
__device__ __forceinline__ void cpa_wait() {
    asm volatile("cp.async.wait_group %0;" :: "n"(N) : "memory");
}
__device__ __forceinline__ void red4(float *p, float a, float b, float c, float d) {
    asm volatile("red.global.add.v4.f32 [%0], {%1, %2, %3, %4};"
                 :: "l"(p), "f"(a), "f"(b), "f"(c), "f"(d) : "memory");
}

// ---- tcgen05 ----
__device__ __forceinline__ void tc_alloc(uint32_t smem_dst, uint32_t ncols) {
    asm volatile("tcgen05.alloc.cta_group::1.sync.aligned.shared::cta.b32 [%0], %1;"
                 :: "r"(smem_dst), "r"(ncols) : "memory");
}
__device__ __forceinline__ void tc_dealloc(uint32_t tmem, uint32_t ncols) {
    asm volatile("tcgen05.dealloc.cta_group::1.sync.aligned.b32 %0, %1;"
                 :: "r"(tmem), "r"(ncols));
}
__device__ __forceinline__ void tc_relinquish() {
    asm volatile("tcgen05.relinquish_alloc_permit.cta_group::1.sync.aligned;");
}
__device__ __forceinline__ void tc_commit(uint32_t mbar) {
    asm volatile("tcgen05.commit.cta_group::1.mbarrier::arrive::one.shared::cluster.b64 [%0];"
                 :: "r"(mbar) : "memory");
}
__device__ __forceinline__ void tc_fence_after() {
    asm volatile("tcgen05.fence::after_thread_sync;" ::: "memory");
}
__device__ __forceinline__ void tc_wait_ld() {
    asm volatile("tcgen05.wait::ld.sync.aligned;" ::: "memory");
}
__device__ __forceinline__ void ldtm32(uint32_t *r, uint32_t addr) {
    asm volatile(
        "tcgen05.ld.sync.aligned.32x32b.x32.b32 "
        "{%0, %1, %2, %3, %4, %5, %6, %7, "
        " %8, %9, %10, %11, %12, %13, %14, %15, "
        " %16, %17, %18, %19, %20, %21, %22, %23, "
        " %24, %25, %26, %27, %28, %29, %30, %31}, [%32];"
        : "=r"(r[0]),  "=r"(r[1]),  "=r"(r[2]),  "=r"(r[3]),
          "=r"(r[4]),  "=r"(r[5]),  "=r"(r[6]),  "=r"(r[7]),
          "=r"(r[8]),  "=r"(r[9]),  "=r"(r[10]), "=r"(r[11]),
          "=r"(r[12]), "=r"(r[13]), "=r"(r[14]), "=r"(r[15]),
          "=r"(r[16]), "=r"(r[17]), "=r"(r[18]), "=r"(r[19]),
          "=r"(r[20]), "=r"(r[21]), "=r"(r[22]), "=r"(r[23]),
          "=r"(r[24]), "=r"(r[25]), "=r"(r[26]), "=r"(r[27]),
          "=r"(r[28]), "=r"(r[29]), "=r"(r[30]), "=r"(r[31])
        : "r"(addr));
}
__device__ __forceinline__ void mma_f16_ss(uint32_t d, uint64_t a_desc,
                                           uint64_t b_desc, uint32_t idesc,
                                           uint32_t en) {
    asm volatile(
        "{\n\t.reg .pred p;\n\t"
        "setp.ne.u32 p, %5, 0;\n\t"
        "tcgen05.mma.cta_group::1.kind::f16 [%0], %1, %2, %3, {%4, %4, %4, %4}, p;\n\t}"
        :: "r"(d), "l"(a_desc), "l"(b_desc), "r"(idesc), "r"(0u), "r"(en)
        : "memory");
}
__device__ __forceinline__ uint64_t make_desc(uint32_t addr) {
    return ((uint64_t)2 << 61) | ((uint64_t)1 << 46) | ((uint64_t)64 << 32) |
           ((uint64_t)1 << 16) | (((uint64_t)(addr >> 4)) & 0x3FFF);
}
__device__ __forceinline__ void fma2(float2 &c, const float2 &a, const float2 &b) {
    unsigned long long       &cc = reinterpret_cast<unsigned long long &>(c);
    const unsigned long long &aa = reinterpret_cast<const unsigned long long &>(a);
    const unsigned long long &bb = reinterpret_cast<const unsigned long long &>(b);
    asm("fma.rn.f32x2 %0, %1, %2, %0;" : "+l"(cc) : "l"(aa), "l"(bb));
}
__device__ __forceinline__ void split1(float v, __nv_bfloat16 &h, __nv_bfloat16 &l) {
    h = __float2bfloat16(v);
    l = __float2bfloat16(v - __bfloat162float(h));
}

// Fast packed hi/lo split (bit-identical to split1 per lane)
__device__ __forceinline__ void split4_fast(float4 v, uint2 &hi, uint2 &lo) {
    uint32_t h01, h23, l01, l23;
    asm("cvt.rn.bf16x2.f32 %0, %1, %2;" : "=r"(h01) : "f"(v.y), "f"(v.x));
    asm("cvt.rn.bf16x2.f32 %0, %1, %2;" : "=r"(h23) : "f"(v.w), "f"(v.z));
    float r0 = v.x - __uint_as_float(h01 << 16);
    float r1 = v.y - __uint_as_float(h01 & 0xFFFF0000u);
    float r2 = v.z - __uint_as_float(h23 << 16);
    float r3 = v.w - __uint_as_float(h23 & 0xFFFF0000u);
    asm("cvt.rn.bf16x2.f32 %0, %1, %2;" : "=r"(l01) : "f"(r1), "f"(r0));
    asm("cvt.rn.bf16x2.f32 %0, %1, %2;" : "=r"(l23) : "f"(r3), "f"(r2));
    hi = make_uint2(h01, h23);
    lo = make_uint2(l01, l23);
}

static constexpr uint32_t TC_IDESC = 0x8200490u; // F32 acc, BF16xBF16, M=128, N=128

__device__ __forceinline__ uint32_t sw32(int r, int ch) {  // 128x128 bf16 tile
    uint32_t byte = ((r >> 3) + (ch >> 3) * 16) * 1024 + (r & 7) * 128 + (ch & 7) * 16;
    return byte ^ ((byte >> 3) & 0x70);
}

// ---------------------------------------------------------------------------
// tc_skinny_f32 (R5 pipeline; fast convert + strength-reduced addressing)
// ---------------------------------------------------------------------------
#define SKF_SMEM (1024 + 2 * 65536)

__global__ void __launch_bounds__(128)
tc_skinny_f32(const float *__restrict__ A, int lda, int Kvalid,
              const __nv_bfloat16 *__restrict__ Bhi,
              const __nv_bfloat16 *__restrict__ Blo, int ldb,
              float *__restrict__ C, int ldc, int kpc, float alpha)
{
#if TC_ENABLED
    extern __shared__ char sm[];
    const uint32_t sb = cvta_smem(sm);
    const int tid = threadIdx.x;
    const int wid = tid >> 5;

    if (wid == 0) tc_alloc(sb, 128);
    if (tid == 64) mbar_init(sb + 8, 1);
    __syncthreads();
    uint32_t tmem;
    asm volatile("ld.shared.b32 %0, [%1];" : "=r"(tmem) : "r"(sb));

    const int m0 = blockIdx.x * 128;
    const int kb0 = blockIdx.z * kpc;
    const int S = kpc >> 6;

    const int aRow = tid >> 4;
    const int aCol = (tid & 15) * 4;
    const float *aBase = A + (size_t)(m0 + aRow) * lda + aCol;
    const size_t aRowStep = (size_t)8 * lda;
    const uint32_t toffA = (uint32_t)(((tid >> 4) * 128 + (tid & 15) * 8) ^ ((tid >> 4) << 4));
    const int bRow = tid >> 3;
    const int bCol = (tid & 7) * 8;
    const uint32_t toffB = (uint32_t)((((tid >> 3) & 7) * 128 + (tid & 7) * 16) ^
                                      ((((tid >> 3) & 7) << 4)));
    const uint32_t bAtom = (uint32_t)(tid >> 6) * 1024;

    float4 regs[16];

    auto ldA = [&](int s) {
        const int kb = kb0 + s * 64;
        const bool ok = (kb + aCol) < Kvalid;
        const float *p = aBase + kb;
#pragma unroll
        for (int i = 0; i < 16; ++i) {
            regs[i] = ok ? *(const float4 *)(p + i * aRowStep)
                         : make_float4(0.f, 0.f, 0.f, 0.f);
        }
    };
    auto ldB = [&](int s) {
        const uint32_t bh = sb + 1024 + (s & 1) * 65536 + 32768;
        const int kb = kb0 + s * 64;
        const __nv_bfloat16 *ph = Bhi + (size_t)bRow * ldb + kb + bCol;
        const __nv_bfloat16 *pl = Blo + (size_t)bRow * ldb + kb + bCol;
        const uint32_t so0 = bAtom + toffB;
#pragma unroll
        for (int i = 0; i < 8; ++i) {
            uint32_t so = so0 + i * 2048;
            cpa16(bh + so,         ph + (size_t)i * 16 * ldb);
            cpa16(bh + 16384 + so, pl + (size_t)i * 16 * ldb);
        }
        cpa_commit();
    };
    auto stA = [&](int s) {
        char *ah = sm + 1024 + (s & 1) * 65536;
        char *al = ah + 16384;
#pragma unroll
        for (int i = 0; i < 16; ++i) {
            uint2 h, l;
            split4_fast(regs[i], h, l);
            uint32_t sz = toffA + i * 1024;
            *(uint2 *)(ah + sz) = h;
            *(uint2 *)(al + sz) = l;
        }
    };

    ldB(0);
    ldA(0);
    uint32_t ph = 0;
    for (int s = 0; s < S; ++s) {
        cpa_wait<0>();
        stA(s);
        __syncthreads();
        fence_async_smem();
        if (wid == 0 && elect_one()) {
            const uint32_t base = sb + 1024 + (s & 1) * 65536;
            uint64_t dah = make_desc(base);
            uint64_t dal = make_desc(base + 16384);
            uint64_t dbh = make_desc(base + 32768);
            uint64_t dbl = make_desc(base + 49152);
#pragma unroll
            for (int k = 0; k < 4; ++k) {
                uint64_t off = (uint64_t)(k * 2);
                mma_f16_ss(tmem, dah + off, dbh + off, TC_IDESC, (s > 0) || (k > 0));
                mma_f16_ss(tmem, dah + off, dbl + off, TC_IDESC, 1u);
                mma_f16_ss(tmem, dal + off, dbh + off, TC_IDESC, 1u);
            }
            tc_commit(sb + 8);
        }
        if (s + 1 < S) { ldB(s + 1); ldA(s + 1); }
        mbar_wait(sb + 8, ph);
        ph ^= 1;
        __syncthreads();
    }

    tc_fence_after();
#pragma unroll
    for (int part = 0; part < 4; ++part) {
        uint32_t d[32];
        ldtm32(d, tmem + part * 32);
        tc_wait_ld();
        float *cp = C + (size_t)(m0 + tid) * ldc + part * 32;
#pragma unroll
        for (int j = 0; j < 8; ++j)
            red4(cp + j * 4,
                 __uint_as_float(d[j * 4 + 0]) * alpha,
                 __uint_as_float(d[j * 4 + 1]) * alpha,
                 __uint_as_float(d[j * 4 + 2]) * alpha,
                 __uint_as_float(d[j * 4 + 3]) * alpha);
    }
    __syncthreads();
    if (wid == 0) {
        tc_relinquish();
        tc_dealloc(tmem, 128);
    }
#endif
}

// ---------------------------------------------------------------------------
// tc_wide (R5 structure, verbatim)
// ---------------------------------------------------------------------------
#define WIDE_SMEM (1024 + 65536 + 131072)

__global__ void __launch_bounds__(128)
tc_wide(const __nv_bfloat16 *__restrict__ Ahi, const __nv_bfloat16 *__restrict__ Alo,
        const __nv_bfloat16 *__restrict__ Bhi, const __nv_bfloat16 *__restrict__ Blo,
        float *__restrict__ C, float alpha)
{
#if TC_ENABLED
    extern __shared__ char sm[];
    const uint32_t sb = cvta_smem(sm);
    const int tid = threadIdx.x;
    const int wid = tid >> 5;

    if (wid == 0) tc_alloc(sb, 512);
    if (tid == 64) mbar_init(sb + 8, 1);
    __syncthreads();
    uint32_t tmem;
    asm volatile("ld.shared.b32 %0, [%1];" : "=r"(tmem) : "r"(sb));

    const int m0 = blockIdx.x * 128;
    const int ng0 = blockIdx.y * 512;

    const uint32_t A0 = sb + 1024;
    const uint32_t A1 = A0 + 32768;

    auto load_B = [&](int n) {
        const uint32_t base = sb + 1024 + 65536 + (n & 1) * 65536;
        const int r0 = ng0 + n * 128;
#pragma unroll
        for (int i = tid; i < 2048; i += 128) {
            int r = i >> 4, ch = i & 15;
            uint32_t so = sw32(r, ch);
            cpa16(base + so,         Bhi + (size_t)(r0 + r) * HDIM + ch * 8);
            cpa16(base + 32768 + so, Blo + (size_t)(r0 + r) * HDIM + ch * 8);
        }
        cpa_commit();
    };

#pragma unroll
    for (int i = tid; i < 2048; i += 128) {
        int r = i >> 4, ch = i & 15;
        uint32_t so = sw32(r, ch);
        cpa16(A0 + so, Ahi + (size_t)(m0 + r) * HDIM + ch * 8);
        cpa16(A1 + so, Alo + (size_t)(m0 + r) * HDIM + ch * 8);
    }
    {
        const uint32_t base = sb + 1024 + 65536;
#pragma unroll
        for (int i = tid; i < 2048; i += 128) {
            int r = i >> 4, ch = i & 15;
            uint32_t so = sw32(r, ch);
            cpa16(base + so,         Bhi + (size_t)(ng0 + r) * HDIM + ch * 8);
            cpa16(base + 32768 + so, Blo + (size_t)(ng0 + r) * HDIM + ch * 8);
        }
    }
    cpa_commit();

    uint32_t ph = 0;
    for (int n = 0; n < 4; ++n) {
        if (n + 1 < 4) { load_B(n + 1); cpa_wait<1>(); }
        else           { cpa_wait<0>(); }
        __syncthreads();
        fence_async_smem();
        if (wid == 0 && elect_one()) {
            const uint32_t bbase = sb + 1024 + 65536 + (n & 1) * 65536;
            uint64_t dah = make_desc(A0);
            uint64_t dal = make_desc(A1);
            uint64_t dbh = make_desc(bbase);
            uint64_t dbl = make_desc(bbase + 32768);
            const uint32_t acc = tmem + n * 128;
#pragma unroll
            for (int k = 0; k < 8; ++k) {
                uint64_t off = (uint64_t)((k & 3) * 2 + (k >> 2) * 1024);
                mma_f16_ss(acc, dah + off, dbh + off, TC_IDESC, k > 0);
                mma_f16_ss(acc, dah + off, dbl + off, TC_IDESC, 1u);
                mma_f16_ss(acc, dal + off, dbh + off, TC_IDESC, 1u);
            }
            tc_commit(sb + 8);
        }
        mbar_wait(sb + 8, ph);
        ph ^= 1;
        __syncthreads();
    }

    tc_fence_after();
    float *st = (float *)(sm + 1024);
    for (int n = 0; n < 4; ++n) {
#pragma unroll
        for (int part = 0; part < 4; ++part) {
            uint32_t d[32];
            ldtm32(d, tmem + n * 128 + part * 32);
            tc_wait_ld();
#pragma unroll
            for (int c = 0; c < 32; ++c)
                st[tid * 33 + c] = __uint_as_float(d[c]) * alpha;
            __syncthreads();
            const int col0 = ng0 + n * 128 + part * 32;
#pragma unroll
            for (int i = 0; i < 32; ++i) {
                int idx = i * 128 + tid;
                int rr = idx >> 5, cc = idx & 31;
                C[(size_t)(m0 + rr) * NCELL + col0 + cc] = st[rr * 33 + cc];
            }
            __syncthreads();
        }
    }
    __syncthreads();
    if (wid == 0) {
        tc_relinquish();
        tc_dealloc(tmem, 512);
    }
#endif
}

// ---------------------------------------------------------------------------
// fp32 -> bf16 hi/lo split kernels
// ---------------------------------------------------------------------------
__global__ void split_cols(const float *__restrict__ src, int ldsrc, int col0,
                           int cols4, __nv_bfloat16 *__restrict__ hi,
                           __nv_bfloat16 *__restrict__ lo)
{
    int idx = blockIdx.x * blockDim.x + threadIdx.x;
    int r = idx / cols4, c = idx - r * cols4;
    float4 v = *(const float4 *)(src + (size_t)r * ldsrc + col0 + c * 4);
    uint2 h, l;
    split4_fast(v, h, l);
    *(uint2 *)(hi + (size_t)idx * 4) = h;
    *(uint2 *)(lo + (size_t)idx * 4) = l;
}

__global__ void wT_split(const float *__restrict__ W, const int *__restrict__ hid,
                         __nv_bfloat16 *__restrict__ hi, __nv_bfloat16 *__restrict__ lo)
{
    int idx = blockIdx.x * blockDim.x + threadIdx.x;   // 128*2048
    int r = idx >> 7;
    int c = idx & 127;
    const float *Wh = W + (size_t)hid[0] * NINP * HDIM;
    float v = (r < NINP) ? Wh[(size_t)r * HDIM + c] : 0.f;
    __nv_bfloat16 h, l;
    split1(v, h, l);
    size_t o = (size_t)c * KPAD + r;
    hi[o] = h;
    lo[o] = l;
}

__global__ void transpose_split(const float *__restrict__ src, int ldsrc, int col0,
                                __nv_bfloat16 *__restrict__ hi,
                                __nv_bfloat16 *__restrict__ lo)
{
    __shared__ float t[32][33];
    int r0 = blockIdx.x * 32, c0 = blockIdx.y * 32;
    int tx = threadIdx.x, ty = threadIdx.y;  // 32 x 8
#pragma unroll
    for (int i = 0; i < 4; ++i) {
        int r = ty + i * 8;
        t[r][tx] = src[(size_t)(r0 + r) * ldsrc + col0 + c0 + tx];
    }
    __syncthreads();
#pragma unroll
    for (int i = 0; i < 4; ++i) {
        int c = ty + i * 8;
        float v = t[tx][c];
        __nv_bfloat16 h, l;
        split1(v, h, l);
        size_t o = (size_t)(c0 + c) * NCELL + r0 + tx;
        hi[o] = h;
        lo[o] = l;
    }
}

// ---------------------------------------------------------------------------
// gemm_small: C[64-mtile, 128-ntile] = bnrelu(A)[.,128] @ B[128,.] (+bias).
// BM=64 -> 128+ CTAs, fills the chip (R8 ncu: 64-CTA version ran at occ 12%).
// BNA: scale/shift computed in-kernel from raw stats; STATS: emit raw stats of C.
// 256 threads; per-thread 4x8 tile.
// ---------------------------------------------------------------------------
#define BM2 64
#define BN2 128

template <bool BNA, bool STATS>
__global__ void __launch_bounds__(256)
gemm_small(const float *__restrict__ A, const float *__restrict__ B,
           float *__restrict__ C, int ldb, int ldc,
           const float *__restrict__ bias,
           const float *__restrict__ statsIn,
           const float *__restrict__ g, const float *__restrict__ be,
           const int *__restrict__ hid, int hstride,
           float *__restrict__ statsOut)
{
    __shared__ float As[BK][BM2 + 4];
    __shared__ float Bs[BK][BN2 + 4];
    __shared__ float bnSs[128], bnBs[128];

    const int tid = threadIdx.x;
    const int tx = tid & 15;
    const int ty = tid >> 4;
    const int m0 = blockIdx.x * BM2;
    const int n0 = blockIdx.y * BN2;

    if (BNA && tid < 128) {
        float s1 = statsIn[tid], s2 = statsIn[128 + tid];
        float mean = s1 * (1.f / (float)NCELL);
        float var = s2 * (1.f / (float)NCELL) - mean * mean;
        float rstd = rsqrtf(var + BN_EPS);
        int off = hid ? hid[0] * hstride : 0;
        float gg = g[off + tid];
        bnSs[tid] = gg * rstd;
        bnBs[tid] = be[off + tid] - gg * mean * rstd;
    }

    // loaders: A tile 64x16 = 256 float4 (1 per thread); B tile 16x128 = 512 (2 per thread)
    const int aRow0 = tid >> 2, aK0 = (tid & 3) * 4;
    const int bK0 = tid >> 5, bN0 = (tid & 31) * 4;
    const int bK1 = (tid + 256) >> 5, bN1 = bN0;

    const float *Ap0 = A + (size_t)(m0 + aRow0) * HDIM + aK0;
    const float *Bp0 = B + (size_t)bK0 * ldb + n0 + bN0;
    const float *Bp1 = B + (size_t)bK1 * ldb + n0 + bN1;

    float2 acc[4][4];
#pragma unroll
    for (int i = 0; i < 4; ++i)
#pragma unroll
        for (int j = 0; j < 4; ++j) acc[i][j] = make_float2(0.f, 0.f);

    float4 ra0 = *(const float4 *)Ap0;
    float4 rb0 = *(const float4 *)Bp0;
    float4 rb1 = *(const float4 *)Bp1;

    const int chunks = HDIM / BK;   // 8
    for (int c = 0; c < chunks; ++c) {
        __syncthreads();
        const int cK = c * BK;
        if (BNA) {
            As[aK0 + 0][aRow0] = fmaxf(fmaf(ra0.x, bnSs[cK + aK0 + 0], bnBs[cK + aK0 + 0]), 0.f);
            As[aK0 + 1][aRow0] = fmaxf(fmaf(ra0.y, bnSs[cK + aK0 + 1], bnBs[cK + aK0 + 1]), 0.f);
            As[aK0 + 2][aRow0] = fmaxf(fmaf(ra0.z, bnSs[cK + aK0 + 2], bnBs[cK + aK0 + 2]), 0.f);
            As[aK0 + 3][aRow0] = fmaxf(fmaf(ra0.w, bnSs[cK + aK0 + 3], bnBs[cK + aK0 + 3]), 0.f);
        } else {
            As[aK0 + 0][aRow0] = ra0.x; As[aK0 + 1][aRow0] = ra0.y;
            As[aK0 + 2][aRow0] = ra0.z; As[aK0 + 3][aRow0] = ra0.w;
        }
        *(float4 *)&Bs[bK0][bN0] = rb0;
        *(float4 *)&Bs[bK1][bN1] = rb1;
        __syncthreads();

        if (c + 1 < chunks) {
            Ap0 += BK;
            ra0 = *(const float4 *)Ap0;
            Bp0 += (size_t)BK * ldb; Bp1 += (size_t)BK * ldb;
            rb0 = *(const float4 *)Bp0;
            rb1 = *(const float4 *)Bp1;
        }

#pragma unroll
        for (int kk = 0; kk < BK; ++kk) {
            float4 a0 = *(const float4 *)&As[kk][ty * 4];
            float4 b0 = *(const float4 *)&Bs[kk][tx * 4];
            float4 b1 = *(const float4 *)&Bs[kk][64 + tx * 4];
            float av[4] = {a0.x, a0.y, a0.z, a0.w};
            float2 bp[4] = {make_float2(b0.x, b0.y), make_float2(b0.z, b0.w),
                            make_float2(b1.x, b1.y), make_float2(b1.z, b1.w)};
#pragma unroll
            for (int i = 0; i < 4; ++i) {
                float2 aa = make_float2(av[i], av[i]);
#pragma unroll
                for (int j = 0; j < 4; ++j) fma2(acc[i][j], aa, bp[j]);
            }
        }
    }

    float bad0[4] = {0.f, 0.f, 0.f, 0.f}, bad1[4] = {0.f, 0.f, 0.f, 0.f};
    if (bias != nullptr) {
#pragma unroll
        for (int j = 0; j < 4; ++j) {
            bad0[j] = bias[n0 + tx * 4 + j];
            bad1[j] = bias[n0 + 64 + tx * 4 + j];
        }
    }

    float cs[8], cq[8];
#pragma unroll
    for (int j = 0; j < 8; ++j) { cs[j] = 0.f; cq[j] = 0.f; }

#pragma unroll
    for (int i = 0; i < 4; ++i) {
        int r = m0 + ty * 4 + i;
        float v[8] = {acc[i][0].x, acc[i][0].y, acc[i][1].x, acc[i][1].y,
                      acc[i][2].x, acc[i][2].y, acc[i][3].x, acc[i][3].y};
        float w[8];
#pragma unroll
        for (int j = 0; j < 4; ++j) { w[j] = v[j] + bad0[j]; w[4 + j] = v[4 + j] + bad1[j]; }
        if (STATS) {
#pragma unroll
            for (int j = 0; j < 8; ++j) { cs[j] += w[j]; cq[j] += w[j] * w[j]; }
        }
        float *crow = C + (size_t)r * ldc;
        *(float4 *)(crow + n0 + tx * 4)      = make_float4(w[0], w[1], w[2], w[3]);
        *(float4 *)(crow + n0 + 64 + tx * 4) = make_float4(w[4], w[5], w[6], w[7]);
    }

    if (STATS) {
        __syncthreads();
        float *sred = (float *)As;     // 256 floats
        if (tid < 128) { sred[tid] = 0.f; sred[128 + tid] = 0.f; }
        __syncthreads();
#pragma unroll
        for (int j = 0; j < 8; ++j) {
            int col = (j < 4) ? (tx * 4 + j) : (64 + tx * 4 + (j - 4));
            atomicAdd(&sred[col], cs[j]);
            atomicAdd(&sred[128 + col], cq[j]);
        }
        __syncthreads();
        if (tid < 128) {
            atomicAdd(statsOut + tid, sred[tid]);
            atomicAdd(statsOut + 128 + tid, sred[128 + tid]);
        }
    }
}

// ---------------------------------------------------------------------------
// BatchNorm stats (enc output only)
// ---------------------------------------------------------------------------
__global__ void bn_stats(const float *__restrict__ h, float *__restrict__ stats)
{
    int col = threadIdx.x;
    int r0 = blockIdx.x * 32;
    float s = 0.f, s2 = 0.f;
#pragma unroll 8
    for (int r = 0; r < 32; ++r) {
        float v = h[(size_t)(r0 + r) * HDIM + col];
        s += v; s2 += v * v;
    }
    atomicAdd(&stats[col], s);
    atomicAdd(&stats[128 + col], s2);
}

// ---------------------------------------------------------------------------
// Row softmax in place
// ---------------------------------------------------------------------------
__global__ void softmax_row(float *__restrict__ attn)
{
    extern __shared__ float row[];
    __shared__ float red[256];
    const int t = threadIdx.x;
    float *p = attn + (size_t)blockIdx.x * NCELL;

    float m = -1e30f;
    for (int i = t; i < NCELL / 4; i += 256) {
        float4 v = ((const float4 *)p)[i];
        ((float4 *)row)[i] = v;
        m = fmaxf(m, fmaxf(fmaxf(v.x, v.y), fmaxf(v.z, v.w)));
    }
    red[t] = m; __syncthreads();
    for (int s = 128; s > 0; s >>= 1) {
        if (t < s) red[t] = fmaxf(red[t], red[t + s]);
        __syncthreads();
    }
    const float bmax = red[0];
    __syncthreads();

    float sum = 0.f;
    for (int i = t; i < NCELL / 4; i += 256) {
        float4 v = ((float4 *)row)[i];
        v.x = __expf(v.x - bmax); v.y = __expf(v.y - bmax);
        v.z = __expf(v.z - bmax); v.w = __expf(v.w - bmax);
        sum += v.x + v.y + v.z + v.w;
        ((float4 *)row)[i] = v;
    }
    red[t] = sum; __syncthreads();
    for (int s = 128; s > 0; s >>= 1) {
        if (t < s) red[t] += red[t + s];
        __syncthreads();
    }
    const float inv = 1.f / red[0];
    __syncthreads();

    for (int i = t; i < NCELL / 4; i += 256) {
        float4 v = ((float4 *)row)[i];
        v.x *= inv; v.y *= inv; v.z *= inv; v.w *= inv;
        ((float4 *)p)[i] = v;
    }
}

// ---------------------------------------------------------------------------
// Variational heads
// ---------------------------------------------------------------------------
__global__ void heads_kernel(const float *__restrict__ o,
                             const float *__restrict__ mW, const float *__restrict__ mb,
                             const float *__restrict__ vW, const float *__restrict__ vb,
                             const float *__restrict__ eps,
                             float *__restrict__ qm, float *__restrict__ qv,
                             float *__restrict__ lat)
{
    extern __shared__ float smh[];
    float *Wm  = smh;
    float *Wv  = smh + 4096;
    float *osm = smh + 8192;
    const int t = threadIdx.x;
    const int r0 = blockIdx.x * 128;

    for (int i = t; i < HDIM * NOUTD; i += 256) { Wm[i] = mW[i]; Wv[i] = vW[i]; }
    for (int i = t; i < 128 * HDIM; i += 256) {
        int r = i >> 7, c = i & 127;
        osm[r * 129 + c] = o[(size_t)(r0 + r) * HDIM + c];
    }
    __syncthreads();

    for (int idx = t; idx < 128 * NOUTD; idx += 256) {
        int r = idx >> 5, c = idx & 31;
        const float *orow = &osm[r * 129];
        float dm = 0.f, dv = 0.f;
#pragma unroll 8
        for (int k = 0; k < HDIM; ++k) {
            float ov = orow[k];
            dm += ov * Wm[k * NOUTD + c];
            dv += ov * Wv[k * NOUTD + c];
        }
        int R = r0 + r;
        float mval = dm + mb[c];
        float vval = __expf(dv + vb[c]);
        qm[R * NOUTD + c]  = mval;
        qv[R * NOUTD + c]  = vval;
        lat[R * NOUTD + c] = mval + sqrtf(vval) * eps[R * NOUTD + c];
    }
}

// ---------------------------------------------------------------------------
// Launch
// ---------------------------------------------------------------------------
extern "C" void kernel_launch(void *const *d_in, const int *in_sizes, int n_in,
                              void *d_out, int out_size)
{
    const float *x       = (const float *)d_in[0];
    const float *spatial = (const float *)d_in[1];
    const float *eps     = (const float *)d_in[2];
    const float *enc_W   = (const float *)d_in[3];
    const float *enc_g   = (const float *)d_in[5];
    const float *enc_be  = (const float *)d_in[6];
    const float *sh_W1   = (const float *)d_in[7];
    const float *sh_g1   = (const float *)d_in[9];
    const float *sh_be1  = (const float *)d_in[10];
    const float *sh_W2   = (const float *)d_in[11];
    const float *sh_g2   = (const float *)d_in[13];
    const float *sh_be2  = (const float *)d_in[14];
    const float *qkv_W   = (const float *)d_in[15];
    const float *qkv_b   = (const float *)d_in[16];
    const float *o_W     = (const float *)d_in[17];
    const float *o_b     = (const float *)d_in[18];
    const float *mean_W  = (const float *)d_in[19];
    const float *mean_b  = (const float *)d_in[20];
    const float *var_W   = (const float *)d_in[21];
    const float *var_b   = (const float *)d_in[22];
    const int   *hid     = (const int *)d_in[23];

    float *out = (float *)d_out;
    float *out_qm   = out;
    float *out_qv   = out + (size_t)NCELL * NOUTD;
    float *out_lat  = out + 2 * (size_t)NCELL * NOUTD;
    float *out_attn = out + 3 * (size_t)NCELL * NOUTD;

    float *bufA, *bufB, *qkv, *kagg, *stats;
    __nv_bfloat16 *q_hi, *q_lo, *ka_hi, *ka_lo;
    __nv_bfloat16 *kT_hi, *kT_lo, *vT_hi, *vT_lo, *wT_hi, *wT_lo;
    cudaGetSymbolAddress((void **)&bufA, g_bufA);
    cudaGetSymbolAddress((void **)&bufB, g_bufB);
    cudaGetSymbolAddress((void **)&qkv,  g_qkv);
    cudaGetSymbolAddress((void **)&kagg, g_kagg);
    cudaGetSymbolAddress((void **)&stats, g_stats);
    cudaGetSymbolAddress((void **)&q_hi, g_q_hi);
    cudaGetSymbolAddress((void **)&q_lo, g_q_lo);
    cudaGetSymbolAddress((void **)&ka_hi, g_ka_hi);
    cudaGetSymbolAddress((void **)&ka_lo, g_ka_lo);
    cudaGetSymbolAddress((void **)&kT_hi, g_kT_hi);
    cudaGetSymbolAddress((void **)&kT_lo, g_kT_lo);
    cudaGetSymbolAddress((void **)&vT_hi, g_vT_hi);
    cudaGetSymbolAddress((void **)&vT_lo, g_vT_lo);
    cudaGetSymbolAddress((void **)&wT_hi, g_wT_hi);
    cudaGetSymbolAddress((void **)&wT_lo, g_wT_lo);

    cudaFuncSetAttribute(tc_skinny_f32, cudaFuncAttributeMaxDynamicSharedMemorySize, SKF_SMEM);
    cudaFuncSetAttribute(tc_wide,       cudaFuncAttributeMaxDynamicSharedMemorySize, WIDE_SMEM);

    const size_t NH_BYTES = (size_t)NCELL * HDIM * sizeof(float);
    const float SCALE = 0.08838834764831845f; // 1/sqrt(128)
    float *slot0 = stats, *slot1 = stats + 256, *slot2 = stats + 512;

    cudaMemsetAsync(stats, 0, 768 * sizeof(float));

    // 1. encoder: h = x @ enc_W[hid]
    wT_split<<<1024, 256>>>(enc_W, hid, wT_hi, wT_lo);
    cudaMemsetAsync(bufA, 0, NH_BYTES);
    tc_skinny_f32<<<dim3(64, 1, 4), 128, SKF_SMEM>>>(
        x, NINP, NINP, wT_hi, wT_lo, KPAD, bufA, HDIM, 512, 1.f);
    bn_stats<<<256, 128>>>(bufA, slot0);

    // 2. sh1 = BN1(bufA) @ W1 ; stats -> slot1     (BM=64: 128 CTAs)
    gemm_small<true, true><<<dim3(128, 1), 256>>>(
        bufA, sh_W1, bufB, HDIM, HDIM, nullptr,
        slot0, enc_g, enc_be, hid, HDIM, slot1);

    // 3. sh2 = BN2(bufB) @ W2 ; stats -> slot2
    gemm_small<true, true><<<dim3(128, 1), 256>>>(
        bufB, sh_W2, bufA, HDIM, HDIM, nullptr,
        slot1, sh_g1, sh_be1, nullptr, 0, slot2);

    // 4. qkv = BN3(bufA) @ qkv_W + qkv_b          (384 CTAs)
    gemm_small<true, false><<<dim3(128, 3), 256>>>(
        bufA, qkv_W, qkv, 3 * HDIM, 3 * HDIM, qkv_b,
        slot2, sh_g2, sh_be2, nullptr, 0, nullptr);

    // 5. small bf16 conversions (q, kT, vT)
    split_cols<<<1024, 256>>>(qkv, 3 * HDIM, 0, HDIM / 4, q_hi, q_lo);
    transpose_split<<<dim3(256, 4), dim3(32, 8)>>>(qkv, 3 * HDIM, HDIM, kT_hi, kT_lo);
    transpose_split<<<dim3(256, 4), dim3(32, 8)>>>(qkv, 3 * HDIM, 2 * HDIM, vT_hi, vT_lo);

    // 6. k_agg = spatial @ k   (split-K = 4)
    cudaMemsetAsync(kagg, 0, NH_BYTES);
    tc_skinny_f32<<<dim3(64, 1, 4), 128, SKF_SMEM>>>(
        spatial, NCELL, NCELL, kT_hi, kT_lo, NCELL, kagg, HDIM, 2048, 1.f);
    split_cols<<<1024, 256>>>(kagg, HDIM, 0, HDIM / 4, ka_hi, ka_lo);

    // 7. logits = (q @ k_agg^T) / sqrt(H)
    tc_wide<<<dim3(64, 16), 128, WIDE_SMEM>>>(q_hi, q_lo, ka_hi, ka_lo, out_attn, SCALE);

    // 8. softmax in place
    softmax_row<<<NCELL, 256, NCELL * sizeof(float)>>>(out_attn);

    // 9. av = attn @ v   (split-K = 4)
    cudaMemsetAsync(bufA, 0, NH_BYTES);
    tc_skinny_f32<<<dim3(64, 1, 4), 128, SKF_SMEM>>>(
        out_attn, NCELL, NCELL, vT_hi, vT_lo, NCELL, bufA, HDIM, 2048, 1.f);

    // 10. o = av @ o_W + o_b
    gemm_small<false, false><<<dim3(128, 1), 256>>>(
        bufA, o_W, bufB, HDIM, HDIM, o_b,
        nullptr, nullptr, nullptr, nullptr, 0, nullptr);

    // 11. variational heads
    const int heads_smem = (4096 + 4096 + 128 * 129) * sizeof(float);
    cudaFuncSetAttribute(heads_kernel, cudaFuncAttributeMaxDynamicSharedMemorySize,
                         heads_smem);
    heads_kernel<<<64, 256, heads_smem>>>(bufB, mean_W, mean_b, var_W, var_b,
                                          eps, out_qm, out_qv, out_lat);
}

// round 10
// speedup vs baseline: 1.3508x; 1.0077x over previous
#include <cuda_runtime.h>
#include <cuda_bf16.h>
#include <math.h>
#include <stdint.h>

#define NCELL 8192
#define NINP  2000
#define KPAD  2048
#define HDIM  128
#define NOUTD 32
#define BN_EPS 1e-3f

#if defined(__CUDA_ARCH_FEAT_SM103_ALL) || defined(__CUDA_ARCH_FEAT_SM100_ALL) || \
    defined(__CUDA_ARCH_FEAT_SM110_ALL) || defined(__CUDA_ARCH_FEAT_SM101_ALL)
#define TC_ENABLED 1
#else
#define TC_ENABLED 0
#endif

// ---------------------------------------------------------------------------
// Scratch
// ---------------------------------------------------------------------------
__device__ __align__(256) float g_bufA[NCELL * HDIM];
__device__ __align__(256) float g_bufB[NCELL * HDIM];
__device__ __align__(256) float g_qkv [NCELL * 3 * HDIM];
__device__ __align__(256) float g_kagg[NCELL * HDIM];
__device__ __align__(256) float g_stats[768];   // 3 BN slots x (sum[128], sumsq[128])

__device__ __align__(256) __nv_bfloat16 g_q_hi [NCELL * HDIM];
__device__ __align__(256) __nv_bfloat16 g_q_lo [NCELL * HDIM];
__device__ __align__(256) __nv_bfloat16 g_ka_hi[NCELL * HDIM];
__device__ __align__(256) __nv_bfloat16 g_ka_lo[NCELL * HDIM];
__device__ __align__(256) __nv_bfloat16 g_kT_hi[HDIM * NCELL];
__device__ __align__(256) __nv_bfloat16 g_kT_lo[HDIM * NCELL];
__device__ __align__(256) __nv_bfloat16 g_vT_hi[HDIM * NCELL];
__device__ __align__(256) __nv_bfloat16 g_vT_lo[HDIM * NCELL];
__device__ __align__(256) __nv_bfloat16 g_wT_hi[HDIM * KPAD];
__device__ __align__(256) __nv_bfloat16 g_wT_lo[HDIM * KPAD];

// ---------------------------------------------------------------------------
// PTX helpers
// ---------------------------------------------------------------------------
__device__ __forceinline__ uint32_t cvta_smem(const void *p) {
    uint32_t a;
    asm("{ .reg .u64 t; cvta.to.shared.u64 t, %1; cvt.u32.u64 %0, t; }"
        : "=r"(a) : "l"(p));
    return a;
}
__device__ __forceinline__ uint32_t elect_one() {
    uint32_t p;
    asm volatile("{ .reg .pred p; elect.sync _|p, 0xFFFFFFFF; selp.b32 %0, 1, 0, p; }"
                 : "=r"(p));
    return p;
}
__device__ __forceinline__ void mbar_init(uint32_t mbar, uint32_t cnt) {
    asm volatile("mbarrier.init.shared.b64 [%0], %1;"
                 :: "r"(mbar), "r"(cnt) : "memory");
}
__device__ __forceinline__ void mbar_wait(uint32_t mbar, uint32_t parity) {
    asm volatile(
        "{\n\t.reg .pred P;\n"
        "LW_%=:\n\t"
        "mbarrier.try_wait.parity.acquire.cta.shared::cta.b64 P, [%0], %1, 0x989680;\n\t"
        "@P bra LD_%=;\n\t"
        "bra LW_%=;\n"
        "LD_%=:\n\t}"
        :: "r"(mbar), "r"(parity) : "memory");
}
__device__ __forceinline__ void fence_async_smem() {
    asm volatile("fence.proxy.async.shared::cta;" ::: "memory");
}
__device__ __forceinline__ void cpa16(uint32_t dst, const void *src) {
    asm volatile("cp.async.cg.shared.global [%0], [%1], 16;"
                 :: "r"(dst), "l"(src) : "memory");
}
__device__ __forceinline__ void cpa_commit() {
    asm volatile("cp.async.commit_group;" ::: "memory");
}
template <int N>
__device__ __forceinline__ void cpa_wait() {
    asm volatile("cp.async.wait_group %0;" :: "n"(N) : "memory");
}
__device__ __forceinline__ void red4(float *p, float a, float b, float c, float d) {
    asm volatile("red.global.add.v4.f32 [%0], {%1, %2, %3, %4};"
                 :: "l"(p), "f"(a), "f"(b), "f"(c), "f"(d) : "memory");
}

// ---- tcgen05 ----
__device__ __forceinline__ void tc_alloc(uint32_t smem_dst, uint32_t ncols) {
    asm volatile("tcgen05.alloc.cta_group::1.sync.aligned.shared::cta.b32 [%0], %1;"
                 :: "r"(smem_dst), "r"(ncols) : "memory");
}
__device__ __forceinline__ void tc_dealloc(uint32_t tmem, uint32_t ncols) {
    asm volatile("tcgen05.dealloc.cta_group::1.sync.aligned.b32 %0, %1;"
                 :: "r"(tmem), "r"(ncols));
}
__device__ __forceinline__ void tc_relinquish() {
    asm volatile("tcgen05.relinquish_alloc_permit.cta_group::1.sync.aligned;");
}
__device__ __forceinline__ void tc_commit(uint32_t mbar) {
    asm volatile("tcgen05.commit.cta_group::1.mbarrier::arrive::one.shared::cluster.b64 [%0];"
                 :: "r"(mbar) : "memory");
}
__device__ __forceinline__ void tc_fence_after() {
    asm volatile("tcgen05.fence::after_thread_sync;" ::: "memory");
}
__device__ __forceinline__ void tc_wait_ld() {
    asm volatile("tcgen05.wait::ld.sync.aligned;" ::: "memory");
}
__device__ __forceinline__ void ldtm32(uint32_t *r, uint32_t addr) {
    asm volatile(
        "tcgen05.ld.sync.aligned.32x32b.x32.b32 "
        "{%0, %1, %2, %3, %4, %5, %6, %7, "
        " %8, %9, %10, %11, %12, %13, %14, %15, "
        " %16, %17, %18, %19, %20, %21, %22, %23, "
        " %24, %25, %26, %27, %28, %29, %30, %31}, [%32];"
        : "=r"(r[0]),  "=r"(r[1]),  "=r"(r[2]),  "=r"(r[3]),
          "=r"(r[4]),  "=r"(r[5]),  "=r"(r[6]),  "=r"(r[7]),
          "=r"(r[8]),  "=r"(r[9]),  "=r"(r[10]), "=r"(r[11]),
          "=r"(r[12]), "=r"(r[13]), "=r"(r[14]), "=r"(r[15]),
          "=r"(r[16]), "=r"(r[17]), "=r"(r[18]), "=r"(r[19]),
          "=r"(r[20]), "=r"(r[21]), "=r"(r[22]), "=r"(r[23]),
          "=r"(r[24]), "=r"(r[25]), "=r"(r[26]), "=r"(r[27]),
          "=r"(r[28]), "=r"(r[29]), "=r"(r[30]), "=r"(r[31])
        : "r"(addr));
}
__device__ __forceinline__ void mma_f16_ss(uint32_t d, uint64_t a_desc,
                                           uint64_t b_desc, uint32_t idesc,
                                           uint32_t en) {
    asm volatile(
        "{\n\t.reg .pred p;\n\t"
        "setp.ne.u32 p, %5, 0;\n\t"
        "tcgen05.mma.cta_group::1.kind::f16 [%0], %1, %2, %3, {%4, %4, %4, %4}, p;\n\t}"
        :: "r"(d), "l"(a_desc), "l"(b_desc), "r"(idesc), "r"(0u), "r"(en)
        : "memory");
}
__device__ __forceinline__ uint64_t make_desc(uint32_t addr) {
    return ((uint64_t)2 << 61) | ((uint64_t)1 << 46) | ((uint64_t)64 << 32) |
           ((uint64_t)1 << 16) | (((uint64_t)(addr >> 4)) & 0x3FFF);
}
__device__ __forceinline__ void fma2(float2 &c, const float2 &a, const float2 &b) {
    unsigned long long       &cc = reinterpret_cast<unsigned long long &>(c);
    const unsigned long long &aa = reinterpret_cast<const unsigned long long &>(a);
    const unsigned long long &bb = reinterpret_cast<const unsigned long long &>(b);
    asm("fma.rn.f32x2 %0, %1, %2, %0;" : "+l"(cc) : "l"(aa), "l"(bb));
}
__device__ __forceinline__ void split1(float v, __nv_bfloat16 &h, __nv_bfloat16 &l) {
    h = __float2bfloat16(v);
    l = __float2bfloat16(v - __bfloat162float(h));
}
// Fast packed hi/lo split (bit-identical to split1 per lane)
__device__ __forceinline__ void split4_fast(float4 v, uint2 &hi, uint2 &lo) {
    uint32_t h01, h23, l01, l23;
    asm("cvt.rn.bf16x2.f32 %0, %1, %2;" : "=r"(h01) : "f"(v.y), "f"(v.x));
    asm("cvt.rn.bf16x2.f32 %0, %1, %2;" : "=r"(h23) : "f"(v.w), "f"(v.z));
    float r0 = v.x - __uint_as_float(h01 << 16);
    float r1 = v.y - __uint_as_float(h01 & 0xFFFF0000u);
    float r2 = v.z - __uint_as_float(h23 << 16);
    float r3 = v.w - __uint_as_float(h23 & 0xFFFF0000u);
    asm("cvt.rn.bf16x2.f32 %0, %1, %2;" : "=r"(l01) : "f"(r1), "f"(r0));
    asm("cvt.rn.bf16x2.f32 %0, %1, %2;" : "=r"(l23) : "f"(r3), "f"(r2));
    hi = make_uint2(h01, h23);
    lo = make_uint2(l01, l23);
}

static constexpr uint32_t TC_IDESC = 0x8200490u; // F32 acc, BF16xBF16, M=128, N=128

__device__ __forceinline__ uint32_t sw32(int r, int ch) {  // 128x128 bf16 tile
    uint32_t byte = ((r >> 3) + (ch >> 3) * 16) * 1024 + (r & 7) * 128 + (ch & 7) * 16;
    return byte ^ ((byte >> 3) & 0x70);
}

// ---------------------------------------------------------------------------
// tc_skinny_f32 (unchanged from 594us kernel)
// ---------------------------------------------------------------------------
#define SKF_SMEM (1024 + 2 * 65536)

__global__ void __launch_bounds__(128)
tc_skinny_f32(const float *__restrict__ A, int lda, int Kvalid,
              const __nv_bfloat16 *__restrict__ Bhi,
              const __nv_bfloat16 *__restrict__ Blo, int ldb,
              float *__restrict__ C, int ldc, int kpc, float alpha)
{
#if TC_ENABLED
    extern __shared__ char sm[];
    const uint32_t sb = cvta_smem(sm);
    const int tid = threadIdx.x;
    const int wid = tid >> 5;

    if (wid == 0) tc_alloc(sb, 128);
    if (tid == 64) mbar_init(sb + 8, 1);
    __syncthreads();
    uint32_t tmem;
    asm volatile("ld.shared.b32 %0, [%1];" : "=r"(tmem) : "r"(sb));

    const int m0 = blockIdx.x * 128;
    const int kb0 = blockIdx.z * kpc;
    const int S = kpc >> 6;

    const int aRow = tid >> 4;
    const int aCol = (tid & 15) * 4;
    const float *aBase = A + (size_t)(m0 + aRow) * lda + aCol;
    const size_t aRowStep = (size_t)8 * lda;
    const uint32_t toffA = (uint32_t)(((tid >> 4) * 128 + (tid & 15) * 8) ^ ((tid >> 4) << 4));
    const int bRow = tid >> 3;
    const int bCol = (tid & 7) * 8;
    const uint32_t toffB = (uint32_t)((((tid >> 3) & 7) * 128 + (tid & 7) * 16) ^
                                      ((((tid >> 3) & 7) << 4)));
    const uint32_t bAtom = (uint32_t)(tid >> 6) * 1024;

    float4 regs[16];

    auto ldA = [&](int s) {
        const int kb = kb0 + s * 64;
        const bool ok = (kb + aCol) < Kvalid;
        const float *p = aBase + kb;
#pragma unroll
        for (int i = 0; i < 16; ++i) {
            regs[i] = ok ? *(const float4 *)(p + i * aRowStep)
                         : make_float4(0.f, 0.f, 0.f, 0.f);
        }
    };
    auto ldB = [&](int s) {
        const uint32_t bh = sb + 1024 + (s & 1) * 65536 + 32768;
        const int kb = kb0 + s * 64;
        const __nv_bfloat16 *ph = Bhi + (size_t)bRow * ldb + kb + bCol;
        const __nv_bfloat16 *pl = Blo + (size_t)bRow * ldb + kb + bCol;
        const uint32_t so0 = bAtom + toffB;
#pragma unroll
        for (int i = 0; i < 8; ++i) {
            uint32_t so = so0 + i * 2048;
            cpa16(bh + so,         ph + (size_t)i * 16 * ldb);
            cpa16(bh + 16384 + so, pl + (size_t)i * 16 * ldb);
        }
        cpa_commit();
    };
    auto stA = [&](int s) {
        char *ah = sm + 1024 + (s & 1) * 65536;
        char *al = ah + 16384;
#pragma unroll
        for (int i = 0; i < 16; ++i) {
            uint2 h, l;
            split4_fast(regs[i], h, l);
            uint32_t sz = toffA + i * 1024;
            *(uint2 *)(ah + sz) = h;
            *(uint2 *)(al + sz) = l;
        }
    };

    ldB(0);
    ldA(0);
    uint32_t ph = 0;
    for (int s = 0; s < S; ++s) {
        cpa_wait<0>();
        stA(s);
        __syncthreads();
        fence_async_smem();
        if (wid == 0 && elect_one()) {
            const uint32_t base = sb + 1024 + (s & 1) * 65536;
            uint64_t dah = make_desc(base);
            uint64_t dal = make_desc(base + 16384);
            uint64_t dbh = make_desc(base + 32768);
            uint64_t dbl = make_desc(base + 49152);
#pragma unroll
            for (int k = 0; k < 4; ++k) {
                uint64_t off = (uint64_t)(k * 2);
                mma_f16_ss(tmem, dah + off, dbh + off, TC_IDESC, (s > 0) || (k > 0));
                mma_f16_ss(tmem, dah + off, dbl + off, TC_IDESC, 1u);
                mma_f16_ss(tmem, dal + off, dbh + off, TC_IDESC, 1u);
            }
            tc_commit(sb + 8);
        }
        if (s + 1 < S) { ldB(s + 1); ldA(s + 1); }
        mbar_wait(sb + 8, ph);
        ph ^= 1;
        __syncthreads();
    }

    tc_fence_after();
#pragma unroll
    for (int part = 0; part < 4; ++part) {
        uint32_t d[32];
        ldtm32(d, tmem + part * 32);
        tc_wait_ld();
        float *cp = C + (size_t)(m0 + tid) * ldc + part * 32;
#pragma unroll
        for (int j = 0; j < 8; ++j)
            red4(cp + j * 4,
                 __uint_as_float(d[j * 4 + 0]) * alpha,
                 __uint_as_float(d[j * 4 + 1]) * alpha,
                 __uint_as_float(d[j * 4 + 2]) * alpha,
                 __uint_as_float(d[j * 4 + 3]) * alpha);
    }
    __syncthreads();
    if (wid == 0) {
        tc_relinquish();
        tc_dealloc(tmem, 128);
    }
#endif
}

// ---------------------------------------------------------------------------
// tc_wide (unchanged)
// ---------------------------------------------------------------------------
#define WIDE_SMEM (1024 + 65536 + 131072)

__global__ void __launch_bounds__(128)
tc_wide(const __nv_bfloat16 *__restrict__ Ahi, const __nv_bfloat16 *__restrict__ Alo,
        const __nv_bfloat16 *__restrict__ Bhi, const __nv_bfloat16 *__restrict__ Blo,
        float *__restrict__ C, float alpha)
{
#if TC_ENABLED
    extern __shared__ char sm[];
    const uint32_t sb = cvta_smem(sm);
    const int tid = threadIdx.x;
    const int wid = tid >> 5;

    if (wid == 0) tc_alloc(sb, 512);
    if (tid == 64) mbar_init(sb + 8, 1);
    __syncthreads();
    uint32_t tmem;
    asm volatile("ld.shared.b32 %0, [%1];" : "=r"(tmem) : "r"(sb));

    const int m0 = blockIdx.x * 128;
    const int ng0 = blockIdx.y * 512;

    const uint32_t A0 = sb + 1024;
    const uint32_t A1 = A0 + 32768;

    auto load_B = [&](int n) {
        const uint32_t base = sb + 1024 + 65536 + (n & 1) * 65536;
        const int r0 = ng0 + n * 128;
#pragma unroll
        for (int i = tid; i < 2048; i += 128) {
            int r = i >> 4, ch = i & 15;
            uint32_t so = sw32(r, ch);
            cpa16(base + so,         Bhi + (size_t)(r0 + r) * HDIM + ch * 8);
            cpa16(base + 32768 + so, Blo + (size_t)(r0 + r) * HDIM + ch * 8);
        }
        cpa_commit();
    };

#pragma unroll
    for (int i = tid; i < 2048; i += 128) {
        int r = i >> 4, ch = i & 15;
        uint32_t so = sw32(r, ch);
        cpa16(A0 + so, Ahi + (size_t)(m0 + r) * HDIM + ch * 8);
        cpa16(A1 + so, Alo + (size_t)(m0 + r) * HDIM + ch * 8);
    }
    {
        const uint32_t base = sb + 1024 + 65536;
#pragma unroll
        for (int i = tid; i < 2048; i += 128) {
            int r = i >> 4, ch = i & 15;
            uint32_t so = sw32(r, ch);
            cpa16(base + so,         Bhi + (size_t)(ng0 + r) * HDIM + ch * 8);
            cpa16(base + 32768 + so, Blo + (size_t)(ng0 + r) * HDIM + ch * 8);
        }
    }
    cpa_commit();

    uint32_t ph = 0;
    for (int n = 0; n < 4; ++n) {
        if (n + 1 < 4) { load_B(n + 1); cpa_wait<1>(); }
        else           { cpa_wait<0>(); }
        __syncthreads();
        fence_async_smem();
        if (wid == 0 && elect_one()) {
            const uint32_t bbase = sb + 1024 + 65536 + (n & 1) * 65536;
            uint64_t dah = make_desc(A0);
            uint64_t dal = make_desc(A1);
            uint64_t dbh = make_desc(bbase);
            uint64_t dbl = make_desc(bbase + 32768);
            const uint32_t acc = tmem + n * 128;
#pragma unroll
            for (int k = 0; k < 8; ++k) {
                uint64_t off = (uint64_t)((k & 3) * 2 + (k >> 2) * 1024);
                mma_f16_ss(acc, dah + off, dbh + off, TC_IDESC, k > 0);
                mma_f16_ss(acc, dah + off, dbl + off, TC_IDESC, 1u);
                mma_f16_ss(acc, dal + off, dbh + off, TC_IDESC, 1u);
            }
            tc_commit(sb + 8);
        }
        mbar_wait(sb + 8, ph);
        ph ^= 1;
        __syncthreads();
    }

    tc_fence_after();
    float *st = (float *)(sm + 1024);
    for (int n = 0; n < 4; ++n) {
#pragma unroll
        for (int part = 0; part < 4; ++part) {
            uint32_t d[32];
            ldtm32(d, tmem + n * 128 + part * 32);
            tc_wait_ld();
#pragma unroll
            for (int c = 0; c < 32; ++c)
                st[tid * 33 + c] = __uint_as_float(d[c]) * alpha;
            __syncthreads();
            const int col0 = ng0 + n * 128 + part * 32;
#pragma unroll
            for (int i = 0; i < 32; ++i) {
                int idx = i * 128 + tid;
                int rr = idx >> 5, cc = idx & 31;
                C[(size_t)(m0 + rr) * NCELL + col0 + cc] = st[rr * 33 + cc];
            }
            __syncthreads();
        }
    }
    __syncthreads();
    if (wid == 0) {
        tc_relinquish();
        tc_dealloc(tmem, 512);
    }
#endif
}

// ---------------------------------------------------------------------------
// fp32 -> bf16 hi/lo split kernels
// ---------------------------------------------------------------------------
__global__ void split_cols(const float *__restrict__ src, int ldsrc, int col0,
                           int cols4, __nv_bfloat16 *__restrict__ hi,
                           __nv_bfloat16 *__restrict__ lo)
{
    int idx = blockIdx.x * blockDim.x + threadIdx.x;
    int r = idx / cols4, c = idx - r * cols4;
    float4 v = *(const float4 *)(src + (size_t)r * ldsrc + col0 + c * 4);
    uint2 h, l;
    split4_fast(v, h, l);
    *(uint2 *)(hi + (size_t)idx * 4) = h;
    *(uint2 *)(lo + (size_t)idx * 4) = l;
}

// enc_W[hid] [2000,128] -> wT hi/lo [128,2048], coalesced via smem transpose
__global__ void wT_split(const float *__restrict__ W, const int *__restrict__ hid,
                         __nv_bfloat16 *__restrict__ hi, __nv_bfloat16 *__restrict__ lo)
{
    __shared__ float t[32][33];
    int r0 = blockIdx.x * 32;   // k rows: 64 blocks cover 0..2047
    int c0 = blockIdx.y * 32;   // out cols: 4 blocks cover 0..127
    int tx = threadIdx.x, ty = threadIdx.y;  // 32 x 8
    const float *Wh = W + (size_t)hid[0] * NINP * HDIM;
#pragma unroll
    for (int i = 0; i < 4; ++i) {
        int r = r0 + ty + i * 8;
        t[ty + i * 8][tx] = (r < NINP) ? Wh[(size_t)r * HDIM + c0 + tx] : 0.f;
    }
    __syncthreads();
#pragma unroll
    for (int i = 0; i < 4; ++i) {
        int c = ty + i * 8;                  // local col
        float v = t[tx][c];                  // = W[r0+tx][c0+c]
        __nv_bfloat16 h, l;
        split1(v, h, l);
        size_t o = (size_t)(c0 + c) * KPAD + r0 + tx;
        hi[o] = h;
        lo[o] = l;
    }
}

__global__ void transpose_split(const float *__restrict__ src, int ldsrc, int col0,
                                __nv_bfloat16 *__restrict__ hi,
                                __nv_bfloat16 *__restrict__ lo)
{
    __shared__ float t[32][33];
    int r0 = blockIdx.x * 32, c0 = blockIdx.y * 32;
    int tx = threadIdx.x, ty = threadIdx.y;  // 32 x 8
#pragma unroll
    for (int i = 0; i < 4; ++i) {
        int r = ty + i * 8;
        t[r][tx] = src[(size_t)(r0 + r) * ldsrc + col0 + c0 + tx];
    }
    __syncthreads();
#pragma unroll
    for (int i = 0; i < 4; ++i) {
        int c = ty + i * 8;
        float v = t[tx][c];
        __nv_bfloat16 h, l;
        split1(v, h, l);
        size_t o = (size_t)(c0 + c) * NCELL + r0 + tx;
        hi[o] = h;
        lo[o] = l;
    }
}

// ---------------------------------------------------------------------------
// gemm_small v3: one-shot staging. C[64,128-ntile] = bnrelu(A)@B (+bias).
// Whole B panel (128x128) + A tile (64x128) staged once; single barrier;
// straight-line K=128 loop. ~100KB dyn smem -> 2 CTAs/SM.
//   smem layout (floats): As[64][132] @0 ; Bs[128][132] @8448 ; bnS @25344 ; bnB @25472
// ---------------------------------------------------------------------------
#define GS_AS   0
#define GS_BS   8448        // 64*132
#define GS_BNS  25344       // 8448 + 128*132
#define GS_BNB  25472
#define GS_SMEM ((25472 + 128) * 4)

template <bool BNA, bool STATS>
__global__ void __launch_bounds__(256)
gemm_small(const float *__restrict__ A, const float *__restrict__ B,
           float *__restrict__ C, int ldb, int ldc,
           const float *__restrict__ bias,
           const float *__restrict__ statsIn,
           const float *__restrict__ g, const float *__restrict__ be,
           const int *__restrict__ hid, int hstride,
           float *__restrict__ statsOut)
{
    extern __shared__ float smf[];
    float *As  = smf + GS_AS;    // [64][132] row-major (m, k)
    float *Bs  = smf + GS_BS;    // [128][132] row-major (k, n)
    float *bnS = smf + GS_BNS;
    float *bnB = smf + GS_BNB;
    const uint32_t sb = cvta_smem(smf);

    const int tid = threadIdx.x;
    const int tx = tid & 15;
    const int ty = tid >> 4;
    const int m0 = blockIdx.x * 64;
    const int n0 = blockIdx.y * 128;

    // stage A (2048 float4) + B (4096 float4) in one cp.async burst
#pragma unroll
    for (int j = 0; j < 8; ++j) {
        int e = j * 256 + tid;
        int m = e >> 5, c = e & 31;
        cpa16(sb + GS_AS * 4 + (uint32_t)(m * 528 + c * 16),
              A + (size_t)(m0 + m) * HDIM + c * 4);
    }
#pragma unroll
    for (int j = 0; j < 16; ++j) {
        int e = j * 256 + tid;
        int k = e >> 5, c = e & 31;
        cpa16(sb + GS_BS * 4 + (uint32_t)(k * 528 + c * 16),
              B + (size_t)k * ldb + n0 + c * 4);
    }
    cpa_commit();

    if (BNA && tid < 128) {
        float s1 = statsIn[tid], s2 = statsIn[128 + tid];
        float mean = s1 * (1.f / (float)NCELL);
        float var = s2 * (1.f / (float)NCELL) - mean * mean;
        float rstd = rsqrtf(var + BN_EPS);
        int off = hid ? hid[0] * hstride : 0;
        float gg = g[off + tid];
        bnS[tid] = gg * rstd;
        bnB[tid] = be[off + tid] - gg * mean * rstd;
    }
    cpa_wait<0>();
    __syncthreads();

    // BN + ReLU applied in place on staged A
    if (BNA) {
#pragma unroll
        for (int j = 0; j < 32; ++j) {
            int e = j * 256 + tid;
            int m = e >> 7, k = e & 127;
            float v = As[m * 132 + k];
            As[m * 132 + k] = fmaxf(fmaf(v, bnS[k], bnB[k]), 0.f);
        }
        __syncthreads();
    }

    float2 acc[4][4];
#pragma unroll
    for (int i = 0; i < 4; ++i)
#pragma unroll
        for (int j = 0; j < 4; ++j) acc[i][j] = make_float2(0.f, 0.f);

    const float *arow0 = As + (ty * 4 + 0) * 132;
    const float *arow1 = As + (ty * 4 + 1) * 132;
    const float *arow2 = As + (ty * 4 + 2) * 132;
    const float *arow3 = As + (ty * 4 + 3) * 132;

#pragma unroll 16
    for (int kk = 0; kk < HDIM; ++kk) {
        float4 b0 = *(const float4 *)&Bs[kk * 132 + tx * 4];
        float4 b1 = *(const float4 *)&Bs[kk * 132 + 64 + tx * 4];
        float2 bp[4] = {make_float2(b0.x, b0.y), make_float2(b0.z, b0.w),
                        make_float2(b1.x, b1.y), make_float2(b1.z, b1.w)};
        float av[4] = {arow0[kk], arow1[kk], arow2[kk], arow3[kk]};
#pragma unroll
        for (int i = 0; i < 4; ++i) {
            float2 aa = make_float2(av[i], av[i]);
#pragma unroll
            for (int j = 0; j < 4; ++j) fma2(acc[i][j], aa, bp[j]);
        }
    }

    float bad0[4] = {0.f, 0.f, 0.f, 0.f}, bad1[4] = {0.f, 0.f, 0.f, 0.f};
    if (bias != nullptr) {
#pragma unroll
        for (int j = 0; j < 4; ++j) {
            bad0[j] = bias[n0 + tx * 4 + j];
            bad1[j] = bias[n0 + 64 + tx * 4 + j];
        }
    }

    float cs[8], cq[8];
#pragma unroll
    for (int j = 0; j < 8; ++j) { cs[j] = 0.f; cq[j] = 0.f; }

#pragma unroll
    for (int i = 0; i < 4; ++i) {
        int r = m0 + ty * 4 + i;
        float v[8] = {acc[i][0].x, acc[i][0].y, acc[i][1].x, acc[i][1].y,
                      acc[i][2].x, acc[i][2].y, acc[i][3].x, acc[i][3].y};
        float w[8];
#pragma unroll
        for (int j = 0; j < 4; ++j) { w[j] = v[j] + bad0[j]; w[4 + j] = v[4 + j] + bad1[j]; }
        if (STATS) {
#pragma unroll
            for (int j = 0; j < 8; ++j) { cs[j] += w[j]; cq[j] += w[j] * w[j]; }
        }
        float *crow = C + (size_t)r * ldc;
        *(float4 *)(crow + n0 + tx * 4)      = make_float4(w[0], w[1], w[2], w[3]);
        *(float4 *)(crow + n0 + 64 + tx * 4) = make_float4(w[4], w[5], w[6], w[7]);
    }

    if (STATS) {
        __syncthreads();
        float *sred = As;     // reuse
        if (tid < 128) { sred[tid] = 0.f; sred[128 + tid] = 0.f; }
        __syncthreads();
#pragma unroll
        for (int j = 0; j < 8; ++j) {
            int col = (j < 4) ? (tx * 4 + j) : (64 + tx * 4 + (j - 4));
            atomicAdd(&sred[col], cs[j]);
            atomicAdd(&sred[128 + col], cq[j]);
        }
        __syncthreads();
        if (tid < 128) {
            atomicAdd(statsOut + tid, sred[tid]);
            atomicAdd(statsOut + 128 + tid, sred[128 + tid]);
        }
    }
}

// ---------------------------------------------------------------------------
// BatchNorm stats (enc output only)
// ---------------------------------------------------------------------------
__global__ void bn_stats(const float *__restrict__ h, float *__restrict__ stats)
{
    int col = threadIdx.x;
    int r0 = blockIdx.x * 32;
    float s = 0.f, s2 = 0.f;
#pragma unroll 8
    for (int r = 0; r < 32; ++r) {
        float v = h[(size_t)(r0 + r) * HDIM + col];
        s += v; s2 += v * v;
    }
    atomicAdd(&stats[col], s);
    atomicAdd(&stats[128 + col], s2);
}

// ---------------------------------------------------------------------------
// Row softmax in place
// ---------------------------------------------------------------------------
__global__ void softmax_row(float *__restrict__ attn)
{
    extern __shared__ float row[];
    __shared__ float red[256];
    const int t = threadIdx.x;
    float *p = attn + (size_t)blockIdx.x * NCELL;

    float m = -1e30f;
    for (int i = t; i < NCELL / 4; i += 256) {
        float4 v = ((const float4 *)p)[i];
        ((float4 *)row)[i] = v;
        m = fmaxf(m, fmaxf(fmaxf(v.x, v.y), fmaxf(v.z, v.w)));
    }
    red[t] = m; __syncthreads();
    for (int s = 128; s > 0; s >>= 1) {
        if (t < s) red[t] = fmaxf(red[t], red[t + s]);
        __syncthreads();
    }
    const float bmax = red[0];
    __syncthreads();

    float sum = 0.f;
    for (int i = t; i < NCELL / 4; i += 256) {
        float4 v = ((float4 *)row)[i];
        v.x = __expf(v.x - bmax); v.y = __expf(v.y - bmax);
        v.z = __expf(v.z - bmax); v.w = __expf(v.w - bmax);
        sum += v.x + v.y + v.z + v.w;
        ((float4 *)row)[i] = v;
    }
    red[t] = sum; __syncthreads();
    for (int s = 128; s > 0; s >>= 1) {
        if (t < s) red[t] += red[t + s];
        __syncthreads();
    }
    const float inv = 1.f / red[0];
    __syncthreads();

    for (int i = t; i < NCELL / 4; i += 256) {
        float4 v = ((float4 *)row)[i];
        v.x *= inv; v.y *= inv; v.z *= inv; v.w *= inv;
        ((float4 *)p)[i] = v;
    }
}

// ---------------------------------------------------------------------------
// Variational heads
// ---------------------------------------------------------------------------
__global__ void heads_kernel(const float *__restrict__ o,
                             const float *__restrict__ mW, const float *__restrict__ mb,
                             const float *__restrict__ vW, const float *__restrict__ vb,
                             const float *__restrict__ eps,
                             float *__restrict__ qm, float *__restrict__ qv,
                             float *__restrict__ lat)
{
    extern __shared__ float smh[];
    float *Wm  = smh;
    float *Wv  = smh + 4096;
    float *osm = smh + 8192;
    const int t = threadIdx.x;
    const int r0 = blockIdx.x * 128;

    for (int i = t; i < HDIM * NOUTD; i += 256) { Wm[i] = mW[i]; Wv[i] = vW[i]; }
    for (int i = t; i < 128 * HDIM; i += 256) {
        int r = i >> 7, c = i & 127;
        osm[r * 129 + c] = o[(size_t)(r0 + r) * HDIM + c];
    }
    __syncthreads();

    for (int idx = t; idx < 128 * NOUTD; idx += 256) {
        int r = idx >> 5, c = idx & 31;
        const float *orow = &osm[r * 129];
        float dm = 0.f, dv = 0.f;
#pragma unroll 8
        for (int k = 0; k < HDIM; ++k) {
            float ov = orow[k];
            dm += ov * Wm[k * NOUTD + c];
            dv += ov * Wv[k * NOUTD + c];
        }
        int R = r0 + r;
        float mval = dm + mb[c];
        float vval = __expf(dv + vb[c]);
        qm[R * NOUTD + c]  = mval;
        qv[R * NOUTD + c]  = vval;
        lat[R * NOUTD + c] = mval + sqrtf(vval) * eps[R * NOUTD + c];
    }
}

// ---------------------------------------------------------------------------
// Launch
// ---------------------------------------------------------------------------
extern "C" void kernel_launch(void *const *d_in, const int *in_sizes, int n_in,
                              void *d_out, int out_size)
{
    const float *x       = (const float *)d_in[0];
    const float *spatial = (const float *)d_in[1];
    const float *eps     = (const float *)d_in[2];
    const float *enc_W   = (const float *)d_in[3];
    const float *enc_g   = (const float *)d_in[5];
    const float *enc_be  = (const float *)d_in[6];
    const float *sh_W1   = (const float *)d_in[7];
    const float *sh_g1   = (const float *)d_in[9];
    const float *sh_be1  = (const float *)d_in[10];
    const float *sh_W2   = (const float *)d_in[11];
    const float *sh_g2   = (const float *)d_in[13];
    const float *sh_be2  = (const float *)d_in[14];
    const float *qkv_W   = (const float *)d_in[15];
    const float *qkv_b   = (const float *)d_in[16];
    const float *o_W     = (const float *)d_in[17];
    const float *o_b     = (const float *)d_in[18];
    const float *mean_W  = (const float *)d_in[19];
    const float *mean_b  = (const float *)d_in[20];
    const float *var_W   = (const float *)d_in[21];
    const float *var_b   = (const float *)d_in[22];
    const int   *hid     = (const int *)d_in[23];

    float *out = (float *)d_out;
    float *out_qm   = out;
    float *out_qv   = out + (size_t)NCELL * NOUTD;
    float *out_lat  = out + 2 * (size_t)NCELL * NOUTD;
    float *out_attn = out + 3 * (size_t)NCELL * NOUTD;

    float *bufA, *bufB, *qkv, *kagg, *stats;
    __nv_bfloat16 *q_hi, *q_lo, *ka_hi, *ka_lo;
    __nv_bfloat16 *kT_hi, *kT_lo, *vT_hi, *vT_lo, *wT_hi, *wT_lo;
    cudaGetSymbolAddress((void **)&bufA, g_bufA);
    cudaGetSymbolAddress((void **)&bufB, g_bufB);
    cudaGetSymbolAddress((void **)&qkv,  g_qkv);
    cudaGetSymbolAddress((void **)&kagg, g_kagg);
    cudaGetSymbolAddress((void **)&stats, g_stats);
    cudaGetSymbolAddress((void **)&q_hi, g_q_hi);
    cudaGetSymbolAddress((void **)&q_lo, g_q_lo);
    cudaGetSymbolAddress((void **)&ka_hi, g_ka_hi);
    cudaGetSymbolAddress((void **)&ka_lo, g_ka_lo);
    cudaGetSymbolAddress((void **)&kT_hi, g_kT_hi);
    cudaGetSymbolAddress((void **)&kT_lo, g_kT_lo);
    cudaGetSymbolAddress((void **)&vT_hi, g_vT_hi);
    cudaGetSymbolAddress((void **)&vT_lo, g_vT_lo);
    cudaGetSymbolAddress((void **)&wT_hi, g_wT_hi);
    cudaGetSymbolAddress((void **)&wT_lo, g_wT_lo);

    cudaFuncSetAttribute(tc_skinny_f32, cudaFuncAttributeMaxDynamicSharedMemorySize, SKF_SMEM);
    cudaFuncSetAttribute(tc_wide,       cudaFuncAttributeMaxDynamicSharedMemorySize, WIDE_SMEM);
    cudaFuncSetAttribute((const void *)gemm_small<true, true>,
                         cudaFuncAttributeMaxDynamicSharedMemorySize, GS_SMEM);
    cudaFuncSetAttribute((const void *)gemm_small<true, false>,
                         cudaFuncAttributeMaxDynamicSharedMemorySize, GS_SMEM);
    cudaFuncSetAttribute((const void *)gemm_small<false, false>,
                         cudaFuncAttributeMaxDynamicSharedMemorySize, GS_SMEM);

    const size_t NH_BYTES = (size_t)NCELL * HDIM * sizeof(float);
    const float SCALE = 0.08838834764831845f; // 1/sqrt(128)
    float *slot0 = stats, *slot1 = stats + 256, *slot2 = stats + 512;

    cudaMemsetAsync(stats, 0, 768 * sizeof(float));

    // 1. encoder: h = x @ enc_W[hid]
    wT_split<<<dim3(64, 4), dim3(32, 8)>>>(enc_W, hid, wT_hi, wT_lo);
    cudaMemsetAsync(bufA, 0, NH_BYTES);
    tc_skinny_f32<<<dim3(64, 1, 4), 128, SKF_SMEM>>>(
        x, NINP, NINP, wT_hi, wT_lo, KPAD, bufA, HDIM, 512, 1.f);
    bn_stats<<<256, 128>>>(bufA, slot0);

    // 2. sh1 = BN1(bufA) @ W1 ; stats -> slot1
    gemm_small<true, true><<<dim3(128, 1), 256, GS_SMEM>>>(
        bufA, sh_W1, bufB, HDIM, HDIM, nullptr,
        slot0, enc_g, enc_be, hid, HDIM, slot1);

    // 3. sh2 = BN2(bufB) @ W2 ; stats -> slot2
    gemm_small<true, true><<<dim3(128, 1), 256, GS_SMEM>>>(
        bufB, sh_W2, bufA, HDIM, HDIM, nullptr,
        slot1, sh_g1, sh_be1, nullptr, 0, slot2);

    // 4. qkv = BN3(bufA) @ qkv_W + qkv_b
    gemm_small<true, false><<<dim3(128, 3), 256, GS_SMEM>>>(
        bufA, qkv_W, qkv, 3 * HDIM, 3 * HDIM, qkv_b,
        slot2, sh_g2, sh_be2, nullptr, 0, nullptr);

    // 5. small bf16 conversions (q, kT, vT)
    split_cols<<<1024, 256>>>(qkv, 3 * HDIM, 0, HDIM / 4, q_hi, q_lo);
    transpose_split<<<dim3(256, 4), dim3(32, 8)>>>(qkv, 3 * HDIM, HDIM, kT_hi, kT_lo);
    transpose_split<<<dim3(256, 4), dim3(32, 8)>>>(qkv, 3 * HDIM, 2 * HDIM, vT_hi, vT_lo);

    // 6. k_agg = spatial @ k   (split-K = 4)
    cudaMemsetAsync(kagg, 0, NH_BYTES);
    tc_skinny_f32<<<dim3(64, 1, 4), 128, SKF_SMEM>>>(
        spatial, NCELL, NCELL, kT_hi, kT_lo, NCELL, kagg, HDIM, 2048, 1.f);
    split_cols<<<1024, 256>>>(kagg, HDIM, 0, HDIM / 4, ka_hi, ka_lo);

    // 7. logits = (q @ k_agg^T) / sqrt(H)
    tc_wide<<<dim3(64, 16), 128, WIDE_SMEM>>>(q_hi, q_lo, ka_hi, ka_lo, out_attn, SCALE);

    // 8. softmax in place
    softmax_row<<<NCELL, 256, NCELL * sizeof(float)>>>(out_attn);

    // 9. av = attn @ v   (split-K = 4)
    cudaMemsetAsync(bufA, 0, NH_BYTES);
    tc_skinny_f32<<<dim3(64, 1, 4), 128, SKF_SMEM>>>(
        out_attn, NCELL, NCELL, vT_hi, vT_lo, NCELL, bufA, HDIM, 2048, 1.f);

    // 10. o = av @ o_W + o_b
    gemm_small<false, false><<<dim3(128, 1), 256, GS_SMEM>>>(
        bufA, o_W, bufB, HDIM, HDIM, o_b,
        nullptr, nullptr, nullptr, nullptr, 0, nullptr);

    // 11. variational heads
    const int heads_smem = (4096 + 4096 + 128 * 129) * sizeof(float);
    cudaFuncSetAttribute(heads_kernel, cudaFuncAttributeMaxDynamicSharedMemorySize,
                         heads_smem);
    heads_kernel<<<64, 256, heads_smem>>>(bufB, mean_W, mean_b, var_W, var_b,
                                          eps, out_qm, out_qv, out_lat);
}

// round 11
// speedup vs baseline: 1.4075x; 1.0420x over previous
#include <cuda_runtime.h>
#include <cuda_bf16.h>
#include <math.h>
#include <stdint.h>

#define NCELL 8192
#define NINP  2000
#define KPAD  2048
#define HDIM  128
#define NOUTD 32
#define BN_EPS 1e-3f

#if defined(__CUDA_ARCH_FEAT_SM103_ALL) || defined(__CUDA_ARCH_FEAT_SM100_ALL) || \
    defined(__CUDA_ARCH_FEAT_SM110_ALL) || defined(__CUDA_ARCH_FEAT_SM101_ALL)
#define TC_ENABLED 1
#else
#define TC_ENABLED 0
#endif

// ---------------------------------------------------------------------------
// Scratch
// ---------------------------------------------------------------------------
__device__ __align__(256) float g_bufA[NCELL * HDIM];
__device__ __align__(256) float g_bufB[NCELL * HDIM];
__device__ __align__(256) float g_qkv [NCELL * 3 * HDIM];
__device__ __align__(256) float g_kagg[NCELL * HDIM];
__device__ __align__(256) float g_stats[768];
__device__ __align__(256) unsigned long long g_rowstats[NCELL];  // (max, sumexp) per row

__device__ __align__(256) __nv_bfloat16 g_q_hi [NCELL * HDIM];
__device__ __align__(256) __nv_bfloat16 g_q_lo [NCELL * HDIM];
__device__ __align__(256) __nv_bfloat16 g_ka_hi[NCELL * HDIM];
__device__ __align__(256) __nv_bfloat16 g_ka_lo[NCELL * HDIM];
__device__ __align__(256) __nv_bfloat16 g_kT_hi[HDIM * NCELL];
__device__ __align__(256) __nv_bfloat16 g_kT_lo[HDIM * NCELL];
__device__ __align__(256) __nv_bfloat16 g_vT_hi[HDIM * NCELL];
__device__ __align__(256) __nv_bfloat16 g_vT_lo[HDIM * NCELL];
__device__ __align__(256) __nv_bfloat16 g_wT_hi[HDIM * KPAD];
__device__ __align__(256) __nv_bfloat16 g_wT_lo[HDIM * KPAD];

// ---------------------------------------------------------------------------
// PTX helpers
// ---------------------------------------------------------------------------
__device__ __forceinline__ uint32_t cvta_smem(const void *p) {
    uint32_t a;
    asm("{ .reg .u64 t; cvta.to.shared.u64 t, %1; cvt.u32.u64 %0, t; }"
        : "=r"(a) : "l"(p));
    return a;
}
__device__ __forceinline__ uint32_t elect_one() {
    uint32_t p;
    asm volatile("{ .reg .pred p; elect.sync _|p, 0xFFFFFFFF; selp.b32 %0, 1, 0, p; }"
                 : "=r"(p));
    return p;
}
__device__ __forceinline__ void mbar_init(uint32_t mbar, uint32_t cnt) {
    asm volatile("mbarrier.init.shared.b64 [%0], %1;"
                 :: "r"(mbar), "r"(cnt) : "memory");
}
__device__ __forceinline__ void mbar_wait(uint32_t mbar, uint32_t parity) {
    asm volatile(
        "{\n\t.reg .pred P;\n"
        "LW_%=:\n\t"
        "mbarrier.try_wait.parity.acquire.cta.shared::cta.b64 P, [%0], %1, 0x989680;\n\t"
        "@P bra LD_%=;\n\t"
        "bra LW_%=;\n"
        "LD_%=:\n\t}"
        :: "r"(mbar), "r"(parity) : "memory");
}
__device__ __forceinline__ void fence_async_smem() {
    asm volatile("fence.proxy.async.shared::cta;" ::: "memory");
}
__device__ __forceinline__ void cpa16(uint32_t dst, const void *src) {
    asm volatile("cp.async.cg.shared.global [%0], [%1], 16;"
                 :: "r"(dst), "l"(src) : "memory");
}
__device__ __forceinline__ void cpa_commit() {
    asm volatile("cp.async.commit_group;" ::: "memory");
}
template <int N>
__device__ __forceinline__ void cpa_wait() {
    asm volatile("cp.async.wait_group %0;" :: "n"(N) : "memory");
}
__device__ __forceinline__ void red4(float *p, float a, float b, float c, float d) {
    asm volatile("red.global.add.v4.f32 [%0], {%1, %2, %3, %4};"
                 :: "l"(p), "f"(a), "f"(b), "f"(c), "f"(d) : "memory");
}

// ---- tcgen05 ----
__device__ __forceinline__ void tc_alloc(uint32_t smem_dst, uint32_t ncols) {
    asm volatile("tcgen05.alloc.cta_group::1.sync.aligned.shared::cta.b32 [%0], %1;"
                 :: "r"(smem_dst), "r"(ncols) : "memory");
}
__device__ __forceinline__ void tc_dealloc(uint32_t tmem, uint32_t ncols) {
    asm volatile("tcgen05.dealloc.cta_group::1.sync.aligned.b32 %0, %1;"
                 :: "r"(tmem), "r"(ncols));
}
__device__ __forceinline__ void tc_relinquish() {
    asm volatile("tcgen05.relinquish_alloc_permit.cta_group::1.sync.aligned;");
}
__device__ __forceinline__ void tc_commit(uint32_t mbar) {
    asm volatile("tcgen05.commit.cta_group::1.mbarrier::arrive::one.shared::cluster.b64 [%0];"
                 :: "r"(mbar) : "memory");
}
__device__ __forceinline__ void tc_fence_after() {
    asm volatile("tcgen05.fence::after_thread_sync;" ::: "memory");
}
__device__ __forceinline__ void tc_wait_ld() {
    asm volatile("tcgen05.wait::ld.sync.aligned;" ::: "memory");
}
__device__ __forceinline__ void ldtm32(uint32_t *r, uint32_t addr) {
    asm volatile(
        "tcgen05.ld.sync.aligned.32x32b.x32.b32 "
        "{%0, %1, %2, %3, %4, %5, %6, %7, "
        " %8, %9, %10, %11, %12, %13, %14, %15, "
        " %16, %17, %18, %19, %20, %21, %22, %23, "
        " %24, %25, %26, %27, %28, %29, %30, %31}, [%32];"
        : "=r"(r[0]),  "=r"(r[1]),  "=r"(r[2]),  "=r"(r[3]),
          "=r"(r[4]),  "=r"(r[5]),  "=r"(r[6]),  "=r"(r[7]),
          "=r"(r[8]),  "=r"(r[9]),  "=r"(r[10]), "=r"(r[11]),
          "=r"(r[12]), "=r"(r[13]), "=r"(r[14]), "=r"(r[15]),
          "=r"(r[16]), "=r"(r[17]), "=r"(r[18]), "=r"(r[19]),
          "=r"(r[20]), "=r"(r[21]), "=r"(r[22]), "=r"(r[23]),
          "=r"(r[24]), "=r"(r[25]), "=r"(r[26]), "=r"(r[27]),
          "=r"(r[28]), "=r"(r[29]), "=r"(r[30]), "=r"(r[31])
        : "r"(addr));
}
__device__ __forceinline__ void mma_f16_ss(uint32_t d, uint64_t a_desc,
                                           uint64_t b_desc, uint32_t idesc,
                                           uint32_t en) {
    asm volatile(
        "{\n\t.reg .pred p;\n\t"
        "setp.ne.u32 p, %5, 0;\n\t"
        "tcgen05.mma.cta_group::1.kind::f16 [%0], %1, %2, %3, {%4, %4, %4, %4}, p;\n\t}"
        :: "r"(d), "l"(a_desc), "l"(b_desc), "r"(idesc), "r"(0u), "r"(en)
        : "memory");
}
__device__ __forceinline__ uint64_t make_desc(uint32_t addr) {
    return ((uint64_t)2 << 61) | ((uint64_t)1 << 46) | ((uint64_t)64 << 32) |
           ((uint64_t)1 << 16) | (((uint64_t)(addr >> 4)) & 0x3FFF);
}
__device__ __forceinline__ void fma2(float2 &c, const float2 &a, const float2 &b) {
    unsigned long long       &cc = reinterpret_cast<unsigned long long &>(c);
    const unsigned long long &aa = reinterpret_cast<const unsigned long long &>(a);
    const unsigned long long &bb = reinterpret_cast<const unsigned long long &>(b);
    asm("fma.rn.f32x2 %0, %1, %2, %0;" : "+l"(cc) : "l"(aa), "l"(bb));
}
__device__ __forceinline__ void split1(float v, __nv_bfloat16 &h, __nv_bfloat16 &l) {
    h = __float2bfloat16(v);
    l = __float2bfloat16(v - __bfloat162float(h));
}
__device__ __forceinline__ void split4_fast(float4 v, uint2 &hi, uint2 &lo) {
    uint32_t h01, h23, l01, l23;
    asm("cvt.rn.bf16x2.f32 %0, %1, %2;" : "=r"(h01) : "f"(v.y), "f"(v.x));
    asm("cvt.rn.bf16x2.f32 %0, %1, %2;" : "=r"(h23) : "f"(v.w), "f"(v.z));
    float r0 = v.x - __uint_as_float(h01 << 16);
    float r1 = v.y - __uint_as_float(h01 & 0xFFFF0000u);
    float r2 = v.z - __uint_as_float(h23 << 16);
    float r3 = v.w - __uint_as_float(h23 & 0xFFFF0000u);
    asm("cvt.rn.bf16x2.f32 %0, %1, %2;" : "=r"(l01) : "f"(r1), "f"(r0));
    asm("cvt.rn.bf16x2.f32 %0, %1, %2;" : "=r"(l23) : "f"(r3), "f"(r2));
    hi = make_uint2(h01, h23);
    lo = make_uint2(l01, l23);
}
// online (max,sumexp) merge into global ull-packed float2
__device__ __forceinline__ void merge_stats(unsigned long long *addr, float m2, float s2) {
    unsigned long long old = *addr, assumed;
    do {
        assumed = old;
        float2 cur = *(float2 *)&assumed;
        float mn = fmaxf(cur.x, m2);
        float sn = cur.y * __expf(cur.x - mn) + s2 * __expf(m2 - mn);
        float2 nf = make_float2(mn, sn);
        old = atomicCAS(addr, assumed, *(unsigned long long *)&nf);
    } while (old != assumed);
}

static constexpr uint32_t TC_IDESC = 0x8200490u;

__device__ __forceinline__ uint32_t sw32(int r, int ch) {
    uint32_t byte = ((r >> 3) + (ch >> 3) * 16) * 1024 + (r & 7) * 128 + (ch & 7) * 16;
    return byte ^ ((byte >> 3) & 0x70);
}

// ---------------------------------------------------------------------------
// tc_skinny_f32<SMAX>: C += f(A_f32) @ (Bhi+Blo)^T
// SMAX: f(v) = exp(v - rowmax)*inv_sum, and f(v) written back to A in place
// (normalized attention). The transform runs in the MMA-overlap window.
// ---------------------------------------------------------------------------
#define SKF_SMEM (1024 + 2 * 65536)

template <bool SMAX>
__global__ void __launch_bounds__(128)
tc_skinny_f32(float *__restrict__ A, int lda, int Kvalid,
              const __nv_bfloat16 *__restrict__ Bhi,
              const __nv_bfloat16 *__restrict__ Blo, int ldb,
              float *__restrict__ C, int ldc, int kpc, float alpha,
              const unsigned long long *__restrict__ rowstats)
{
#if TC_ENABLED
    extern __shared__ char sm[];
    const uint32_t sb = cvta_smem(sm);
    const int tid = threadIdx.x;
    const int wid = tid >> 5;

    if (wid == 0) tc_alloc(sb, 128);
    if (tid == 64) mbar_init(sb + 8, 1);
    __syncthreads();
    uint32_t tmem;
    asm volatile("ld.shared.b32 %0, [%1];" : "=r"(tmem) : "r"(sb));

    const int m0 = blockIdx.x * 128;
    const int kb0 = blockIdx.z * kpc;
    const int S = kpc >> 6;

    const int aRow = tid >> 4;
    const int aCol = (tid & 15) * 4;
    float *aBase = A + (size_t)(m0 + aRow) * lda + aCol;
    const size_t aRowStep = (size_t)8 * lda;
    const uint32_t toffA = (uint32_t)(((tid >> 4) * 128 + (tid & 15) * 8) ^ ((tid >> 4) << 4));
    const int bRow = tid >> 3;
    const int bCol = (tid & 7) * 8;
    const uint32_t toffB = (uint32_t)((((tid >> 3) & 7) * 128 + (tid & 7) * 16) ^
                                      ((((tid >> 3) & 7) << 4)));
    const uint32_t bAtom = (uint32_t)(tid >> 6) * 1024;

    float4 regs[16];
    float rmax[16], rinv[16];
    if (SMAX) {
#pragma unroll
        for (int i = 0; i < 16; ++i) {
            unsigned long long u = rowstats[m0 + aRow + i * 8];
            float2 st = *(float2 *)&u;
            rmax[i] = st.x;
            rinv[i] = 1.f / st.y;
        }
    }

    auto ldA = [&](int s) {
        const int kb = kb0 + s * 64;
        const bool ok = (kb + aCol) < Kvalid;
        const float *p = aBase + kb;
#pragma unroll
        for (int i = 0; i < 16; ++i) {
            regs[i] = ok ? *(const float4 *)(p + i * aRowStep)
                         : make_float4(0.f, 0.f, 0.f, 0.f);
        }
    };
    // softmax transform + in-place normalized store (overlaps MMA)
    auto xform = [&](int s) {
        if (!SMAX) return;
        const int kb = kb0 + s * 64;
        float *p = aBase + kb;
#pragma unroll
        for (int i = 0; i < 16; ++i) {
            float4 v = regs[i];
            v.x = __expf(v.x - rmax[i]) * rinv[i];
            v.y = __expf(v.y - rmax[i]) * rinv[i];
            v.z = __expf(v.z - rmax[i]) * rinv[i];
            v.w = __expf(v.w - rmax[i]) * rinv[i];
            regs[i] = v;
            *(float4 *)(p + i * aRowStep) = v;
        }
    };
    auto ldB = [&](int s) {
        const uint32_t bh = sb + 1024 + (s & 1) * 65536 + 32768;
        const int kb = kb0 + s * 64;
        const __nv_bfloat16 *ph = Bhi + (size_t)bRow * ldb + kb + bCol;
        const __nv_bfloat16 *pl = Blo + (size_t)bRow * ldb + kb + bCol;
        const uint32_t so0 = bAtom + toffB;
#pragma unroll
        for (int i = 0; i < 8; ++i) {
            uint32_t so = so0 + i * 2048;
            cpa16(bh + so,         ph + (size_t)i * 16 * ldb);
            cpa16(bh + 16384 + so, pl + (size_t)i * 16 * ldb);
        }
        cpa_commit();
    };
    auto stA = [&](int s) {
        char *ah = sm + 1024 + (s & 1) * 65536;
        char *al = ah + 16384;
#pragma unroll
        for (int i = 0; i < 16; ++i) {
            uint2 h, l;
            split4_fast(regs[i], h, l);
            uint32_t sz = toffA + i * 1024;
            *(uint2 *)(ah + sz) = h;
            *(uint2 *)(al + sz) = l;
        }
    };

    ldB(0);
    ldA(0);
    xform(0);
    uint32_t ph = 0;
    for (int s = 0; s < S; ++s) {
        cpa_wait<0>();
        stA(s);
        __syncthreads();
        fence_async_smem();
        if (wid == 0 && elect_one()) {
            const uint32_t base = sb + 1024 + (s & 1) * 65536;
            uint64_t dah = make_desc(base);
            uint64_t dal = make_desc(base + 16384);
            uint64_t dbh = make_desc(base + 32768);
            uint64_t dbl = make_desc(base + 49152);
#pragma unroll
            for (int k = 0; k < 4; ++k) {
                uint64_t off = (uint64_t)(k * 2);
                mma_f16_ss(tmem, dah + off, dbh + off, TC_IDESC, (s > 0) || (k > 0));
                mma_f16_ss(tmem, dah + off, dbl + off, TC_IDESC, 1u);
                mma_f16_ss(tmem, dal + off, dbh + off, TC_IDESC, 1u);
            }
            tc_commit(sb + 8);
        }
        if (s + 1 < S) { ldB(s + 1); ldA(s + 1); xform(s + 1); }
        mbar_wait(sb + 8, ph);
        ph ^= 1;
        __syncthreads();
    }

    tc_fence_after();
#pragma unroll
    for (int part = 0; part < 4; ++part) {
        uint32_t d[32];
        ldtm32(d, tmem + part * 32);
        tc_wait_ld();
        float *cp = C + (size_t)(m0 + tid) * ldc + part * 32;
#pragma unroll
        for (int j = 0; j < 8; ++j)
            red4(cp + j * 4,
                 __uint_as_float(d[j * 4 + 0]) * alpha,
                 __uint_as_float(d[j * 4 + 1]) * alpha,
                 __uint_as_float(d[j * 4 + 2]) * alpha,
                 __uint_as_float(d[j * 4 + 3]) * alpha);
    }
    __syncthreads();
    if (wid == 0) {
        tc_relinquish();
        tc_dealloc(tmem, 128);
    }
#endif
}

// ---------------------------------------------------------------------------
// tc_wide: logits GEMM + per-row softmax partial stats in the epilogue
// ---------------------------------------------------------------------------
#define WIDE_SMEM (1024 + 65536 + 131072)

__global__ void __launch_bounds__(128)
tc_wide(const __nv_bfloat16 *__restrict__ Ahi, const __nv_bfloat16 *__restrict__ Alo,
        const __nv_bfloat16 *__restrict__ Bhi, const __nv_bfloat16 *__restrict__ Blo,
        float *__restrict__ C, float alpha,
        unsigned long long *__restrict__ rowstats)
{
#if TC_ENABLED
    extern __shared__ char sm[];
    const uint32_t sb = cvta_smem(sm);
    const int tid = threadIdx.x;
    const int wid = tid >> 5;

    if (wid == 0) tc_alloc(sb, 512);
    if (tid == 64) mbar_init(sb + 8, 1);
    __syncthreads();
    uint32_t tmem;
    asm volatile("ld.shared.b32 %0, [%1];" : "=r"(tmem) : "r"(sb));

    const int m0 = blockIdx.x * 128;
    const int ng0 = blockIdx.y * 512;

    const uint32_t A0 = sb + 1024;
    const uint32_t A1 = A0 + 32768;

    auto load_B = [&](int n) {
        const uint32_t base = sb + 1024 + 65536 + (n & 1) * 65536;
        const int r0 = ng0 + n * 128;
#pragma unroll
        for (int i = tid; i < 2048; i += 128) {
            int r = i >> 4, ch = i & 15;
            uint32_t so = sw32(r, ch);
            cpa16(base + so,         Bhi + (size_t)(r0 + r) * HDIM + ch * 8);
            cpa16(base + 32768 + so, Blo + (size_t)(r0 + r) * HDIM + ch * 8);
        }
        cpa_commit();
    };

#pragma unroll
    for (int i = tid; i < 2048; i += 128) {
        int r = i >> 4, ch = i & 15;
        uint32_t so = sw32(r, ch);
        cpa16(A0 + so, Ahi + (size_t)(m0 + r) * HDIM + ch * 8);
        cpa16(A1 + so, Alo + (size_t)(m0 + r) * HDIM + ch * 8);
    }
    {
        const uint32_t base = sb + 1024 + 65536;
#pragma unroll
        for (int i = tid; i < 2048; i += 128) {
            int r = i >> 4, ch = i & 15;
            uint32_t so = sw32(r, ch);
            cpa16(base + so,         Bhi + (size_t)(ng0 + r) * HDIM + ch * 8);
            cpa16(base + 32768 + so, Blo + (size_t)(ng0 + r) * HDIM + ch * 8);
        }
    }
    cpa_commit();

    uint32_t ph = 0;
    for (int n = 0; n < 4; ++n) {
        if (n + 1 < 4) { load_B(n + 1); cpa_wait<1>(); }
        else           { cpa_wait<0>(); }
        __syncthreads();
        fence_async_smem();
        if (wid == 0 && elect_one()) {
            const uint32_t bbase = sb + 1024 + 65536 + (n & 1) * 65536;
            uint64_t dah = make_desc(A0);
            uint64_t dal = make_desc(A1);
            uint64_t dbh = make_desc(bbase);
            uint64_t dbl = make_desc(bbase + 32768);
            const uint32_t acc = tmem + n * 128;
#pragma unroll
            for (int k = 0; k < 8; ++k) {
                uint64_t off = (uint64_t)((k & 3) * 2 + (k >> 2) * 1024);
                mma_f16_ss(acc, dah + off, dbh + off, TC_IDESC, k > 0);
                mma_f16_ss(acc, dah + off, dbl + off, TC_IDESC, 1u);
                mma_f16_ss(acc, dal + off, dbh + off, TC_IDESC, 1u);
            }
            tc_commit(sb + 8);
        }
        mbar_wait(sb + 8, ph);
        ph ^= 1;
        __syncthreads();
    }

    // epilogue: store logits + accumulate per-row (max, sumexp) partials
    tc_fence_after();
    float *st = (float *)(sm + 1024);
    float mloc = -1e30f, sloc = 0.f;
    for (int n = 0; n < 4; ++n) {
#pragma unroll
        for (int part = 0; part < 4; ++part) {
            uint32_t d[32];
            ldtm32(d, tmem + n * 128 + part * 32);
            tc_wait_ld();
            float v[32];
            float mb = -1e30f;
#pragma unroll
            for (int c = 0; c < 32; ++c) {
                v[c] = __uint_as_float(d[c]) * alpha;
                mb = fmaxf(mb, v[c]);
            }
            float sb2 = 0.f;
#pragma unroll
            for (int c = 0; c < 32; ++c) {
                sb2 += __expf(v[c] - mb);
                st[tid * 33 + c] = v[c];
            }
            // merge batch stats into running
            float mn = fmaxf(mloc, mb);
            sloc = sloc * __expf(mloc - mn) + sb2 * __expf(mb - mn);
            mloc = mn;
            __syncthreads();
            const int col0 = ng0 + n * 128 + part * 32;
#pragma unroll
            for (int i = 0; i < 32; ++i) {
                int idx = i * 128 + tid;
                int rr = idx >> 5, cc = idx & 31;
                C[(size_t)(m0 + rr) * NCELL + col0 + cc] = st[rr * 33 + cc];
            }
            __syncthreads();
        }
    }
    merge_stats(&rowstats[m0 + tid], mloc, sloc);

    __syncthreads();
    if (wid == 0) {
        tc_relinquish();
        tc_dealloc(tmem, 512);
    }
#endif
}

// rowstats init: (max=-1e30, sum=0)
__global__ void init_rowstats(unsigned long long *rs)
{
    int i = blockIdx.x * blockDim.x + threadIdx.x;
    float2 z = make_float2(-1e30f, 0.f);
    rs[i] = *(unsigned long long *)&z;
}

// ---------------------------------------------------------------------------
// fp32 -> bf16 hi/lo split kernels
// ---------------------------------------------------------------------------
__global__ void split_cols(const float *__restrict__ src, int ldsrc, int col0,
                           int cols4, __nv_bfloat16 *__restrict__ hi,
                           __nv_bfloat16 *__restrict__ lo)
{
    int idx = blockIdx.x * blockDim.x + threadIdx.x;
    int r = idx / cols4, c = idx - r * cols4;
    float4 v = *(const float4 *)(src + (size_t)r * ldsrc + col0 + c * 4);
    uint2 h, l;
    split4_fast(v, h, l);
    *(uint2 *)(hi + (size_t)idx * 4) = h;
    *(uint2 *)(lo + (size_t)idx * 4) = l;
}

__global__ void wT_split(const float *__restrict__ W, const int *__restrict__ hid,
                         __nv_bfloat16 *__restrict__ hi, __nv_bfloat16 *__restrict__ lo)
{
    __shared__ float t[32][33];
    int r0 = blockIdx.x * 32;
    int c0 = blockIdx.y * 32;
    int tx = threadIdx.x, ty = threadIdx.y;
    const float *Wh = W + (size_t)hid[0] * NINP * HDIM;
#pragma unroll
    for (int i = 0; i < 4; ++i) {
        int r = r0 + ty + i * 8;
        t[ty + i * 8][tx] = (r < NINP) ? Wh[(size_t)r * HDIM + c0 + tx] : 0.f;
    }
    __syncthreads();
#pragma unroll
    for (int i = 0; i < 4; ++i) {
        int c = ty + i * 8;
        float v = t[tx][c];
        __nv_bfloat16 h, l;
        split1(v, h, l);
        size_t o = (size_t)(c0 + c) * KPAD + r0 + tx;
        hi[o] = h;
        lo[o] = l;
    }
}

__global__ void transpose_split(const float *__restrict__ src, int ldsrc, int col0,
                                __nv_bfloat16 *__restrict__ hi,
                                __nv_bfloat16 *__restrict__ lo)
{
    __shared__ float t[32][33];
    int r0 = blockIdx.x * 32, c0 = blockIdx.y * 32;
    int tx = threadIdx.x, ty = threadIdx.y;
#pragma unroll
    for (int i = 0; i < 4; ++i) {
        int r = ty + i * 8;
        t[r][tx] = src[(size_t)(r0 + r) * ldsrc + col0 + c0 + tx];
    }
    __syncthreads();
#pragma unroll
    for (int i = 0; i < 4; ++i) {
        int c = ty + i * 8;
        float v = t[tx][c];
        __nv_bfloat16 h, l;
        split1(v, h, l);
        size_t o = (size_t)(c0 + c) * NCELL + r0 + tx;
        hi[o] = h;
        lo[o] = l;
    }
}

// ---------------------------------------------------------------------------
// gemm_small v3 (unchanged from 589us kernel)
// ---------------------------------------------------------------------------
#define GS_AS   0
#define GS_BS   8448
#define GS_BNS  25344
#define GS_BNB  25472
#define GS_SMEM ((25472 + 128) * 4)

template <bool BNA, bool STATS>
__global__ void __launch_bounds__(256)
gemm_small(const float *__restrict__ A, const float *__restrict__ B,
           float *__restrict__ C, int ldb, int ldc,
           const float *__restrict__ bias,
           const float *__restrict__ statsIn,
           const float *__restrict__ g, const float *__restrict__ be,
           const int *__restrict__ hid, int hstride,
           float *__restrict__ statsOut)
{
    extern __shared__ float smf[];
    float *As  = smf + GS_AS;
    float *Bs  = smf + GS_BS;
    float *bnS = smf + GS_BNS;
    float *bnB = smf + GS_BNB;
    const uint32_t sb = cvta_smem(smf);

    const int tid = threadIdx.x;
    const int tx = tid & 15;
    const int ty = tid >> 4;
    const int m0 = blockIdx.x * 64;
    const int n0 = blockIdx.y * 128;

#pragma unroll
    for (int j = 0; j < 8; ++j) {
        int e = j * 256 + tid;
        int m = e >> 5, c = e & 31;
        cpa16(sb + GS_AS * 4 + (uint32_t)(m * 528 + c * 16),
              A + (size_t)(m0 + m) * HDIM + c * 4);
    }
#pragma unroll
    for (int j = 0; j < 16; ++j) {
        int e = j * 256 + tid;
        int k = e >> 5, c = e & 31;
        cpa16(sb + GS_BS * 4 + (uint32_t)(k * 528 + c * 16),
              B + (size_t)k * ldb + n0 + c * 4);
    }
    cpa_commit();

    if (BNA && tid < 128) {
        float s1 = statsIn[tid], s2 = statsIn[128 + tid];
        float mean = s1 * (1.f / (float)NCELL);
        float var = s2 * (1.f / (float)NCELL) - mean * mean;
        float rstd = rsqrtf(var + BN_EPS);
        int off = hid ? hid[0] * hstride : 0;
        float gg = g[off + tid];
        bnS[tid] = gg * rstd;
        bnB[tid] = be[off + tid] - gg * mean * rstd;
    }
    cpa_wait<0>();
    __syncthreads();

    if (BNA) {
#pragma unroll
        for (int j = 0; j < 32; ++j) {
            int e = j * 256 + tid;
            int m = e >> 7, k = e & 127;
            float v = As[m * 132 + k];
            As[m * 132 + k] = fmaxf(fmaf(v, bnS[k], bnB[k]), 0.f);
        }
        __syncthreads();
    }

    float2 acc[4][4];
#pragma unroll
    for (int i = 0; i < 4; ++i)
#pragma unroll
        for (int j = 0; j < 4; ++j) acc[i][j] = make_float2(0.f, 0.f);

    const float *arow0 = As + (ty * 4 + 0) * 132;
    const float *arow1 = As + (ty * 4 + 1) * 132;
    const float *arow2 = As + (ty * 4 + 2) * 132;
    const float *arow3 = As + (ty * 4 + 3) * 132;

#pragma unroll 16
    for (int kk = 0; kk < HDIM; ++kk) {
        float4 b0 = *(const float4 *)&Bs[kk * 132 + tx * 4];
        float4 b1 = *(const float4 *)&Bs[kk * 132 + 64 + tx * 4];
        float2 bp[4] = {make_float2(b0.x, b0.y), make_float2(b0.z, b0.w),
                        make_float2(b1.x, b1.y), make_float2(b1.z, b1.w)};
        float av[4] = {arow0[kk], arow1[kk], arow2[kk], arow3[kk]};
#pragma unroll
        for (int i = 0; i < 4; ++i) {
            float2 aa = make_float2(av[i], av[i]);
#pragma unroll
            for (int j = 0; j < 4; ++j) fma2(acc[i][j], aa, bp[j]);
        }
    }

    float bad0[4] = {0.f, 0.f, 0.f, 0.f}, bad1[4] = {0.f, 0.f, 0.f, 0.f};
    if (bias != nullptr) {
#pragma unroll
        for (int j = 0; j < 4; ++j) {
            bad0[j] = bias[n0 + tx * 4 + j];
            bad1[j] = bias[n0 + 64 + tx * 4 + j];
        }
    }

    float cs[8], cq[8];
#pragma unroll
    for (int j = 0; j < 8; ++j) { cs[j] = 0.f; cq[j] = 0.f; }

#pragma unroll
    for (int i = 0; i < 4; ++i) {
        int r = m0 + ty * 4 + i;
        float v[8] = {acc[i][0].x, acc[i][0].y, acc[i][1].x, acc[i][1].y,
                      acc[i][2].x, acc[i][2].y, acc[i][3].x, acc[i][3].y};
        float w[8];
#pragma unroll
        for (int j = 0; j < 4; ++j) { w[j] = v[j] + bad0[j]; w[4 + j] = v[4 + j] + bad1[j]; }
        if (STATS) {
#pragma unroll
            for (int j = 0; j < 8; ++j) { cs[j] += w[j]; cq[j] += w[j] * w[j]; }
        }
        float *crow = C + (size_t)r * ldc;
        *(float4 *)(crow + n0 + tx * 4)      = make_float4(w[0], w[1], w[2], w[3]);
        *(float4 *)(crow + n0 + 64 + tx * 4) = make_float4(w[4], w[5], w[6], w[7]);
    }

    if (STATS) {
        __syncthreads();
        float *sred = As;
        if (tid < 128) { sred[tid] = 0.f; sred[128 + tid] = 0.f; }
        __syncthreads();
#pragma unroll
        for (int j = 0; j < 8; ++j) {
            int col = (j < 4) ? (tx * 4 + j) : (64 + tx * 4 + (j - 4));
            atomicAdd(&sred[col], cs[j]);
            atomicAdd(&sred[128 + col], cq[j]);
        }
        __syncthreads();
        if (tid < 128) {
            atomicAdd(statsOut + tid, sred[tid]);
            atomicAdd(statsOut + 128 + tid, sred[128 + tid]);
        }
    }
}

// ---------------------------------------------------------------------------
// BatchNorm stats (enc output only)
// ---------------------------------------------------------------------------
__global__ void bn_stats(const float *__restrict__ h, float *__restrict__ stats)
{
    int col = threadIdx.x;
    int r0 = blockIdx.x * 32;
    float s = 0.f, s2 = 0.f;
#pragma unroll 8
    for (int r = 0; r < 32; ++r) {
        float v = h[(size_t)(r0 + r) * HDIM + col];
        s += v; s2 += v * v;
    }
    atomicAdd(&stats[col], s);
    atomicAdd(&stats[128 + col], s2);
}

// ---------------------------------------------------------------------------
// Variational heads
// ---------------------------------------------------------------------------
__global__ void heads_kernel(const float *__restrict__ o,
                             const float *__restrict__ mW, const float *__restrict__ mb,
                             const float *__restrict__ vW, const float *__restrict__ vb,
                             const float *__restrict__ eps,
                             float *__restrict__ qm, float *__restrict__ qv,
                             float *__restrict__ lat)
{
    extern __shared__ float smh[];
    float *Wm  = smh;
    float *Wv  = smh + 4096;
    float *osm = smh + 8192;
    const int t = threadIdx.x;
    const int r0 = blockIdx.x * 128;

    for (int i = t; i < HDIM * NOUTD; i += 256) { Wm[i] = mW[i]; Wv[i] = vW[i]; }
    for (int i = t; i < 128 * HDIM; i += 256) {
        int r = i >> 7, c = i & 127;
        osm[r * 129 + c] = o[(size_t)(r0 + r) * HDIM + c];
    }
    __syncthreads();

    for (int idx = t; idx < 128 * NOUTD; idx += 256) {
        int r = idx >> 5, c = idx & 31;
        const float *orow = &osm[r * 129];
        float dm = 0.f, dv = 0.f;
#pragma unroll 8
        for (int k = 0; k < HDIM; ++k) {
            float ov = orow[k];
            dm += ov * Wm[k * NOUTD + c];
            dv += ov * Wv[k * NOUTD + c];
        }
        int R = r0 + r;
        float mval = dm + mb[c];
        float vval = __expf(dv + vb[c]);
        qm[R * NOUTD + c]  = mval;
        qv[R * NOUTD + c]  = vval;
        lat[R * NOUTD + c] = mval + sqrtf(vval) * eps[R * NOUTD + c];
    }
}

// ---------------------------------------------------------------------------
// Launch
// ---------------------------------------------------------------------------
extern "C" void kernel_launch(void *const *d_in, const int *in_sizes, int n_in,
                              void *d_out, int out_size)
{
    const float *x       = (const float *)d_in[0];
    const float *spatial = (const float *)d_in[1];
    const float *eps     = (const float *)d_in[2];
    const float *enc_W   = (const float *)d_in[3];
    const float *enc_g   = (const float *)d_in[5];
    const float *enc_be  = (const float *)d_in[6];
    const float *sh_W1   = (const float *)d_in[7];
    const float *sh_g1   = (const float *)d_in[9];
    const float *sh_be1  = (const float *)d_in[10];
    const float *sh_W2   = (const float *)d_in[11];
    const float *sh_g2   = (const float *)d_in[13];
    const float *sh_be2  = (const float *)d_in[14];
    const float *qkv_W   = (const float *)d_in[15];
    const float *qkv_b   = (const float *)d_in[16];
    const float *o_W     = (const float *)d_in[17];
    const float *o_b     = (const float *)d_in[18];
    const float *mean_W  = (const float *)d_in[19];
    const float *mean_b  = (const float *)d_in[20];
    const float *var_W   = (const float *)d_in[21];
    const float *var_b   = (const float *)d_in[22];
    const int   *hid     = (const int *)d_in[23];

    float *out = (float *)d_out;
    float *out_qm   = out;
    float *out_qv   = out + (size_t)NCELL * NOUTD;
    float *out_lat  = out + 2 * (size_t)NCELL * NOUTD;
    float *out_attn = out + 3 * (size_t)NCELL * NOUTD;

    float *bufA, *bufB, *qkv, *kagg, *stats;
    unsigned long long *rowstats;
    __nv_bfloat16 *q_hi, *q_lo, *ka_hi, *ka_lo;
    __nv_bfloat16 *kT_hi, *kT_lo, *vT_hi, *vT_lo, *wT_hi, *wT_lo;
    cudaGetSymbolAddress((void **)&bufA, g_bufA);
    cudaGetSymbolAddress((void **)&bufB, g_bufB);
    cudaGetSymbolAddress((void **)&qkv,  g_qkv);
    cudaGetSymbolAddress((void **)&kagg, g_kagg);
    cudaGetSymbolAddress((void **)&stats, g_stats);
    cudaGetSymbolAddress((void **)&rowstats, g_rowstats);
    cudaGetSymbolAddress((void **)&q_hi, g_q_hi);
    cudaGetSymbolAddress((void **)&q_lo, g_q_lo);
    cudaGetSymbolAddress((void **)&ka_hi, g_ka_hi);
    cudaGetSymbolAddress((void **)&ka_lo, g_ka_lo);
    cudaGetSymbolAddress((void **)&kT_hi, g_kT_hi);
    cudaGetSymbolAddress((void **)&kT_lo, g_kT_lo);
    cudaGetSymbolAddress((void **)&vT_hi, g_vT_hi);
    cudaGetSymbolAddress((void **)&vT_lo, g_vT_lo);
    cudaGetSymbolAddress((void **)&wT_hi, g_wT_hi);
    cudaGetSymbolAddress((void **)&wT_lo, g_wT_lo);

    cudaFuncSetAttribute(tc_skinny_f32<false>, cudaFuncAttributeMaxDynamicSharedMemorySize, SKF_SMEM);
    cudaFuncSetAttribute(tc_skinny_f32<true>,  cudaFuncAttributeMaxDynamicSharedMemorySize, SKF_SMEM);
    cudaFuncSetAttribute(tc_wide,              cudaFuncAttributeMaxDynamicSharedMemorySize, WIDE_SMEM);
    cudaFuncSetAttribute((const void *)gemm_small<true, true>,
                         cudaFuncAttributeMaxDynamicSharedMemorySize, GS_SMEM);
    cudaFuncSetAttribute((const void *)gemm_small<true, false>,
                         cudaFuncAttributeMaxDynamicSharedMemorySize, GS_SMEM);
    cudaFuncSetAttribute((const void *)gemm_small<false, false>,
                         cudaFuncAttributeMaxDynamicSharedMemorySize, GS_SMEM);

    const size_t NH_BYTES = (size_t)NCELL * HDIM * sizeof(float);
    const float SCALE = 0.08838834764831845f;
    float *slot0 = stats, *slot1 = stats + 256, *slot2 = stats + 512;

    cudaMemsetAsync(stats, 0, 768 * sizeof(float));
    init_rowstats<<<32, 256>>>(rowstats);

    // 1. encoder: h = x @ enc_W[hid]
    wT_split<<<dim3(64, 4), dim3(32, 8)>>>(enc_W, hid, wT_hi, wT_lo);
    cudaMemsetAsync(bufA, 0, NH_BYTES);
    tc_skinny_f32<false><<<dim3(64, 1, 4), 128, SKF_SMEM>>>(
        (float *)x, NINP, NINP, wT_hi, wT_lo, KPAD, bufA, HDIM, 512, 1.f, nullptr);
    bn_stats<<<256, 128>>>(bufA, slot0);

    // 2. sh1 = BN1(bufA) @ W1 ; stats -> slot1
    gemm_small<true, true><<<dim3(128, 1), 256, GS_SMEM>>>(
        bufA, sh_W1, bufB, HDIM, HDIM, nullptr,
        slot0, enc_g, enc_be, hid, HDIM, slot1);

    // 3. sh2 = BN2(bufB) @ W2 ; stats -> slot2
    gemm_small<true, true><<<dim3(128, 1), 256, GS_SMEM>>>(
        bufB, sh_W2, bufA, HDIM, HDIM, nullptr,
        slot1, sh_g1, sh_be1, nullptr, 0, slot2);

    // 4. qkv = BN3(bufA) @ qkv_W + qkv_b
    gemm_small<true, false><<<dim3(128, 3), 256, GS_SMEM>>>(
        bufA, qkv_W, qkv, 3 * HDIM, 3 * HDIM, qkv_b,
        slot2, sh_g2, sh_be2, nullptr, 0, nullptr);

    // 5. small bf16 conversions (q, kT, vT)
    split_cols<<<1024, 256>>>(qkv, 3 * HDIM, 0, HDIM / 4, q_hi, q_lo);
    transpose_split<<<dim3(256, 4), dim3(32, 8)>>>(qkv, 3 * HDIM, HDIM, kT_hi, kT_lo);
    transpose_split<<<dim3(256, 4), dim3(32, 8)>>>(qkv, 3 * HDIM, 2 * HDIM, vT_hi, vT_lo);

    // 6. k_agg = spatial @ k
    cudaMemsetAsync(kagg, 0, NH_BYTES);
    tc_skinny_f32<false><<<dim3(64, 1, 4), 128, SKF_SMEM>>>(
        (float *)spatial, NCELL, NCELL, kT_hi, kT_lo, NCELL, kagg, HDIM, 2048, 1.f, nullptr);
    split_cols<<<1024, 256>>>(kagg, HDIM, 0, HDIM / 4, ka_hi, ka_lo);

    // 7. logits + row softmax stats
    tc_wide<<<dim3(64, 16), 128, WIDE_SMEM>>>(q_hi, q_lo, ka_hi, ka_lo, out_attn,
                                              SCALE, rowstats);

    // 8+9. fused: attn = softmax(logits) written in place, av = attn @ v
    cudaMemsetAsync(bufA, 0, NH_BYTES);
    tc_skinny_f32<true><<<dim3(64, 1, 4), 128, SKF_SMEM>>>(
        out_attn, NCELL, NCELL, vT_hi, vT_lo, NCELL, bufA, HDIM, 2048, 1.f, rowstats);

    // 10. o = av @ o_W + o_b
    gemm_small<false, false><<<dim3(128, 1), 256, GS_SMEM>>>(
        bufA, o_W, bufB, HDIM, HDIM, o_b,
        nullptr, nullptr, nullptr, nullptr, 0, nullptr);

    // 11. variational heads
    const int heads_smem = (4096 + 4096 + 128 * 129) * sizeof(float);
    cudaFuncSetAttribute(heads_kernel, cudaFuncAttributeMaxDynamicSharedMemorySize,
                         heads_smem);
    heads_kernel<<<64, 256, heads_smem>>>(bufB, mean_W, mean_b, var_W, var_b,
                                          eps, out_qm, out_qv, out_lat);
}

// round 13
// speedup vs baseline: 1.4253x; 1.0127x over previous
#include <cuda_runtime.h>
#include <cuda_bf16.h>
#include <math.h>
#include <stdint.h>

#define NCELL 8192
#define NINP  2000
#define KPAD  2048
#define HDIM  128
#define NOUTD 32
#define BN_EPS 1e-3f

#if defined(__CUDA_ARCH_FEAT_SM103_ALL) || defined(__CUDA_ARCH_FEAT_SM100_ALL) || \
    defined(__CUDA_ARCH_FEAT_SM110_ALL) || defined(__CUDA_ARCH_FEAT_SM101_ALL)
#define TC_ENABLED 1
#else
#define TC_ENABLED 0
#endif

// ---------------------------------------------------------------------------
// Scratch
// ---------------------------------------------------------------------------
__device__ __align__(256) float g_bufA[NCELL * HDIM];
__device__ __align__(256) float g_bufB[NCELL * HDIM];
__device__ __align__(256) float g_qkv [NCELL * 3 * HDIM];
__device__ __align__(256) float g_kagg[NCELL * HDIM];
__device__ __align__(256) float g_stats[768];
__device__ __align__(256) unsigned long long g_rowstats[NCELL];

__device__ __align__(256) __nv_bfloat16 g_q_hi [NCELL * HDIM];
__device__ __align__(256) __nv_bfloat16 g_q_lo [NCELL * HDIM];
__device__ __align__(256) __nv_bfloat16 g_ka_hi[NCELL * HDIM];
__device__ __align__(256) __nv_bfloat16 g_ka_lo[NCELL * HDIM];
__device__ __align__(256) __nv_bfloat16 g_kT_hi[HDIM * NCELL];
__device__ __align__(256) __nv_bfloat16 g_kT_lo[HDIM * NCELL];
__device__ __align__(256) __nv_bfloat16 g_vT_hi[HDIM * NCELL];
__device__ __align__(256) __nv_bfloat16 g_vT_lo[HDIM * NCELL];
__device__ __align__(256) __nv_bfloat16 g_wT_hi[HDIM * KPAD];
__device__ __align__(256) __nv_bfloat16 g_wT_lo[HDIM * KPAD];

// ---------------------------------------------------------------------------
// PTX helpers
// ---------------------------------------------------------------------------
__device__ __forceinline__ uint32_t cvta_smem(const void *p) {
    uint32_t a;
    asm("{ .reg .u64 t; cvta.to.shared.u64 t, %1; cvt.u32.u64 %0, t; }"
        : "=r"(a) : "l"(p));
    return a;
}
__device__ __forceinline__ uint32_t elect_one() {
    uint32_t p;
    asm volatile("{ .reg .pred p; elect.sync _|p, 0xFFFFFFFF; selp.b32 %0, 1, 0, p; }"
                 : "=r"(p));
    return p;
}
__device__ __forceinline__ void mbar_init(uint32_t mbar, uint32_t cnt) {
    asm volatile("mbarrier.init.shared.b64 [%0], %1;"
                 :: "r"(mbar), "r"(cnt) : "memory");
}
__device__ __forceinline__ void mbar_wait(uint32_t mbar, uint32_t parity) {
    asm volatile(
        "{\n\t.reg .pred P;\n"
        "LW_%=:\n\t"
        "mbarrier.try_wait.parity.acquire.cta.shared::cta.b64 P, [%0], %1, 0x989680;\n\t"
        "@P bra LD_%=;\n\t"
        "bra LW_%=;\n"
        "LD_%=:\n\t}"
        :: "r"(mbar), "r"(parity) : "memory");
}
__device__ __forceinline__ void fence_async_smem() {
    asm volatile("fence.proxy.async.shared::cta;" ::: "memory");
}
__device__ __forceinline__ void cpa16(uint32_t dst, const void *src) {
    asm volatile("cp.async.cg.shared.global [%0], [%1], 16;"
                 :: "r"(dst), "l"(src) : "memory");
}
__device__ __forceinline__ void cpa_commit() {
    asm volatile("cp.async.commit_group;" ::: "memory");
}
template <int N>
__device__ __forceinline__ void cpa_wait() {
    asm volatile("cp.async.wait_group %0;" :: "n"(N) : "memory");
}
__device__ __forceinline__ void red4(float *p, float a, float b, float c, float d) {
    asm volatile("red.global.add.v4.f32 [%0], {%1, %2, %3, %4};"
                 :: "l"(p), "f"(a), "f"(b), "f"(c), "f"(d) : "memory");
}

// ---- tcgen05 ----
__device__ __forceinline__ void tc_alloc(uint32_t smem_dst, uint32_t ncols) {
    asm volatile("tcgen05.alloc.cta_group::1.sync.aligned.shared::cta.b32 [%0], %1;"
                 :: "r"(smem_dst), "r"(ncols) : "memory");
}
__device__ __forceinline__ void tc_dealloc(uint32_t tmem, uint32_t ncols) {
    asm volatile("tcgen05.dealloc.cta_group::1.sync.aligned.b32 %0, %1;"
                 :: "r"(tmem), "r"(ncols));
}
__device__ __forceinline__ void tc_relinquish() {
    asm volatile("tcgen05.relinquish_alloc_permit.cta_group::1.sync.aligned;");
}
__device__ __forceinline__ void tc_commit(uint32_t mbar) {
    asm volatile("tcgen05.commit.cta_group::1.mbarrier::arrive::one.shared::cluster.b64 [%0];"
                 :: "r"(mbar) : "memory");
}
__device__ __forceinline__ void tc_fence_after() {
    asm volatile("tcgen05.fence::after_thread_sync;" ::: "memory");
}
__device__ __forceinline__ void tc_wait_ld() {
    asm volatile("tcgen05.wait::ld.sync.aligned;" ::: "memory");
}
__device__ __forceinline__ void ldtm32(uint32_t *r, uint32_t addr) {
    asm volatile(
        "tcgen05.ld.sync.aligned.32x32b.x32.b32 "
        "{%0, %1, %2, %3, %4, %5, %6, %7, "
        " %8, %9, %10, %11, %12, %13, %14, %15, "
        " %16, %17, %18, %19, %20, %21, %22, %23, "
        " %24, %25, %26, %27, %28, %29, %30, %31}, [%32];"
        : "=r"(r[0]),  "=r"(r[1]),  "=r"(r[2]),  "=r"(r[3]),
          "=r"(r[4]),  "=r"(r[5]),  "=r"(r[6]),  "=r"(r[7]),
          "=r"(r[8]),  "=r"(r[9]),  "=r"(r[10]), "=r"(r[11]),
          "=r"(r[12]), "=r"(r[13]), "=r"(r[14]), "=r"(r[15]),
          "=r"(r[16]), "=r"(r[17]), "=r"(r[18]), "=r"(r[19]),
          "=r"(r[20]), "=r"(r[21]), "=r"(r[22]), "=r"(r[23]),
          "=r"(r[24]), "=r"(r[25]), "=r"(r[26]), "=r"(r[27]),
          "=r"(r[28]), "=r"(r[29]), "=r"(r[30]), "=r"(r[31])
        : "r"(addr));
}
__device__ __forceinline__ void mma_f16_ss(uint32_t d, uint64_t a_desc,
                                           uint64_t b_desc, uint32_t idesc,
                                           uint32_t en) {
    asm volatile(
        "{\n\t.reg .pred p;\n\t"
        "setp.ne.u32 p, %5, 0;\n\t"
        "tcgen05.mma.cta_group::1.kind::f16 [%0], %1, %2, %3, {%4, %4, %4, %4}, p;\n\t}"
        :: "r"(d), "l"(a_desc), "l"(b_desc), "r"(idesc), "r"(0u), "r"(en)
        : "memory");
}
__device__ __forceinline__ uint64_t make_desc(uint32_t addr) {
    return ((uint64_t)2 << 61) | ((uint64_t)1 << 46) | ((uint64_t)64 << 32) |
           ((uint64_t)1 << 16) | (((uint64_t)(addr >> 4)) & 0x3FFF);
}
__device__ __forceinline__ void fma2(float2 &c, const float2 &a, const float2 &b) {
    unsigned long long       &cc = reinterpret_cast<unsigned long long &>(c);
    const unsigned long long &aa = reinterpret_cast<const unsigned long long &>(a);
    const unsigned long long &bb = reinterpret_cast<const unsigned long long &>(b);
    asm("fma.rn.f32x2 %0, %1, %2, %0;" : "+l"(cc) : "l"(aa), "l"(bb));
}
__device__ __forceinline__ void split1(float v, __nv_bfloat16 &h, __nv_bfloat16 &l) {
    h = __float2bfloat16(v);
    l = __float2bfloat16(v - __bfloat162float(h));
}
__device__ __forceinline__ void split4_fast(float4 v, uint2 &hi, uint2 &lo) {
    uint32_t h01, h23, l01, l23;
    asm("cvt.rn.bf16x2.f32 %0, %1, %2;" : "=r"(h01) : "f"(v.y), "f"(v.x));
    asm("cvt.rn.bf16x2.f32 %0, %1, %2;" : "=r"(h23) : "f"(v.w), "f"(v.z));
    float r0 = v.x - __uint_as_float(h01 << 16);
    float r1 = v.y - __uint_as_float(h01 & 0xFFFF0000u);
    float r2 = v.z - __uint_as_float(h23 << 16);
    float r3 = v.w - __uint_as_float(h23 & 0xFFFF0000u);
    asm("cvt.rn.bf16x2.f32 %0, %1, %2;" : "=r"(l01) : "f"(r1), "f"(r0));
    asm("cvt.rn.bf16x2.f32 %0, %1, %2;" : "=r"(l23) : "f"(r3), "f"(r2));
    hi = make_uint2(h01, h23);
    lo = make_uint2(l01, l23);
}
__device__ __forceinline__ void merge_stats(unsigned long long *addr, float m2, float s2) {
    unsigned long long old = *addr, assumed;
    do {
        assumed = old;
        float2 cur = *(float2 *)&assumed;
        float mn = fmaxf(cur.x, m2);
        float sn = cur.y * __expf(cur.x - mn) + s2 * __expf(m2 - mn);
        float2 nf = make_float2(mn, sn);
        old = atomicCAS(addr, assumed, *(unsigned long long *)&nf);
    } while (old != assumed);
}

static constexpr uint32_t TC_IDESC = 0x8200490u;

__device__ __forceinline__ uint32_t sw32(int r, int ch) {
    uint32_t byte = ((r >> 3) + (ch >> 3) * 16) * 1024 + (r & 7) * 128 + (ch & 7) * 16;
    return byte ^ ((byte >> 3) & 0x70);
}

// ---------------------------------------------------------------------------
// tc_skinny_f32: C += A_f32 @ (Bhi+Blo)^T   (enc + spatial GEMMs)
// ---------------------------------------------------------------------------
#define SKF_SMEM (1024 + 2 * 65536)

__global__ void __launch_bounds__(128)
tc_skinny_f32(const float *__restrict__ A, int lda, int Kvalid,
              const __nv_bfloat16 *__restrict__ Bhi,
              const __nv_bfloat16 *__restrict__ Blo, int ldb,
              float *__restrict__ C, int ldc, int kpc, float alpha)
{
#if TC_ENABLED
    extern __shared__ char sm[];
    const uint32_t sb = cvta_smem(sm);
    const int tid = threadIdx.x;
    const int wid = tid >> 5;

    if (wid == 0) tc_alloc(sb, 128);
    if (tid == 64) mbar_init(sb + 8, 1);
    __syncthreads();
    uint32_t tmem;
    asm volatile("ld.shared.b32 %0, [%1];" : "=r"(tmem) : "r"(sb));

    const int m0 = blockIdx.x * 128;
    const int kb0 = blockIdx.z * kpc;
    const int S = kpc >> 6;

    const int aRow = tid >> 4;
    const int aCol = (tid & 15) * 4;
    const float *aBase = A + (size_t)(m0 + aRow) * lda + aCol;
    const size_t aRowStep = (size_t)8 * lda;
    const uint32_t toffA = (uint32_t)(((tid >> 4) * 128 + (tid & 15) * 8) ^ ((tid >> 4) << 4));
    const int bRow = tid >> 3;
    const int bCol = (tid & 7) * 8;
    const uint32_t toffB = (uint32_t)((((tid >> 3) & 7) * 128 + (tid & 7) * 16) ^
                                      ((((tid >> 3) & 7) << 4)));
    const uint32_t bAtom = (uint32_t)(tid >> 6) * 1024;

    float4 regs[16];

    auto ldA = [&](int s) {
        const int kb = kb0 + s * 64;
        const bool ok = (kb + aCol) < Kvalid;
        const float *p = aBase + kb;
#pragma unroll
        for (int i = 0; i < 16; ++i) {
            regs[i] = ok ? *(const float4 *)(p + i * aRowStep)
                         : make_float4(0.f, 0.f, 0.f, 0.f);
        }
    };
    auto ldB = [&](int s) {
        const uint32_t bh = sb + 1024 + (s & 1) * 65536 + 32768;
        const int kb = kb0 + s * 64;
        const __nv_bfloat16 *ph = Bhi + (size_t)bRow * ldb + kb + bCol;
        const __nv_bfloat16 *pl = Blo + (size_t)bRow * ldb + kb + bCol;
        const uint32_t so0 = bAtom + toffB;
#pragma unroll
        for (int i = 0; i < 8; ++i) {
            uint32_t so = so0 + i * 2048;
            cpa16(bh + so,         ph + (size_t)i * 16 * ldb);
            cpa16(bh + 16384 + so, pl + (size_t)i * 16 * ldb);
        }
        cpa_commit();
    };
    auto stA = [&](int s) {
        char *ah = sm + 1024 + (s & 1) * 65536;
        char *al = ah + 16384;
#pragma unroll
        for (int i = 0; i < 16; ++i) {
            uint2 h, l;
            split4_fast(regs[i], h, l);
            uint32_t sz = toffA + i * 1024;
            *(uint2 *)(ah + sz) = h;
            *(uint2 *)(al + sz) = l;
        }
    };

    ldB(0);
    ldA(0);
    uint32_t ph = 0;
    for (int s = 0; s < S; ++s) {
        cpa_wait<0>();
        stA(s);
        __syncthreads();
        fence_async_smem();
        if (wid == 0 && elect_one()) {
            const uint32_t base = sb + 1024 + (s & 1) * 65536;
            uint64_t dah = make_desc(base);
            uint64_t dal = make_desc(base + 16384);
            uint64_t dbh = make_desc(base + 32768);
            uint64_t dbl = make_desc(base + 49152);
#pragma unroll
            for (int k = 0; k < 4; ++k) {
                uint64_t off = (uint64_t)(k * 2);
                mma_f16_ss(tmem, dah + off, dbh + off, TC_IDESC, (s > 0) || (k > 0));
                mma_f16_ss(tmem, dah + off, dbl + off, TC_IDESC, 1u);
                mma_f16_ss(tmem, dal + off, dbh + off, TC_IDESC, 1u);
            }
            tc_commit(sb + 8);
        }
        if (s + 1 < S) { ldB(s + 1); ldA(s + 1); }
        mbar_wait(sb + 8, ph);
        ph ^= 1;
        __syncthreads();
    }

    tc_fence_after();
#pragma unroll
    for (int part = 0; part < 4; ++part) {
        uint32_t d[32];
        ldtm32(d, tmem + part * 32);
        tc_wait_ld();
        float *cp = C + (size_t)(m0 + tid) * ldc + part * 32;
#pragma unroll
        for (int j = 0; j < 8; ++j)
            red4(cp + j * 4,
                 __uint_as_float(d[j * 4 + 0]) * alpha,
                 __uint_as_float(d[j * 4 + 1]) * alpha,
                 __uint_as_float(d[j * 4 + 2]) * alpha,
                 __uint_as_float(d[j * 4 + 3]) * alpha);
    }
    __syncthreads();
    if (wid == 0) {
        tc_relinquish();
        tc_dealloc(tmem, 128);
    }
#endif
}

// ---------------------------------------------------------------------------
// tc_wide_stats: logits GEMM, row (max, sumexp) stats ONLY — no logits store.
// ---------------------------------------------------------------------------
#define WIDE_SMEM (1024 + 65536 + 131072)

__global__ void __launch_bounds__(128)
tc_wide_stats(const __nv_bfloat16 *__restrict__ Ahi, const __nv_bfloat16 *__restrict__ Alo,
              const __nv_bfloat16 *__restrict__ Bhi, const __nv_bfloat16 *__restrict__ Blo,
              float alpha, unsigned long long *__restrict__ rowstats)
{
#if TC_ENABLED
    extern __shared__ char sm[];
    const uint32_t sb = cvta_smem(sm);
    const int tid = threadIdx.x;
    const int wid = tid >> 5;

    if (wid == 0) tc_alloc(sb, 512);
    if (tid == 64) mbar_init(sb + 8, 1);
    __syncthreads();
    uint32_t tmem;
    asm volatile("ld.shared.b32 %0, [%1];" : "=r"(tmem) : "r"(sb));

    const int m0 = blockIdx.x * 128;
    const int ng0 = blockIdx.y * 512;

    const uint32_t A0 = sb + 1024;
    const uint32_t A1 = A0 + 32768;

    auto load_B = [&](int n) {
        const uint32_t base = sb + 1024 + 65536 + (n & 1) * 65536;
        const int r0 = ng0 + n * 128;
#pragma unroll
        for (int i = tid; i < 2048; i += 128) {
            int r = i >> 4, ch = i & 15;
            uint32_t so = sw32(r, ch);
            cpa16(base + so,         Bhi + (size_t)(r0 + r) * HDIM + ch * 8);
            cpa16(base + 32768 + so, Blo + (size_t)(r0 + r) * HDIM + ch * 8);
        }
        cpa_commit();
    };

#pragma unroll
    for (int i = tid; i < 2048; i += 128) {
        int r = i >> 4, ch = i & 15;
        uint32_t so = sw32(r, ch);
        cpa16(A0 + so, Ahi + (size_t)(m0 + r) * HDIM + ch * 8);
        cpa16(A1 + so, Alo + (size_t)(m0 + r) * HDIM + ch * 8);
    }
    {
        const uint32_t base = sb + 1024 + 65536;
#pragma unroll
        for (int i = tid; i < 2048; i += 128) {
            int r = i >> 4, ch = i & 15;
            uint32_t so = sw32(r, ch);
            cpa16(base + so,         Bhi + (size_t)(ng0 + r) * HDIM + ch * 8);
            cpa16(base + 32768 + so, Blo + (size_t)(ng0 + r) * HDIM + ch * 8);
        }
    }
    cpa_commit();

    uint32_t ph = 0;
    for (int n = 0; n < 4; ++n) {
        if (n + 1 < 4) { load_B(n + 1); cpa_wait<1>(); }
        else           { cpa_wait<0>(); }
        __syncthreads();
        fence_async_smem();
        if (wid == 0 && elect_one()) {
            const uint32_t bbase = sb + 1024 + 65536 + (n & 1) * 65536;
            uint64_t dah = make_desc(A0);
            uint64_t dal = make_desc(A1);
            uint64_t dbh = make_desc(bbase);
            uint64_t dbl = make_desc(bbase + 32768);
            const uint32_t acc = tmem + n * 128;
#pragma unroll
            for (int k = 0; k < 8; ++k) {
                uint64_t off = (uint64_t)((k & 3) * 2 + (k >> 2) * 1024);
                mma_f16_ss(acc, dah + off, dbh + off, TC_IDESC, k > 0);
                mma_f16_ss(acc, dah + off, dbl + off, TC_IDESC, 1u);
                mma_f16_ss(acc, dal + off, dbh + off, TC_IDESC, 1u);
            }
            tc_commit(sb + 8);
        }
        mbar_wait(sb + 8, ph);
        ph ^= 1;
        __syncthreads();
    }

    tc_fence_after();
    float mloc = -1e30f, sloc = 0.f;
    for (int n = 0; n < 4; ++n) {
#pragma unroll
        for (int part = 0; part < 4; ++part) {
            uint32_t d[32];
            ldtm32(d, tmem + n * 128 + part * 32);
            tc_wait_ld();
            float mb = -1e30f;
            float v[32];
#pragma unroll
            for (int c = 0; c < 32; ++c) {
                v[c] = __uint_as_float(d[c]) * alpha;
                mb = fmaxf(mb, v[c]);
            }
            float sb2 = 0.f;
#pragma unroll
            for (int c = 0; c < 32; ++c) sb2 += __expf(v[c] - mb);
            float mn = fmaxf(mloc, mb);
            sloc = sloc * __expf(mloc - mn) + sb2 * __expf(mb - mn);
            mloc = mn;
        }
    }
    merge_stats(&rowstats[m0 + tid], mloc, sloc);

    __syncthreads();
    if (wid == 0) {
        tc_relinquish();
        tc_dealloc(tmem, 512);
    }
#endif
}

// ---------------------------------------------------------------------------
// tc_attn: pass 2. Recompute logits tile = q@ka^T, softmax with known stats,
// write attn, convert tile to bf16 hi/lo, accumulate av += attn @ v in TMEM.
// FIX vs R12: K_{j+1} prefetch moved AFTER mbar_wait(MMA1) — the prefetch was
// overwriting the K buffer while MMA1 was still reading it (race, rel_err 5e-2).
// ---------------------------------------------------------------------------
#define AT_QH 1024
#define AT_QL (AT_QH + 32768)
#define AT_KH (AT_QL + 32768)
#define AT_KL (AT_KH + 32768)
#define AT_VH (AT_KL + 32768)
#define AT_VL (AT_VH + 32768)
#define AT_P  (AT_VL + 32768)
#define AT_PH AT_P
#define AT_PL (AT_P + 16384)
#define AT_SMEM (AT_P + 32768)
#define AT_JB 16

__global__ void __launch_bounds__(128)
tc_attn(const __nv_bfloat16 *__restrict__ Qhi, const __nv_bfloat16 *__restrict__ Qlo,
        const __nv_bfloat16 *__restrict__ KAhi, const __nv_bfloat16 *__restrict__ KAlo,
        const __nv_bfloat16 *__restrict__ VThi, const __nv_bfloat16 *__restrict__ VTlo,
        float *__restrict__ attn, float *__restrict__ av,
        const unsigned long long *__restrict__ rowstats, float alpha)
{
#if TC_ENABLED
    extern __shared__ char sm[];
    const uint32_t sb = cvta_smem(sm);
    const int tid = threadIdx.x;
    const int wid = tid >> 5;

    if (wid == 0) tc_alloc(sb, 256);
    if (tid == 64) mbar_init(sb + 8, 1);
    __syncthreads();
    uint32_t tmem;
    asm volatile("ld.shared.b32 %0, [%1];" : "=r"(tmem) : "r"(sb));
    const uint32_t LACC = tmem;
    const uint32_t VACC = tmem + 128;

    const int m0 = blockIdx.x * 128;
    const int j0 = blockIdx.z * AT_JB;

    float rmax, rinv;
    {
        unsigned long long u = rowstats[m0 + tid];
        float2 st2 = *(float2 *)&u;
        rmax = st2.x;
        rinv = 1.f / st2.y;
    }
    const uint32_t pbase = (uint32_t)((tid >> 3) * 1024 + (tid & 7) * 128);
    const uint32_t pxor  = (uint32_t)((tid & 7) << 4);

    // prologue: Q + K(j0) + V(j0), one group
#pragma unroll
    for (int i = tid; i < 2048; i += 128) {
        int r = i >> 4, ch = i & 15;
        uint32_t so = sw32(r, ch);
        size_t off = (size_t)(m0 + r) * HDIM + ch * 8;
        cpa16(sb + AT_QH + so, Qhi + off);
        cpa16(sb + AT_QL + so, Qlo + off);
    }
    {
        const int jc0 = j0 * 128;
#pragma unroll
        for (int i = tid; i < 2048; i += 128) {
            int r = i >> 4, ch = i & 15;
            uint32_t so = sw32(r, ch);
            size_t offK = (size_t)(jc0 + r) * HDIM + ch * 8;
            size_t offV = (size_t)r * NCELL + jc0 + ch * 8;
            cpa16(sb + AT_KH + so, KAhi + offK);
            cpa16(sb + AT_KL + so, KAlo + offK);
            cpa16(sb + AT_VH + so, VThi + offV);
            cpa16(sb + AT_VL + so, VTlo + offV);
        }
    }
    cpa_commit();

    const uint64_t dQH = make_desc(sb + AT_QH);
    const uint64_t dQL = make_desc(sb + AT_QL);
    const uint64_t dKH = make_desc(sb + AT_KH);
    const uint64_t dKL = make_desc(sb + AT_KL);
    const uint64_t dVH = make_desc(sb + AT_VH);
    const uint64_t dVL = make_desc(sb + AT_VL);
    const uint64_t dPH = make_desc(sb + AT_PH);
    const uint64_t dPL = make_desc(sb + AT_PL);
    float *st = (float *)(sm + AT_P);

    uint32_t ph = 0;
    for (int jj = 0; jj < AT_JB; ++jj) {
        const int jc0 = (j0 + jj) * 128;
        if (jj == 0) cpa_wait<0>(); else cpa_wait<1>();
        __syncthreads();
        fence_async_smem();
        // MMA1: logits = Q @ Ka^T (fresh accumulator)
        if (wid == 0 && elect_one()) {
#pragma unroll
            for (int k = 0; k < 8; ++k) {
                uint64_t off = (uint64_t)((k & 3) * 2 + (k >> 2) * 1024);
                mma_f16_ss(LACC, dQH + off, dKH + off, TC_IDESC, k > 0);
                mma_f16_ss(LACC, dQH + off, dKL + off, TC_IDESC, 1u);
                mma_f16_ss(LACC, dQL + off, dKH + off, TC_IDESC, 1u);
            }
            tc_commit(sb + 8);
        }
        mbar_wait(sb + 8, ph);
        ph ^= 1;
        tc_fence_after();

        // prefetch K_{j+1} — AFTER MMA1 completion (K buffer now free).
        // Load still overlaps the softmax/store/MMA2 phase below.
        if (jj + 1 < AT_JB) {
            const int jn = (j0 + jj + 1) * 128;
#pragma unroll
            for (int i = tid; i < 2048; i += 128) {
                int r = i >> 4, ch = i & 15;
                uint32_t so = sw32(r, ch);
                size_t off = (size_t)(jn + r) * HDIM + ch * 8;
                cpa16(sb + AT_KH + so, KAhi + off);
                cpa16(sb + AT_KL + so, KAlo + off);
            }
            cpa_commit();
        }

        // two halves of 64 cols each
#pragma unroll
        for (int h = 0; h < 2; ++h) {
            float v[64];
#pragma unroll
            for (int q = 0; q < 2; ++q) {
                uint32_t d[32];
                ldtm32(d, LACC + h * 64 + q * 32);
                tc_wait_ld();
#pragma unroll
                for (int c = 0; c < 32; ++c) {
                    float x = __uint_as_float(d[c]) * alpha;
                    v[q * 32 + c] = __expf(x - rmax) * rinv;
                }
                __syncthreads();
#pragma unroll
                for (int c = 0; c < 32; ++c) st[tid * 33 + c] = v[q * 32 + c];
                __syncthreads();
                const int col0 = jc0 + h * 64 + q * 32;
#pragma unroll
                for (int i = 0; i < 32; ++i) {
                    int idx = i * 128 + tid;
                    int rr = idx >> 5, cc = idx & 31;
                    attn[(size_t)(m0 + rr) * NCELL + col0 + cc] = st[rr * 33 + cc];
                }
            }
            __syncthreads();
#pragma unroll
            for (int ch = 0; ch < 8; ++ch) {
                float4 a = make_float4(v[ch * 8 + 0], v[ch * 8 + 1],
                                       v[ch * 8 + 2], v[ch * 8 + 3]);
                float4 b = make_float4(v[ch * 8 + 4], v[ch * 8 + 5],
                                       v[ch * 8 + 6], v[ch * 8 + 7]);
                uint2 h0, l0, h1, l1;
                split4_fast(a, h0, l0);
                split4_fast(b, h1, l1);
                uint32_t addr = pbase + ((uint32_t)(ch * 16) ^ pxor);
                *(uint4 *)(sm + AT_PH + addr) = make_uint4(h0.x, h0.y, h1.x, h1.y);
                *(uint4 *)(sm + AT_PL + addr) = make_uint4(l0.x, l0.y, l1.x, l1.y);
            }
            __syncthreads();
            fence_async_smem();
            // MMA2: av += P @ V^T
            if (wid == 0 && elect_one()) {
#pragma unroll
                for (int k = 0; k < 4; ++k) {
                    uint64_t aoff = (uint64_t)(k * 2);
                    uint64_t boff = (uint64_t)(k * 2 + h * 1024);
                    uint32_t en0 = (jj > 0) || (h > 0) || (k > 0);
                    mma_f16_ss(VACC, dPH + aoff, dVH + boff, TC_IDESC, en0);
                    mma_f16_ss(VACC, dPH + aoff, dVL + boff, TC_IDESC, 1u);
                    mma_f16_ss(VACC, dPL + aoff, dVH + boff, TC_IDESC, 1u);
                }
                tc_commit(sb + 8);
            }
            mbar_wait(sb + 8, ph);
            ph ^= 1;
            __syncthreads();
        }
        tc_fence_after();
        // prefetch V_{j+1} (V buffer free: MMA2 of both halves completed)
        if (jj + 1 < AT_JB) {
            const int jn = (j0 + jj + 1) * 128;
#pragma unroll
            for (int i = tid; i < 2048; i += 128) {
                int r = i >> 4, ch = i & 15;
                uint32_t so = sw32(r, ch);
                size_t off = (size_t)r * NCELL + jn + ch * 8;
                cpa16(sb + AT_VH + so, VThi + off);
                cpa16(sb + AT_VL + so, VTlo + off);
            }
            cpa_commit();
        }
    }

    // av epilogue
#pragma unroll
    for (int part = 0; part < 4; ++part) {
        uint32_t d[32];
        ldtm32(d, VACC + part * 32);
        tc_wait_ld();
        float *cp = av + (size_t)(m0 + tid) * HDIM + part * 32;
#pragma unroll
        for (int j = 0; j < 8; ++j)
            red4(cp + j * 4,
                 __uint_as_float(d[j * 4 + 0]),
                 __uint_as_float(d[j * 4 + 1]),
                 __uint_as_float(d[j * 4 + 2]),
                 __uint_as_float(d[j * 4 + 3]));
    }
    __syncthreads();
    if (wid == 0) {
        tc_relinquish();
        tc_dealloc(tmem, 256);
    }
#endif
}

__global__ void init_rowstats(unsigned long long *rs)
{
    int i = blockIdx.x * blockDim.x + threadIdx.x;
    float2 z = make_float2(-1e30f, 0.f);
    rs[i] = *(unsigned long long *)&z;
}

// ---------------------------------------------------------------------------
// fp32 -> bf16 hi/lo split kernels
// ---------------------------------------------------------------------------
__global__ void split_cols(const float *__restrict__ src, int ldsrc, int col0,
                           int cols4, __nv_bfloat16 *__restrict__ hi,
                           __nv_bfloat16 *__restrict__ lo)
{
    int idx = blockIdx.x * blockDim.x + threadIdx.x;
    int r = idx / cols4, c = idx - r * cols4;
    float4 v = *(const float4 *)(src + (size_t)r * ldsrc + col0 + c * 4);
    uint2 h, l;
    split4_fast(v, h, l);
    *(uint2 *)(hi + (size_t)idx * 4) = h;
    *(uint2 *)(lo + (size_t)idx * 4) = l;
}

__global__ void wT_split(const float *__restrict__ W, const int *__restrict__ hid,
                         __nv_bfloat16 *__restrict__ hi, __nv_bfloat16 *__restrict__ lo)
{
    __shared__ float t[32][33];
    int r0 = blockIdx.x * 32;
    int c0 = blockIdx.y * 32;
    int tx = threadIdx.x, ty = threadIdx.y;
    const float *Wh = W + (size_t)hid[0] * NINP * HDIM;
#pragma unroll
    for (int i = 0; i < 4; ++i) {
        int r = r0 + ty + i * 8;
        t[ty + i * 8][tx] = (r < NINP) ? Wh[(size_t)r * HDIM + c0 + tx] : 0.f;
    }
    __syncthreads();
#pragma unroll
    for (int i = 0; i < 4; ++i) {
        int c = ty + i * 8;
        float v = t[tx][c];
        __nv_bfloat16 h, l;
        split1(v, h, l);
        size_t o = (size_t)(c0 + c) * KPAD + r0 + tx;
        hi[o] = h;
        lo[o] = l;
    }
}

__global__ void transpose_split(const float *__restrict__ src, int ldsrc, int col0,
                                __nv_bfloat16 *__restrict__ hi,
                                __nv_bfloat16 *__restrict__ lo)
{
    __shared__ float t[32][33];
    int r0 = blockIdx.x * 32, c0 = blockIdx.y * 32;
    int tx = threadIdx.x, ty = threadIdx.y;
#pragma unroll
    for (int i = 0; i < 4; ++i) {
        int r = ty + i * 8;
        t[r][tx] = src[(size_t)(r0 + r) * ldsrc + col0 + c0 + tx];
    }
    __syncthreads();
#pragma unroll
    for (int i = 0; i < 4; ++i) {
        int c = ty + i * 8;
        float v = t[tx][c];
        __nv_bfloat16 h, l;
        split1(v, h, l);
        size_t o = (size_t)(c0 + c) * NCELL + r0 + tx;
        hi[o] = h;
        lo[o] = l;
    }
}

// ---------------------------------------------------------------------------
// gemm_small v3 (unchanged)
// ---------------------------------------------------------------------------
#define GS_AS   0
#define GS_BS   8448
#define GS_BNS  25344
#define GS_BNB  25472
#define GS_SMEM ((25472 + 128) * 4)

template <bool BNA, bool STATS>
__global__ void __launch_bounds__(256)
gemm_small(const float *__restrict__ A, const float *__restrict__ B,
           float *__restrict__ C, int ldb, int ldc,
           const float *__restrict__ bias,
           const float *__restrict__ statsIn,
           const float *__restrict__ g, const float *__restrict__ be,
           const int *__restrict__ hid, int hstride,
           float *__restrict__ statsOut)
{
    extern __shared__ float smf[];
    float *As  = smf + GS_AS;
    float *Bs  = smf + GS_BS;
    float *bnS = smf + GS_BNS;
    float *bnB = smf + GS_BNB;
    const uint32_t sb = cvta_smem(smf);

    const int tid = threadIdx.x;
    const int tx = tid & 15;
    const int ty = tid >> 4;
    const int m0 = blockIdx.x * 64;
    const int n0 = blockIdx.y * 128;

#pragma unroll
    for (int j = 0; j < 8; ++j) {
        int e = j * 256 + tid;
        int m = e >> 5, c = e & 31;
        cpa16(sb + GS_AS * 4 + (uint32_t)(m * 528 + c * 16),
              A + (size_t)(m0 + m) * HDIM + c * 4);
    }
#pragma unroll
    for (int j = 0; j < 16; ++j) {
        int e = j * 256 + tid;
        int k = e >> 5, c = e & 31;
        cpa16(sb + GS_BS * 4 + (uint32_t)(k * 528 + c * 16),
              B + (size_t)k * ldb + n0 + c * 4);
    }
    cpa_commit();

    if (BNA && tid < 128) {
        float s1 = statsIn[tid], s2 = statsIn[128 + tid];
        float mean = s1 * (1.f / (float)NCELL);
        float var = s2 * (1.f / (float)NCELL) - mean * mean;
        float rstd = rsqrtf(var + BN_EPS);
        int off = hid ? hid[0] * hstride : 0;
        float gg = g[off + tid];
        bnS[tid] = gg * rstd;
        bnB[tid] = be[off + tid] - gg * mean * rstd;
    }
    cpa_wait<0>();
    __syncthreads();

    if (BNA) {
#pragma unroll
        for (int j = 0; j < 32; ++j) {
            int e = j * 256 + tid;
            int m = e >> 7, k = e & 127;
            float v = As[m * 132 + k];
            As[m * 132 + k] = fmaxf(fmaf(v, bnS[k], bnB[k]), 0.f);
        }
        __syncthreads();
    }

    float2 acc[4][4];
#pragma unroll
    for (int i = 0; i < 4; ++i)
#pragma unroll
        for (int j = 0; j < 4; ++j) acc[i][j] = make_float2(0.f, 0.f);

    const float *arow0 = As + (ty * 4 + 0) * 132;
    const float *arow1 = As + (ty * 4 + 1) * 132;
    const float *arow2 = As + (ty * 4 + 2) * 132;
    const float *arow3 = As + (ty * 4 + 3) * 132;

#pragma unroll 16
    for (int kk = 0; kk < HDIM; ++kk) {
        float4 b0 = *(const float4 *)&Bs[kk * 132 + tx * 4];
        float4 b1 = *(const float4 *)&Bs[kk * 132 + 64 + tx * 4];
        float2 bp[4] = {make_float2(b0.x, b0.y), make_float2(b0.z, b0.w),
                        make_float2(b1.x, b1.y), make_float2(b1.z, b1.w)};
        float av[4] = {arow0[kk], arow1[kk], arow2[kk], arow3[kk]};
#pragma unroll
        for (int i = 0; i < 4; ++i) {
            float2 aa = make_float2(av[i], av[i]);
#pragma unroll
            for (int j = 0; j < 4; ++j) fma2(acc[i][j], aa, bp[j]);
        }
    }

    float bad0[4] = {0.f, 0.f, 0.f, 0.f}, bad1[4] = {0.f, 0.f, 0.f, 0.f};
    if (bias != nullptr) {
#pragma unroll
        for (int j = 0; j < 4; ++j) {
            bad0[j] = bias[n0 + tx * 4 + j];
            bad1[j] = bias[n0 + 64 + tx * 4 + j];
        }
    }

    float cs[8], cq[8];
#pragma unroll
    for (int j = 0; j < 8; ++j) { cs[j] = 0.f; cq[j] = 0.f; }

#pragma unroll
    for (int i = 0; i < 4; ++i) {
        int r = m0 + ty * 4 + i;
        float v[8] = {acc[i][0].x, acc[i][0].y, acc[i][1].x, acc[i][1].y,
                      acc[i][2].x, acc[i][2].y, acc[i][3].x, acc[i][3].y};
        float w[8];
#pragma unroll
        for (int j = 0; j < 4; ++j) { w[j] = v[j] + bad0[j]; w[4 + j] = v[4 + j] + bad1[j]; }
        if (STATS) {
#pragma unroll
            for (int j = 0; j < 8; ++j) { cs[j] += w[j]; cq[j] += w[j] * w[j]; }
        }
        float *crow = C + (size_t)r * ldc;
        *(float4 *)(crow + n0 + tx * 4)      = make_float4(w[0], w[1], w[2], w[3]);
        *(float4 *)(crow + n0 + 64 + tx * 4) = make_float4(w[4], w[5], w[6], w[7]);
    }

    if (STATS) {
        __syncthreads();
        float *sred = As;
        if (tid < 128) { sred[tid] = 0.f; sred[128 + tid] = 0.f; }
        __syncthreads();
#pragma unroll
        for (int j = 0; j < 8; ++j) {
            int col = (j < 4) ? (tx * 4 + j) : (64 + tx * 4 + (j - 4));
            atomicAdd(&sred[col], cs[j]);
            atomicAdd(&sred[128 + col], cq[j]);
        }
        __syncthreads();
        if (tid < 128) {
            atomicAdd(statsOut + tid, sred[tid]);
            atomicAdd(statsOut + 128 + tid, sred[128 + tid]);
        }
    }
}

// ---------------------------------------------------------------------------
// BatchNorm stats (enc output only)
// ---------------------------------------------------------------------------
__global__ void bn_stats(const float *__restrict__ h, float *__restrict__ stats)
{
    int col = threadIdx.x;
    int r0 = blockIdx.x * 32;
    float s = 0.f, s2 = 0.f;
#pragma unroll 8
    for (int r = 0; r < 32; ++r) {
        float v = h[(size_t)(r0 + r) * HDIM + col];
        s += v; s2 += v * v;
    }
    atomicAdd(&stats[col], s);
    atomicAdd(&stats[128 + col], s2);
}

// ---------------------------------------------------------------------------
// Variational heads
// ---------------------------------------------------------------------------
__global__ void heads_kernel(const float *__restrict__ o,
                             const float *__restrict__ mW, const float *__restrict__ mb,
                             const float *__restrict__ vW, const float *__restrict__ vb,
                             const float *__restrict__ eps,
                             float *__restrict__ qm, float *__restrict__ qv,
                             float *__restrict__ lat)
{
    extern __shared__ float smh[];
    float *Wm  = smh;
    float *Wv  = smh + 4096;
    float *osm = smh + 8192;
    const int t = threadIdx.x;
    const int r0 = blockIdx.x * 128;

    for (int i = t; i < HDIM * NOUTD; i += 256) { Wm[i] = mW[i]; Wv[i] = vW[i]; }
    for (int i = t; i < 128 * HDIM; i += 256) {
        int r = i >> 7, c = i & 127;
        osm[r * 129 + c] = o[(size_t)(r0 + r) * HDIM + c];
    }
    __syncthreads();

    for (int idx = t; idx < 128 * NOUTD; idx += 256) {
        int r = idx >> 5, c = idx & 31;
        const float *orow = &osm[r * 129];
        float dm = 0.f, dv = 0.f;
#pragma unroll 8
        for (int k = 0; k < HDIM; ++k) {
            float ov = orow[k];
            dm += ov * Wm[k * NOUTD + c];
            dv += ov * Wv[k * NOUTD + c];
        }
        int R = r0 + r;
        float mval = dm + mb[c];
        float vval = __expf(dv + vb[c]);
        qm[R * NOUTD + c]  = mval;
        qv[R * NOUTD + c]  = vval;
        lat[R * NOUTD + c] = mval + sqrtf(vval) * eps[R * NOUTD + c];
    }
}

// ---------------------------------------------------------------------------
// Launch
// ---------------------------------------------------------------------------
extern "C" void kernel_launch(void *const *d_in, const int *in_sizes, int n_in,
                              void *d_out, int out_size)
{
    const float *x       = (const float *)d_in[0];
    const float *spatial = (const float *)d_in[1];
    const float *eps     = (const float *)d_in[2];
    const float *enc_W   = (const float *)d_in[3];
    const float *enc_g   = (const float *)d_in[5];
    const float *enc_be  = (const float *)d_in[6];
    const float *sh_W1   = (const float *)d_in[7];
    const float *sh_g1   = (const float *)d_in[9];
    const float *sh_be1  = (const float *)d_in[10];
    const float *sh_W2   = (const float *)d_in[11];
    const float *sh_g2   = (const float *)d_in[13];
    const float *sh_be2  = (const float *)d_in[14];
    const float *qkv_W   = (const float *)d_in[15];
    const float *qkv_b   = (const float *)d_in[16];
    const float *o_W     = (const float *)d_in[17];
    const float *o_b     = (const float *)d_in[18];
    const float *mean_W  = (const float *)d_in[19];
    const float *mean_b  = (const float *)d_in[20];
    const float *var_W   = (const float *)d_in[21];
    const float *var_b   = (const float *)d_in[22];
    const int   *hid     = (const int *)d_in[23];

    float *out = (float *)d_out;
    float *out_qm   = out;
    float *out_qv   = out + (size_t)NCELL * NOUTD;
    float *out_lat  = out + 2 * (size_t)NCELL * NOUTD;
    float *out_attn = out + 3 * (size_t)NCELL * NOUTD;

    float *bufA, *bufB, *qkv, *kagg, *stats;
    unsigned long long *rowstats;
    __nv_bfloat16 *q_hi, *q_lo, *ka_hi, *ka_lo;
    __nv_bfloat16 *kT_hi, *kT_lo, *vT_hi, *vT_lo, *wT_hi, *wT_lo;
    cudaGetSymbolAddress((void **)&bufA, g_bufA);
    cudaGetSymbolAddress((void **)&bufB, g_bufB);
    cudaGetSymbolAddress((void **)&qkv,  g_qkv);
    cudaGetSymbolAddress((void **)&kagg, g_kagg);
    cudaGetSymbolAddress((void **)&stats, g_stats);
    cudaGetSymbolAddress((void **)&rowstats, g_rowstats);
    cudaGetSymbolAddress((void **)&q_hi, g_q_hi);
    cudaGetSymbolAddress((void **)&q_lo, g_q_lo);
    cudaGetSymbolAddress((void **)&ka_hi, g_ka_hi);
    cudaGetSymbolAddress((void **)&ka_lo, g_ka_lo);
    cudaGetSymbolAddress((void **)&kT_hi, g_kT_hi);
    cudaGetSymbolAddress((void **)&kT_lo, g_kT_lo);
    cudaGetSymbolAddress((void **)&vT_hi, g_vT_hi);
    cudaGetSymbolAddress((void **)&vT_lo, g_vT_lo);
    cudaGetSymbolAddress((void **)&wT_hi, g_wT_hi);
    cudaGetSymbolAddress((void **)&wT_lo, g_wT_lo);

    cudaFuncSetAttribute(tc_skinny_f32, cudaFuncAttributeMaxDynamicSharedMemorySize, SKF_SMEM);
    cudaFuncSetAttribute(tc_wide_stats, cudaFuncAttributeMaxDynamicSharedMemorySize, WIDE_SMEM);
    cudaFuncSetAttribute(tc_attn,       cudaFuncAttributeMaxDynamicSharedMemorySize, AT_SMEM);
    cudaFuncSetAttribute((const void *)gemm_small<true, true>,
                         cudaFuncAttributeMaxDynamicSharedMemorySize, GS_SMEM);
    cudaFuncSetAttribute((const void *)gemm_small<true, false>,
                         cudaFuncAttributeMaxDynamicSharedMemorySize, GS_SMEM);
    cudaFuncSetAttribute((const void *)gemm_small<false, false>,
                         cudaFuncAttributeMaxDynamicSharedMemorySize, GS_SMEM);

    const size_t NH_BYTES = (size_t)NCELL * HDIM * sizeof(float);
    const float SCALE = 0.08838834764831845f;
    float *slot0 = stats, *slot1 = stats + 256, *slot2 = stats + 512;

    cudaMemsetAsync(stats, 0, 768 * sizeof(float));
    init_rowstats<<<32, 256>>>(rowstats);

    // 1. encoder: h = x @ enc_W[hid]
    wT_split<<<dim3(64, 4), dim3(32, 8)>>>(enc_W, hid, wT_hi, wT_lo);
    cudaMemsetAsync(bufA, 0, NH_BYTES);
    tc_skinny_f32<<<dim3(64, 1, 4), 128, SKF_SMEM>>>(
        x, NINP, NINP, wT_hi, wT_lo, KPAD, bufA, HDIM, 512, 1.f);
    bn_stats<<<256, 128>>>(bufA, slot0);

    // 2. sh1 = BN1(bufA) @ W1 ; stats -> slot1
    gemm_small<true, true><<<dim3(128, 1), 256, GS_SMEM>>>(
        bufA, sh_W1, bufB, HDIM, HDIM, nullptr,
        slot0, enc_g, enc_be, hid, HDIM, slot1);

    // 3. sh2 = BN2(bufB) @ W2 ; stats -> slot2
    gemm_small<true, true><<<dim3(128, 1), 256, GS_SMEM>>>(
        bufB, sh_W2, bufA, HDIM, HDIM, nullptr,
        slot1, sh_g1, sh_be1, nullptr, 0, slot2);

    // 4. qkv = BN3(bufA) @ qkv_W + qkv_b
    gemm_small<true, false><<<dim3(128, 3), 256, GS_SMEM>>>(
        bufA, qkv_W, qkv, 3 * HDIM, 3 * HDIM, qkv_b,
        slot2, sh_g2, sh_be2, nullptr, 0, nullptr);

    // 5. small bf16 conversions (q, kT, vT)
    split_cols<<<1024, 256>>>(qkv, 3 * HDIM, 0, HDIM / 4, q_hi, q_lo);
    transpose_split<<<dim3(256, 4), dim3(32, 8)>>>(qkv, 3 * HDIM, HDIM, kT_hi, kT_lo);
    transpose_split<<<dim3(256, 4), dim3(32, 8)>>>(qkv, 3 * HDIM, 2 * HDIM, vT_hi, vT_lo);

    // 6. k_agg = spatial @ k
    cudaMemsetAsync(kagg, 0, NH_BYTES);
    tc_skinny_f32<<<dim3(64, 1, 4), 128, SKF_SMEM>>>(
        spatial, NCELL, NCELL, kT_hi, kT_lo, NCELL, kagg, HDIM, 2048, 1.f);
    split_cols<<<1024, 256>>>(kagg, HDIM, 0, HDIM / 4, ka_hi, ka_lo);

    // 7. pass 1: row softmax stats (no logits store)
    tc_wide_stats<<<dim3(64, 16), 128, WIDE_SMEM>>>(q_hi, q_lo, ka_hi, ka_lo,
                                                    SCALE, rowstats);

    // 8. pass 2: recompute logits, softmax -> attn output, av = attn @ v
    cudaMemsetAsync(bufA, 0, NH_BYTES);
    tc_attn<<<dim3(64, 1, 4), 128, AT_SMEM>>>(
        q_hi, q_lo, ka_hi, ka_lo, vT_hi, vT_lo, out_attn, bufA, rowstats, SCALE);

    // 9. o = av @ o_W + o_b
    gemm_small<false, false><<<dim3(128, 1), 256, GS_SMEM>>>(
        bufA, o_W, bufB, HDIM, HDIM, o_b,
        nullptr, nullptr, nullptr, nullptr, 0, nullptr);

    // 10. variational heads
    const int heads_smem = (4096 + 4096 + 128 * 129) * sizeof(float);
    cudaFuncSetAttribute(heads_kernel, cudaFuncAttributeMaxDynamicSharedMemorySize,
                         heads_smem);
    heads_kernel<<<64, 256, heads_smem>>>(bufB, mean_W, mean_b, var_W, var_b,
                                          eps, out_qm, out_qv, out_lat);
}